// round 1
// baseline (speedup 1.0000x reference)
#include <cuda_runtime.h>
#include <cuda_bf16.h>

#define N_NODES 50000
#define N_EDGES 800000
#define B_GRAPH 8
#define HID 64
#define DOUT 32

// Scratch (device globals — no allocations allowed)
__device__ float g_h[(size_t)N_NODES * DOUT];      // segment_sum(e_out, dst)
__device__ float g_ecomb[B_GRAPH * DOUT];
__device__ float g_ncomb[B_GRAPH * DOUT];

__global__ void zero_kernel() {
    size_t i = (size_t)blockIdx.x * blockDim.x + threadIdx.x;
    if (i < (size_t)N_NODES * DOUT) g_h[i] = 0.f;
    if (i < B_GRAPH * DOUT) { g_ecomb[i] = 0.f; g_ncomb[i] = 0.f; }
}

// ---------------------------------------------------------------------------
// Edge kernel: per tile of 128 edges
//   X[128][128] = concat(edge_feat, node_feat[src], node_feat[dst], g_repr[e2g])
//   H = relu(X @ W1 + b1)   [128 x 64]
//   Y = H @ W2 + b2         [128 x 32]
//   e_out = Y; atomicAdd into g_h[dst]; block-reduce into g_ecomb[e2g]
// ---------------------------------------------------------------------------
__global__ void __launch_bounds__(256) edge_kernel(
    const float* __restrict__ edge_feat, const float* __restrict__ node_feat,
    const float* __restrict__ g_repr, const int* __restrict__ src,
    const int* __restrict__ dst, const int* __restrict__ e2g,
    const float* __restrict__ W1, const float* __restrict__ b1,
    const float* __restrict__ W2, const float* __restrict__ b2,
    float* __restrict__ e_out)
{
    extern __shared__ float sm[];
    float* W1s = sm;              // 128*64 = 8192
    float* W2s = sm + 8192;       // 64*32  = 2048
    float* b1s = sm + 10240;      // 64
    float* b2s = sm + 10304;      // 32
    float* Es  = sm + 10336;      // 8*32 = 256
    float* Xs  = sm + 10592;      // 128 rows, stride 129 = 16512
    float* Hs  = Xs;              // alias: 128 rows, stride 65 = 8320

    const int tid = threadIdx.x;

    // stage weights
    {
        const float4* wg = (const float4*)W1;  float4* ws = (float4*)W1s;
        for (int i = tid; i < 2048; i += 256) ws[i] = wg[i];
        const float4* w2g = (const float4*)W2; float4* w2s = (float4*)W2s;
        for (int i = tid; i < 512; i += 256) w2s[i] = w2g[i];
        if (tid < HID)  b1s[tid] = b1[tid];
        if (tid < DOUT) b2s[tid] = b2[tid];
        Es[tid] = 0.f;
    }

    const size_t e0 = (size_t)blockIdx.x * 128;

    // gather: 2 threads per edge row, each fills 64 floats (16 float4 gmem loads)
    {
        const int r = tid >> 1, half = tid & 1;
        const size_t e = e0 + r;
        const int si = src[e], di = dst[e], gi = e2g[e];
        const float4* p0 = (const float4*)(half ? node_feat + (size_t)di * 32
                                                : edge_feat + e * 32);
        const float4* p1 = (const float4*)(half ? g_repr + (size_t)gi * 32
                                                : node_feat + (size_t)si * 32);
        float* xr = Xs + r * 129 + half * 64;
#pragma unroll
        for (int q = 0; q < 8; q++) {
            float4 v = p0[q];
            xr[q*4+0]=v.x; xr[q*4+1]=v.y; xr[q*4+2]=v.z; xr[q*4+3]=v.w;
        }
#pragma unroll
        for (int q = 0; q < 8; q++) {
            float4 v = p1[q];
            xr[32+q*4+0]=v.x; xr[32+q*4+1]=v.y; xr[32+q*4+2]=v.z; xr[32+q*4+3]=v.w;
        }
    }
    __syncthreads();

    // GEMM1: 128x64x128. thread (tx=tid&15, ty=tid>>4) -> 8 edges x 4 hidden
    const int tx = tid & 15, ty = tid >> 4;
    float acc[8][4];
#pragma unroll
    for (int i = 0; i < 8; i++)
#pragma unroll
        for (int j = 0; j < 4; j++) acc[i][j] = b1s[tx * 4 + j];

    const float* xbase = Xs + ty * 129;
#pragma unroll 4
    for (int k = 0; k < 128; k++) {
        float4 w = *(const float4*)(W1s + k * 64 + tx * 4);
        float xv[8];
#pragma unroll
        for (int i = 0; i < 8; i++) xv[i] = xbase[i * 16 * 129 + k];
#pragma unroll
        for (int i = 0; i < 8; i++) {
            acc[i][0] += xv[i] * w.x;
            acc[i][1] += xv[i] * w.y;
            acc[i][2] += xv[i] * w.z;
            acc[i][3] += xv[i] * w.w;
        }
    }
    __syncthreads();   // done reading Xs

    // relu -> Hs (stride 65)
#pragma unroll
    for (int i = 0; i < 8; i++) {
        float* hr = Hs + (ty + 16 * i) * 65 + tx * 4;
        hr[0] = fmaxf(acc[i][0], 0.f);
        hr[1] = fmaxf(acc[i][1], 0.f);
        hr[2] = fmaxf(acc[i][2], 0.f);
        hr[3] = fmaxf(acc[i][3], 0.f);
    }
    __syncthreads();

    // GEMM2: 128x32x64. thread (tx2=tid&7, ty2=tid>>3) -> 4 edges x 4 out
    const int tx2 = tid & 7, ty2 = tid >> 3;
    float acc2[4][4];
#pragma unroll
    for (int i = 0; i < 4; i++)
#pragma unroll
        for (int j = 0; j < 4; j++) acc2[i][j] = b2s[tx2 * 4 + j];

    const float* hbase = Hs + ty2 * 65;
#pragma unroll 4
    for (int k = 0; k < 64; k++) {
        float4 w = *(const float4*)(W2s + k * 32 + tx2 * 4);
        float hv[4];
#pragma unroll
        for (int i = 0; i < 4; i++) hv[i] = hbase[i * 32 * 65 + k];
#pragma unroll
        for (int i = 0; i < 4; i++) {
            acc2[i][0] += hv[i] * w.x;
            acc2[i][1] += hv[i] * w.y;
            acc2[i][2] += hv[i] * w.z;
            acc2[i][3] += hv[i] * w.w;
        }
    }

    // epilogue: write e_out, scatter to g_h[dst], smem-reduce e_comb
#pragma unroll
    for (int i = 0; i < 4; i++) {
        const int r = ty2 + 32 * i;
        const size_t e = e0 + r;
        float4 v = make_float4(acc2[i][0], acc2[i][1], acc2[i][2], acc2[i][3]);
        *(float4*)(e_out + e * 32 + tx2 * 4) = v;
        const int di = dst[e];
        float* hp = g_h + (size_t)di * 32 + tx2 * 4;
        atomicAdd(hp + 0, v.x); atomicAdd(hp + 1, v.y);
        atomicAdd(hp + 2, v.z); atomicAdd(hp + 3, v.w);
        const int gi = e2g[e];
        float* ep = Es + gi * 32 + tx2 * 4;
        atomicAdd(ep + 0, v.x); atomicAdd(ep + 1, v.y);
        atomicAdd(ep + 2, v.z); atomicAdd(ep + 3, v.w);
    }
    __syncthreads();
    atomicAdd(&g_ecomb[tid], Es[tid]);
}

// ---------------------------------------------------------------------------
// Node kernel: per tile of 128 nodes (last tile partial)
//   X[128][96] = concat(node_feat, g_h, g_repr[n2g]); MLP 96->64->32
// ---------------------------------------------------------------------------
__global__ void __launch_bounds__(256) node_kernel(
    const float* __restrict__ node_feat, const float* __restrict__ g_repr,
    const int* __restrict__ n2g,
    const float* __restrict__ W1, const float* __restrict__ b1,
    const float* __restrict__ W2, const float* __restrict__ b2,
    float* __restrict__ n_out)
{
    extern __shared__ float sm[];
    float* W1s = sm;              // 96*64 = 6144
    float* W2s = sm + 6144;       // 2048
    float* b1s = sm + 8192;       // 64
    float* b2s = sm + 8256;       // 32
    float* Ns  = sm + 8288;       // 256
    float* Xs  = sm + 8544;       // 128 rows, stride 97 = 12416
    float* Hs  = Xs;              // alias, 128*65 = 8320

    const int tid = threadIdx.x;
    {
        const float4* wg = (const float4*)W1;  float4* ws = (float4*)W1s;
        for (int i = tid; i < 1536; i += 256) ws[i] = wg[i];
        const float4* w2g = (const float4*)W2; float4* w2s = (float4*)W2s;
        for (int i = tid; i < 512; i += 256) w2s[i] = w2g[i];
        if (tid < HID)  b1s[tid] = b1[tid];
        if (tid < DOUT) b2s[tid] = b2[tid];
        Ns[tid] = 0.f;
    }

    const int n0 = blockIdx.x * 128;

    // gather: 3072 float4 segments (24 per row)
    for (int s = tid; s < 3072; s += 256) {
        const int r = s / 24, q = s % 24;
        const int node = n0 + r;
        float4 v = make_float4(0.f, 0.f, 0.f, 0.f);
        if (node < N_NODES) {
            if (q < 8)       v = ((const float4*)(node_feat + (size_t)node * 32))[q];
            else if (q < 16) v = ((const float4*)(g_h + (size_t)node * 32))[q - 8];
            else {
                const int gi = n2g[node];
                v = ((const float4*)(g_repr + (size_t)gi * 32))[q - 16];
            }
        }
        float* xr = Xs + r * 97 + q * 4;
        xr[0]=v.x; xr[1]=v.y; xr[2]=v.z; xr[3]=v.w;
    }
    __syncthreads();

    // GEMM1: 128x64x96
    const int tx = tid & 15, ty = tid >> 4;
    float acc[8][4];
#pragma unroll
    for (int i = 0; i < 8; i++)
#pragma unroll
        for (int j = 0; j < 4; j++) acc[i][j] = b1s[tx * 4 + j];

    const float* xbase = Xs + ty * 97;
#pragma unroll 4
    for (int k = 0; k < 96; k++) {
        float4 w = *(const float4*)(W1s + k * 64 + tx * 4);
        float xv[8];
#pragma unroll
        for (int i = 0; i < 8; i++) xv[i] = xbase[i * 16 * 97 + k];
#pragma unroll
        for (int i = 0; i < 8; i++) {
            acc[i][0] += xv[i] * w.x;
            acc[i][1] += xv[i] * w.y;
            acc[i][2] += xv[i] * w.z;
            acc[i][3] += xv[i] * w.w;
        }
    }
    __syncthreads();

#pragma unroll
    for (int i = 0; i < 8; i++) {
        float* hr = Hs + (ty + 16 * i) * 65 + tx * 4;
        hr[0] = fmaxf(acc[i][0], 0.f);
        hr[1] = fmaxf(acc[i][1], 0.f);
        hr[2] = fmaxf(acc[i][2], 0.f);
        hr[3] = fmaxf(acc[i][3], 0.f);
    }
    __syncthreads();

    // GEMM2: 128x32x64
    const int tx2 = tid & 7, ty2 = tid >> 3;
    float acc2[4][4];
#pragma unroll
    for (int i = 0; i < 4; i++)
#pragma unroll
        for (int j = 0; j < 4; j++) acc2[i][j] = b2s[tx2 * 4 + j];

    const float* hbase = Hs + ty2 * 65;
#pragma unroll 4
    for (int k = 0; k < 64; k++) {
        float4 w = *(const float4*)(W2s + k * 32 + tx2 * 4);
        float hv[4];
#pragma unroll
        for (int i = 0; i < 4; i++) hv[i] = hbase[i * 32 * 65 + k];
#pragma unroll
        for (int i = 0; i < 4; i++) {
            acc2[i][0] += hv[i] * w.x;
            acc2[i][1] += hv[i] * w.y;
            acc2[i][2] += hv[i] * w.z;
            acc2[i][3] += hv[i] * w.w;
        }
    }

#pragma unroll
    for (int i = 0; i < 4; i++) {
        const int r = ty2 + 32 * i;
        const int node = n0 + r;
        if (node < N_NODES) {
            float4 v = make_float4(acc2[i][0], acc2[i][1], acc2[i][2], acc2[i][3]);
            *(float4*)(n_out + (size_t)node * 32 + tx2 * 4) = v;
            const int gi = n2g[node];
            float* np = Ns + gi * 32 + tx2 * 4;
            atomicAdd(np + 0, v.x); atomicAdd(np + 1, v.y);
            atomicAdd(np + 2, v.z); atomicAdd(np + 3, v.w);
        }
    }
    __syncthreads();
    atomicAdd(&g_ncomb[tid], Ns[tid]);
}

// ---------------------------------------------------------------------------
// Global kernel: u_inp = concat(n_comb, e_comb, g_repr) [8 x 96] -> MLP
// ---------------------------------------------------------------------------
__global__ void global_kernel(
    const float* __restrict__ g_repr,
    const float* __restrict__ Wu1, const float* __restrict__ bu1,
    const float* __restrict__ Wu2, const float* __restrict__ bu2,
    float* __restrict__ g_out)
{
    __shared__ float Hs[B_GRAPH * HID];
    const int tid = threadIdx.x;
    for (int idx = tid; idx < B_GRAPH * HID; idx += blockDim.x) {
        const int b = idx >> 6, j = idx & 63;
        float s = bu1[j];
        for (int k = 0; k < 32; k++) s += g_ncomb[b * 32 + k] * Wu1[k * 64 + j];
        for (int k = 0; k < 32; k++) s += g_ecomb[b * 32 + k] * Wu1[(32 + k) * 64 + j];
        for (int k = 0; k < 32; k++) s += g_repr[b * 32 + k] * Wu1[(64 + k) * 64 + j];
        Hs[idx] = fmaxf(s, 0.f);
    }
    __syncthreads();
    for (int idx = tid; idx < B_GRAPH * DOUT; idx += blockDim.x) {
        const int b = idx >> 5, c = idx & 31;
        float s = bu2[c];
        for (int k = 0; k < 64; k++) s += Hs[b * 64 + k] * Wu2[k * 32 + c];
        g_out[idx] = s;
    }
}

extern "C" void kernel_launch(void* const* d_in, const int* in_sizes, int n_in,
                              void* d_out, int out_size)
{
    const float* edge_feat = (const float*)d_in[0];
    const float* node_feat = (const float*)d_in[1];
    const float* g_repr    = (const float*)d_in[2];
    const int*   src       = (const int*)d_in[3];
    const int*   dst       = (const int*)d_in[4];
    const int*   n2g       = (const int*)d_in[5];
    const int*   e2g       = (const int*)d_in[6];
    const float* W_e1 = (const float*)d_in[7];
    const float* b_e1 = (const float*)d_in[8];
    const float* W_e2 = (const float*)d_in[9];
    const float* b_e2 = (const float*)d_in[10];
    const float* W_n1 = (const float*)d_in[11];
    const float* b_n1 = (const float*)d_in[12];
    const float* W_n2 = (const float*)d_in[13];
    const float* b_n2 = (const float*)d_in[14];
    const float* W_u1 = (const float*)d_in[15];
    const float* b_u1 = (const float*)d_in[16];
    const float* W_u2 = (const float*)d_in[17];
    const float* b_u2 = (const float*)d_in[18];

    float* out = (float*)d_out;
    float* e_out = out;                                   // [E, 32]
    float* n_out = out + (size_t)N_EDGES * DOUT;          // [N, 32]
    float* g_out = out + (size_t)(N_EDGES + N_NODES) * DOUT; // [B, 32]

    const int edge_smem = 27104 * 4;   // 108,416 B
    const int node_smem = 20960 * 4;   // 83,840 B
    cudaFuncSetAttribute(edge_kernel, cudaFuncAttributeMaxDynamicSharedMemorySize, edge_smem);
    cudaFuncSetAttribute(node_kernel, cudaFuncAttributeMaxDynamicSharedMemorySize, node_smem);

    zero_kernel<<<6250, 256>>>();
    edge_kernel<<<N_EDGES / 128, 256, edge_smem>>>(
        edge_feat, node_feat, g_repr, src, dst, e2g,
        W_e1, b_e1, W_e2, b_e2, e_out);
    node_kernel<<<(N_NODES + 127) / 128, 256, node_smem>>>(
        node_feat, g_repr, n2g, W_n1, b_n1, W_n2, b_n2, n_out);
    global_kernel<<<1, 256>>>(g_repr, W_u1, b_u1, W_u2, b_u2, g_out);
}

// round 2
// speedup vs baseline: 1.1300x; 1.1300x over previous
#include <cuda_runtime.h>
#include <cuda_bf16.h>

#define N_NODES 50000
#define N_EDGES 800000
#define B_GRAPH 8
#define HID 64
#define DOUT 32

typedef unsigned long long ull;

__device__ __forceinline__ ull fma2(ull a, ull b, ull c) {
    ull d;
    asm("fma.rn.f32x2 %0, %1, %2, %3;" : "=l"(d) : "l"(a), "l"(b), "l"(c));
    return d;
}
__device__ __forceinline__ ull pack2(float x) {
    ull d;
    asm("mov.b64 %0, {%1, %1};" : "=l"(d) : "f"(x));
    return d;
}
__device__ __forceinline__ float2 unpack2(ull v) {
    float2 r;
    asm("mov.b64 {%0, %1}, %2;" : "=f"(r.x), "=f"(r.y) : "l"(v));
    return r;
}

// Scratch (device globals — no allocations allowed)
__device__ float g_h[(size_t)N_NODES * DOUT];      // segment_sum(e_out, dst)
__device__ float g_ecomb[B_GRAPH * DOUT];
__device__ float g_ncomb[B_GRAPH * DOUT];

__global__ void zero_kernel() {
    size_t i = (size_t)blockIdx.x * blockDim.x + threadIdx.x;
    if (i < (size_t)N_NODES * DOUT) g_h[i] = 0.f;
    if (i < B_GRAPH * DOUT) { g_ecomb[i] = 0.f; g_ncomb[i] = 0.f; }
}

// ---------------------------------------------------------------------------
// Edge kernel: tile = 128 edges, 256 threads, f32x2 packed GEMMs
// ---------------------------------------------------------------------------
__global__ void __launch_bounds__(256) edge_kernel(
    const float* __restrict__ edge_feat, const float* __restrict__ node_feat,
    const float* __restrict__ g_repr, const int* __restrict__ src,
    const int* __restrict__ dst, const int* __restrict__ e2g,
    const float* __restrict__ W1, const float* __restrict__ b1,
    const float* __restrict__ W2, const float* __restrict__ b2,
    float* __restrict__ e_out)
{
    extern __shared__ float sm[];
    float* W1s = sm;              // 128*64 = 8192
    float* W2s = sm + 8192;       // 64*32  = 2048
    float* b1s = sm + 10240;      // 64
    float* b2s = sm + 10304;      // 32
    float* Es  = sm + 10336;      // 8*32 = 256
    float* Xs  = sm + 10592;      // 128 rows, stride 132 = 16896
    float* Hs  = Xs;              // alias: 128 rows, stride 68

    const int tid = threadIdx.x;

    // stage weights
    {
        const float4* wg = (const float4*)W1;  float4* ws = (float4*)W1s;
        for (int i = tid; i < 2048; i += 256) ws[i] = wg[i];
        const float4* w2g = (const float4*)W2; float4* w2s = (float4*)W2s;
        for (int i = tid; i < 512; i += 256) w2s[i] = w2g[i];
        if (tid < HID)  b1s[tid] = b1[tid];
        if (tid < DOUT) b2s[tid] = b2[tid];
        Es[tid] = 0.f;
    }

    const size_t e0 = (size_t)blockIdx.x * 128;

    // gather: 2 threads per edge row, each fills 64 floats (16B vector stores)
    {
        const int r = tid >> 1, half = tid & 1;
        const size_t e = e0 + r;
        const int si = src[e], di = dst[e], gi = e2g[e];
        const float4* p0 = (const float4*)(half ? node_feat + (size_t)di * 32
                                                : edge_feat + e * 32);
        const float4* p1 = (const float4*)(half ? g_repr + (size_t)gi * 32
                                                : node_feat + (size_t)si * 32);
        float* xr = Xs + r * 132 + half * 64;
#pragma unroll
        for (int q = 0; q < 8; q++) *(float4*)(xr + q * 4) = p0[q];
#pragma unroll
        for (int q = 0; q < 8; q++) *(float4*)(xr + 32 + q * 4) = p1[q];
    }
    __syncthreads();

    // GEMM1: 128x64x128. thread = 4 edges (ty+32i) x 8 cols (tx*8..+7), f32x2
    const int tx = tid & 7, ty = tid >> 3;
    ull acc1[4][4];
    {
        const ulonglong2* bp = (const ulonglong2*)(b1s + tx * 8);
        ulonglong2 ba = bp[0], bb = bp[1];
#pragma unroll
        for (int i = 0; i < 4; i++) {
            acc1[i][0] = ba.x; acc1[i][1] = ba.y;
            acc1[i][2] = bb.x; acc1[i][3] = bb.y;
        }
    }
    const float* x0 = Xs + ty * 132;
#pragma unroll 4
    for (int k = 0; k < 128; k++) {
        const ulonglong2* wp = (const ulonglong2*)(W1s + k * 64 + tx * 8);
        ulonglong2 wa = wp[0], wb = wp[1];
        ull w[4] = { wa.x, wa.y, wb.x, wb.y };
        ull xp[4];
        xp[0] = pack2(x0[k]);
        xp[1] = pack2(x0[4224 + k]);
        xp[2] = pack2(x0[8448 + k]);
        xp[3] = pack2(x0[12672 + k]);
#pragma unroll
        for (int i = 0; i < 4; i++)
#pragma unroll
            for (int j = 0; j < 4; j++)
                acc1[i][j] = fma2(xp[i], w[j], acc1[i][j]);
    }
    __syncthreads();   // done reading Xs

    // relu -> Hs (stride 68, 16B-aligned rows)
#pragma unroll
    for (int i = 0; i < 4; i++) {
        float* hr = Hs + (ty + 32 * i) * 68 + tx * 8;
#pragma unroll
        for (int j = 0; j < 4; j++) {
            float2 v = unpack2(acc1[i][j]);
            hr[2 * j]     = fmaxf(v.x, 0.f);
            hr[2 * j + 1] = fmaxf(v.y, 0.f);
        }
    }
    __syncthreads();

    // GEMM2: 128x32x64. thread = 2 edges (ty2+64i) x 8 cols (tx2*8..+7)
    const int tx2 = tid & 3, ty2 = tid >> 2;
    ull acc2[2][4];
    {
        const ulonglong2* bp = (const ulonglong2*)(b2s + tx2 * 8);
        ulonglong2 ba = bp[0], bb = bp[1];
        acc2[0][0] = acc2[1][0] = ba.x; acc2[0][1] = acc2[1][1] = ba.y;
        acc2[0][2] = acc2[1][2] = bb.x; acc2[0][3] = acc2[1][3] = bb.y;
    }
    const float* h0 = Hs + ty2 * 68;
#pragma unroll 4
    for (int k = 0; k < 64; k++) {
        const ulonglong2* wp = (const ulonglong2*)(W2s + k * 32 + tx2 * 8);
        ulonglong2 wa = wp[0], wb = wp[1];
        ull w[4] = { wa.x, wa.y, wb.x, wb.y };
        ull xa = pack2(h0[k]);
        ull xb = pack2(h0[64 * 68 + k]);
#pragma unroll
        for (int j = 0; j < 4; j++) {
            acc2[0][j] = fma2(xa, w[j], acc2[0][j]);
            acc2[1][j] = fma2(xb, w[j], acc2[1][j]);
        }
    }

    // epilogue: write e_out, scatter to g_h[dst], smem-reduce e_comb
#pragma unroll
    for (int i = 0; i < 2; i++) {
        const int r = ty2 + 64 * i;
        const size_t e = e0 + r;
        float o[8];
#pragma unroll
        for (int j = 0; j < 4; j++) {
            float2 v = unpack2(acc2[i][j]);
            o[2 * j] = v.x; o[2 * j + 1] = v.y;
        }
        *(float4*)(e_out + e * 32 + tx2 * 8)     = make_float4(o[0], o[1], o[2], o[3]);
        *(float4*)(e_out + e * 32 + tx2 * 8 + 4) = make_float4(o[4], o[5], o[6], o[7]);
        const int di = dst[e];
        float* hp = g_h + (size_t)di * 32 + tx2 * 8;
#pragma unroll
        for (int q = 0; q < 8; q++) atomicAdd(hp + q, o[q]);
        const int gi = e2g[e];
        float* ep = Es + gi * 32 + tx2 * 8;
#pragma unroll
        for (int q = 0; q < 8; q++) atomicAdd(ep + q, o[q]);
    }
    __syncthreads();
    atomicAdd(&g_ecomb[tid], Es[tid]);
}

// ---------------------------------------------------------------------------
// Node kernel: tile = 128 nodes, X[128][96] -> MLP 96->64->32, f32x2
// ---------------------------------------------------------------------------
__global__ void __launch_bounds__(256) node_kernel(
    const float* __restrict__ node_feat, const float* __restrict__ g_repr,
    const int* __restrict__ n2g,
    const float* __restrict__ W1, const float* __restrict__ b1,
    const float* __restrict__ W2, const float* __restrict__ b2,
    float* __restrict__ n_out)
{
    extern __shared__ float sm[];
    float* W1s = sm;              // 96*64 = 6144
    float* W2s = sm + 6144;       // 2048
    float* b1s = sm + 8192;       // 64
    float* b2s = sm + 8256;       // 32
    float* Ns  = sm + 8288;       // 256
    float* Xs  = sm + 8544;       // 128 rows, stride 100 = 12800
    float* Hs  = Xs;              // alias, stride 68

    const int tid = threadIdx.x;
    {
        const float4* wg = (const float4*)W1;  float4* ws = (float4*)W1s;
        for (int i = tid; i < 1536; i += 256) ws[i] = wg[i];
        const float4* w2g = (const float4*)W2; float4* w2s = (float4*)W2s;
        for (int i = tid; i < 512; i += 256) w2s[i] = w2g[i];
        if (tid < HID)  b1s[tid] = b1[tid];
        if (tid < DOUT) b2s[tid] = b2[tid];
        Ns[tid] = 0.f;
    }

    const int n0 = blockIdx.x * 128;

    // gather: 24 float4 per row
    for (int s = tid; s < 3072; s += 256) {
        const int r = s / 24, q = s % 24;
        const int node = n0 + r;
        float4 v = make_float4(0.f, 0.f, 0.f, 0.f);
        if (node < N_NODES) {
            if (q < 8)       v = ((const float4*)(node_feat + (size_t)node * 32))[q];
            else if (q < 16) v = ((const float4*)(g_h + (size_t)node * 32))[q - 8];
            else {
                const int gi = n2g[node];
                v = ((const float4*)(g_repr + (size_t)gi * 32))[q - 16];
            }
        }
        *(float4*)(Xs + r * 100 + q * 4) = v;
    }
    __syncthreads();

    // GEMM1: 128x64x96
    const int tx = tid & 7, ty = tid >> 3;
    ull acc1[4][4];
    {
        const ulonglong2* bp = (const ulonglong2*)(b1s + tx * 8);
        ulonglong2 ba = bp[0], bb = bp[1];
#pragma unroll
        for (int i = 0; i < 4; i++) {
            acc1[i][0] = ba.x; acc1[i][1] = ba.y;
            acc1[i][2] = bb.x; acc1[i][3] = bb.y;
        }
    }
    const float* x0 = Xs + ty * 100;
#pragma unroll 4
    for (int k = 0; k < 96; k++) {
        const ulonglong2* wp = (const ulonglong2*)(W1s + k * 64 + tx * 8);
        ulonglong2 wa = wp[0], wb = wp[1];
        ull w[4] = { wa.x, wa.y, wb.x, wb.y };
        ull xp[4];
        xp[0] = pack2(x0[k]);
        xp[1] = pack2(x0[3200 + k]);
        xp[2] = pack2(x0[6400 + k]);
        xp[3] = pack2(x0[9600 + k]);
#pragma unroll
        for (int i = 0; i < 4; i++)
#pragma unroll
            for (int j = 0; j < 4; j++)
                acc1[i][j] = fma2(xp[i], w[j], acc1[i][j]);
    }
    __syncthreads();

#pragma unroll
    for (int i = 0; i < 4; i++) {
        float* hr = Hs + (ty + 32 * i) * 68 + tx * 8;
#pragma unroll
        for (int j = 0; j < 4; j++) {
            float2 v = unpack2(acc1[i][j]);
            hr[2 * j]     = fmaxf(v.x, 0.f);
            hr[2 * j + 1] = fmaxf(v.y, 0.f);
        }
    }
    __syncthreads();

    // GEMM2: 128x32x64
    const int tx2 = tid & 3, ty2 = tid >> 2;
    ull acc2[2][4];
    {
        const ulonglong2* bp = (const ulonglong2*)(b2s + tx2 * 8);
        ulonglong2 ba = bp[0], bb = bp[1];
        acc2[0][0] = acc2[1][0] = ba.x; acc2[0][1] = acc2[1][1] = ba.y;
        acc2[0][2] = acc2[1][2] = bb.x; acc2[0][3] = acc2[1][3] = bb.y;
    }
    const float* h0 = Hs + ty2 * 68;
#pragma unroll 4
    for (int k = 0; k < 64; k++) {
        const ulonglong2* wp = (const ulonglong2*)(W2s + k * 32 + tx2 * 8);
        ulonglong2 wa = wp[0], wb = wp[1];
        ull w[4] = { wa.x, wa.y, wb.x, wb.y };
        ull xa = pack2(h0[k]);
        ull xb = pack2(h0[64 * 68 + k]);
#pragma unroll
        for (int j = 0; j < 4; j++) {
            acc2[0][j] = fma2(xa, w[j], acc2[0][j]);
            acc2[1][j] = fma2(xb, w[j], acc2[1][j]);
        }
    }

#pragma unroll
    for (int i = 0; i < 2; i++) {
        const int r = ty2 + 64 * i;
        const int node = n0 + r;
        if (node < N_NODES) {
            float o[8];
#pragma unroll
            for (int j = 0; j < 4; j++) {
                float2 v = unpack2(acc2[i][j]);
                o[2 * j] = v.x; o[2 * j + 1] = v.y;
            }
            *(float4*)(n_out + (size_t)node * 32 + tx2 * 8)     = make_float4(o[0], o[1], o[2], o[3]);
            *(float4*)(n_out + (size_t)node * 32 + tx2 * 8 + 4) = make_float4(o[4], o[5], o[6], o[7]);
            const int gi = n2g[node];
            float* np = Ns + gi * 32 + tx2 * 8;
#pragma unroll
            for (int q = 0; q < 8; q++) atomicAdd(np + q, o[q]);
        }
    }
    __syncthreads();
    atomicAdd(&g_ncomb[tid], Ns[tid]);
}

// ---------------------------------------------------------------------------
// Global kernel: u_inp = concat(n_comb, e_comb, g_repr) [8 x 96] -> MLP
// ---------------------------------------------------------------------------
__global__ void __launch_bounds__(256) global_kernel(
    const float* __restrict__ g_repr,
    const float* __restrict__ Wu1, const float* __restrict__ bu1,
    const float* __restrict__ Wu2, const float* __restrict__ bu2,
    float* __restrict__ g_out)
{
    __shared__ float U[B_GRAPH * 96];
    __shared__ float W1u[96 * HID];
    __shared__ float W2u[HID * DOUT];
    __shared__ float Hg[B_GRAPH * HID];
    const int tid = threadIdx.x;

    for (int i = tid; i < B_GRAPH * 96; i += 256) {
        const int b = i / 96, c = i % 96;
        float v;
        if (c < 32)      v = g_ncomb[b * 32 + c];
        else if (c < 64) v = g_ecomb[b * 32 + (c - 32)];
        else             v = g_repr[b * 32 + (c - 64)];
        U[i] = v;
    }
    {
        const float4* wg = (const float4*)Wu1; float4* ws = (float4*)W1u;
        for (int i = tid; i < 1536; i += 256) ws[i] = wg[i];
        const float4* w2g = (const float4*)Wu2; float4* w2s = (float4*)W2u;
        for (int i = tid; i < 512; i += 256) w2s[i] = w2g[i];
    }
    __syncthreads();

    for (int idx = tid; idx < B_GRAPH * HID; idx += 256) {
        const int b = idx >> 6, j = idx & 63;
        float s = bu1[j];
#pragma unroll 8
        for (int k = 0; k < 96; k++) s += U[b * 96 + k] * W1u[k * 64 + j];
        Hg[idx] = fmaxf(s, 0.f);
    }
    __syncthreads();
    for (int idx = tid; idx < B_GRAPH * DOUT; idx += 256) {
        const int b = idx >> 5, c = idx & 31;
        float s = bu2[c];
#pragma unroll 8
        for (int k = 0; k < 64; k++) s += Hg[b * 64 + k] * W2u[k * 32 + c];
        g_out[idx] = s;
    }
}

extern "C" void kernel_launch(void* const* d_in, const int* in_sizes, int n_in,
                              void* d_out, int out_size)
{
    const float* edge_feat = (const float*)d_in[0];
    const float* node_feat = (const float*)d_in[1];
    const float* g_repr    = (const float*)d_in[2];
    const int*   src       = (const int*)d_in[3];
    const int*   dst       = (const int*)d_in[4];
    const int*   n2g       = (const int*)d_in[5];
    const int*   e2g       = (const int*)d_in[6];
    const float* W_e1 = (const float*)d_in[7];
    const float* b_e1 = (const float*)d_in[8];
    const float* W_e2 = (const float*)d_in[9];
    const float* b_e2 = (const float*)d_in[10];
    const float* W_n1 = (const float*)d_in[11];
    const float* b_n1 = (const float*)d_in[12];
    const float* W_n2 = (const float*)d_in[13];
    const float* b_n2 = (const float*)d_in[14];
    const float* W_u1 = (const float*)d_in[15];
    const float* b_u1 = (const float*)d_in[16];
    const float* W_u2 = (const float*)d_in[17];
    const float* b_u2 = (const float*)d_in[18];

    float* out = (float*)d_out;
    float* e_out = out;                                      // [E, 32]
    float* n_out = out + (size_t)N_EDGES * DOUT;             // [N, 32]
    float* g_out = out + (size_t)(N_EDGES + N_NODES) * DOUT; // [B, 32]

    const int edge_smem = 27488 * 4;   // 109,952 B
    const int node_smem = 21344 * 4;   //  85,376 B
    cudaFuncSetAttribute(edge_kernel, cudaFuncAttributeMaxDynamicSharedMemorySize, edge_smem);
    cudaFuncSetAttribute(node_kernel, cudaFuncAttributeMaxDynamicSharedMemorySize, node_smem);

    zero_kernel<<<6250, 256>>>();
    edge_kernel<<<N_EDGES / 128, 256, edge_smem>>>(
        edge_feat, node_feat, g_repr, src, dst, e2g,
        W_e1, b_e1, W_e2, b_e2, e_out);
    node_kernel<<<(N_NODES + 127) / 128, 256, node_smem>>>(
        node_feat, g_repr, n2g, W_n1, b_n1, W_n2, b_n2, n_out);
    global_kernel<<<1, 256>>>(g_repr, W_u1, b_u1, W_u2, b_u2, g_out);
}

// round 5
// speedup vs baseline: 1.5552x; 1.3763x over previous
#include <cuda_runtime.h>
#include <cuda_bf16.h>
#include <cstdint>

#define N_NODES 50000
#define N_EDGES 800000
#define B_GRAPH 8
#define HID 64
#define DOUT 32

typedef unsigned long long ull;

__device__ __forceinline__ ull fma2(ull a, ull b, ull c) {
    ull d;
    asm("fma.rn.f32x2 %0, %1, %2, %3;" : "=l"(d) : "l"(a), "l"(b), "l"(c));
    return d;
}
__device__ __forceinline__ ull pack2(float x) {
    ull d;
    asm("mov.b64 %0, {%1, %1};" : "=l"(d) : "f"(x));
    return d;
}
__device__ __forceinline__ float2 unpack2(ull v) {
    float2 r;
    asm("mov.b64 {%0, %1}, %2;" : "=f"(r.x), "=f"(r.y) : "l"(v));
    return r;
}
__device__ __forceinline__ void mma_bf16(float* d, const uint32_t* a,
                                         uint32_t b0, uint32_t b1) {
    asm volatile(
        "mma.sync.aligned.m16n8k16.row.col.f32.bf16.bf16.f32 "
        "{%0,%1,%2,%3}, {%4,%5,%6,%7}, {%8,%9}, {%0,%1,%2,%3};"
        : "+f"(d[0]), "+f"(d[1]), "+f"(d[2]), "+f"(d[3])
        : "r"(a[0]), "r"(a[1]), "r"(a[2]), "r"(a[3]), "r"(b0), "r"(b1));
}

// -------------------- scratch (device globals) --------------------
__device__ float g_h[(size_t)N_NODES * DOUT];
__device__ float g_ecomb[B_GRAPH * DOUT];
__device__ float g_ncomb[B_GRAPH * DOUT];
// W1^T hi/lo: [n=64 rows][stride 136 bf16] (k = 0..127)
__device__ __align__(16) __nv_bfloat16 gWThi[64 * 136];
__device__ __align__(16) __nv_bfloat16 gWTlo[64 * 136];

// -------------------- zero + weight prep --------------------
__global__ void zero_kernel(const float* __restrict__ W1) {
    if (blockIdx.x == 6250) {
        for (int idx = threadIdx.x; idx < 8192; idx += 256) {
            const int k = idx >> 6, n = idx & 63;
            const float v = W1[k * 64 + n];
            const __nv_bfloat16 h = __float2bfloat16(v);
            const __nv_bfloat16 l = __float2bfloat16(v - __bfloat162float(h));
            gWThi[n * 136 + k] = h;
            gWTlo[n * 136 + k] = l;
        }
        return;
    }
    size_t i = (size_t)blockIdx.x * blockDim.x + threadIdx.x;
    if (i < (size_t)N_NODES * DOUT) g_h[i] = 0.f;
    if (i < B_GRAPH * DOUT) { g_ecomb[i] = 0.f; g_ncomb[i] = 0.f; }
}

// float8 -> bf16 hi/lo (exact residual split)
__device__ __forceinline__ void cvt8(float4 a, float4 b, uint4& hi, uint4& lo) {
    __nv_bfloat162 h0 = __floats2bfloat162_rn(a.x, a.y);
    __nv_bfloat162 h1 = __floats2bfloat162_rn(a.z, a.w);
    __nv_bfloat162 h2 = __floats2bfloat162_rn(b.x, b.y);
    __nv_bfloat162 h3 = __floats2bfloat162_rn(b.z, b.w);
    float2 f0 = __bfloat1622float2(h0), f1 = __bfloat1622float2(h1);
    float2 f2 = __bfloat1622float2(h2), f3 = __bfloat1622float2(h3);
    __nv_bfloat162 l0 = __floats2bfloat162_rn(a.x - f0.x, a.y - f0.y);
    __nv_bfloat162 l1 = __floats2bfloat162_rn(a.z - f1.x, a.w - f1.y);
    __nv_bfloat162 l2 = __floats2bfloat162_rn(b.x - f2.x, b.y - f2.y);
    __nv_bfloat162 l3 = __floats2bfloat162_rn(b.z - f3.x, b.w - f3.y);
    hi.x = *(uint32_t*)&h0; hi.y = *(uint32_t*)&h1; hi.z = *(uint32_t*)&h2; hi.w = *(uint32_t*)&h3;
    lo.x = *(uint32_t*)&l0; lo.y = *(uint32_t*)&l1; lo.z = *(uint32_t*)&l2; lo.w = *(uint32_t*)&l3;
}

// ---------------- edge kernel smem layout (bytes) ----------------
// X rows: 128 rows x 272B (136 bf16, k contiguous). WT rows: 64 x 272B.
#define SM_XHI   0        // 34816
#define SM_XLO   34816    // 34816
#define SM_WTHI  69632    // 17408
#define SM_WTLO  87040    // 17408 -> end 104448
#define SM_B1    104448   // 256
#define SM_B2    104704   // 128
#define SM_ES    104832   // 1024 -> end 105856
#define SM_W2    87040    // alias over WTLO (8192 <= 17408)
#define SM_HS    0        // alias over XHI: 128 rows x 68 f (272B) exactly
#define SM_TOTAL 105856

__global__ void __launch_bounds__(256) edge_kernel(
    const float* __restrict__ edge_feat, const float* __restrict__ node_feat,
    const float* __restrict__ g_repr, const int* __restrict__ src,
    const int* __restrict__ dst, const int* __restrict__ e2g,
    const float* __restrict__ b1, const float* __restrict__ W2,
    const float* __restrict__ b2, float* __restrict__ e_out)
{
    extern __shared__ unsigned char smem[];
    const int tid = threadIdx.x;
    const int wid = tid >> 5, lid = tid & 31;

    __nv_bfloat16* Xhi = (__nv_bfloat16*)(smem + SM_XHI);
    __nv_bfloat16* Xlo = (__nv_bfloat16*)(smem + SM_XLO);
    const __nv_bfloat16* WTh = (const __nv_bfloat16*)(smem + SM_WTHI);
    const __nv_bfloat16* WTl = (const __nv_bfloat16*)(smem + SM_WTLO);
    float* b1s = (float*)(smem + SM_B1);
    float* b2s = (float*)(smem + SM_B2);
    float* Es  = (float*)(smem + SM_ES);
    float* W2s = (float*)(smem + SM_W2);
    float* Hs  = (float*)(smem + SM_HS);

    // ---- stage WT (hi+lo), b1, b2, Es ----
    {
        uint4* dsth = (uint4*)(smem + SM_WTHI);
        uint4* dstl = (uint4*)(smem + SM_WTLO);
        const uint4* srch = (const uint4*)gWThi;
        const uint4* srcl = (const uint4*)gWTlo;
        for (int i = tid; i < 1088; i += 256) { dsth[i] = srch[i]; dstl[i] = srcl[i]; }
        if (tid < HID)  b1s[tid] = b1[tid];
        if (tid < DOUT) b2s[tid] = b2[tid];
        Es[tid] = 0.f;
    }

    const size_t e0 = (size_t)blockIdx.x * 128;

    // ---- gather + split-convert into Xhi/Xlo (2 threads per edge row) ----
    {
        const int r = tid >> 1, half = tid & 1;
        const size_t e = e0 + r;
        const int si = src[e], di = dst[e], gi = e2g[e];
        const float4* p0 = (const float4*)(half ? node_feat + (size_t)di * 32
                                                : edge_feat + e * 32);
        const float4* p1 = (const float4*)(half ? g_repr + (size_t)gi * 32
                                                : node_feat + (size_t)si * 32);
        const int kb = half * 64;
        __nv_bfloat16* xh = Xhi + r * 136 + kb;
        __nv_bfloat16* xl = Xlo + r * 136 + kb;
#pragma unroll
        for (int g = 0; g < 4; g++) {
            uint4 hi, lo;
            cvt8(p0[2 * g], p0[2 * g + 1], hi, lo);
            *(uint4*)(xh + g * 8) = hi;
            *(uint4*)(xl + g * 8) = lo;
        }
#pragma unroll
        for (int g = 0; g < 4; g++) {
            uint4 hi, lo;
            cvt8(p1[2 * g], p1[2 * g + 1], hi, lo);
            *(uint4*)(xh + 32 + g * 8) = hi;
            *(uint4*)(xl + 32 + g * 8) = lo;
        }
    }
    __syncthreads();

    // ---- GEMM1 via mma.sync m16n8k16 bf16, 4-term hi/lo split ----
    // warp wid owns edge rows 16*wid .. 16*wid+15
    const int g = lid >> 2, t = lid & 3;
    const int r0 = 16 * wid + g;
    float acc[8][4];
#pragma unroll
    for (int n0 = 0; n0 < 8; n0++)
#pragma unroll
        for (int j = 0; j < 4; j++) acc[n0][j] = 0.f;

#pragma unroll
    for (int ks = 0; ks < 8; ks++) {
        const int c0 = ks * 16 + 2 * t;
        const __nv_bfloat16* xh = Xhi + r0 * 136 + c0;
        const __nv_bfloat16* xl = Xlo + r0 * 136 + c0;
        uint32_t ah[4], al[4];
        ah[0] = *(const uint32_t*)(xh);
        ah[1] = *(const uint32_t*)(xh + 8 * 136);
        ah[2] = *(const uint32_t*)(xh + 8);
        ah[3] = *(const uint32_t*)(xh + 8 * 136 + 8);
        al[0] = *(const uint32_t*)(xl);
        al[1] = *(const uint32_t*)(xl + 8 * 136);
        al[2] = *(const uint32_t*)(xl + 8);
        al[3] = *(const uint32_t*)(xl + 8 * 136 + 8);
#pragma unroll
        for (int n0 = 0; n0 < 8; n0++) {
            const __nv_bfloat16* wh = WTh + (n0 * 8 + g) * 136 + c0;
            const __nv_bfloat16* wl = WTl + (n0 * 8 + g) * 136 + c0;
            uint32_t bh0 = *(const uint32_t*)(wh);
            uint32_t bh1 = *(const uint32_t*)(wh + 8);
            uint32_t bl0 = *(const uint32_t*)(wl);
            uint32_t bl1 = *(const uint32_t*)(wl + 8);
            mma_bf16(acc[n0], ah, bh0, bh1);
            mma_bf16(acc[n0], ah, bl0, bl1);
            mma_bf16(acc[n0], al, bh0, bh1);
            mma_bf16(acc[n0], al, bl0, bl1);
        }
    }

    // ---- bias + relu -> Hs (aliases Xhi, warp-local rows: no barrier needed) ----
    {
        float* h0 = Hs + r0 * 68;
        float* h1 = Hs + (r0 + 8) * 68;
#pragma unroll
        for (int n0 = 0; n0 < 8; n0++) {
            const int n = n0 * 8 + 2 * t;
            float2 bb = *(const float2*)(b1s + n);
            float2 v0 = make_float2(fmaxf(acc[n0][0] + bb.x, 0.f),
                                    fmaxf(acc[n0][1] + bb.y, 0.f));
            float2 v1 = make_float2(fmaxf(acc[n0][2] + bb.x, 0.f),
                                    fmaxf(acc[n0][3] + bb.y, 0.f));
            *(float2*)(h0 + n) = v0;
            *(float2*)(h1 + n) = v1;
        }
    }
    __syncthreads();   // all mma reads of WTlo + H writes complete

    // ---- stage W2 into dead WTlo region ----
    {
        const float4* w2g = (const float4*)W2; float4* w2s = (float4*)W2s;
        for (int i = tid; i < 512; i += 256) w2s[i] = w2g[i];
    }
    __syncthreads();

    // ---- GEMM2: 128x32x64 in f32x2 ----
    const int tx2 = tid & 3, ty2 = tid >> 2;
    ull acc2[2][4];
    {
        const ulonglong2* bp = (const ulonglong2*)(b2s + tx2 * 8);
        ulonglong2 ba = bp[0], bb = bp[1];
        acc2[0][0] = acc2[1][0] = ba.x; acc2[0][1] = acc2[1][1] = ba.y;
        acc2[0][2] = acc2[1][2] = bb.x; acc2[0][3] = acc2[1][3] = bb.y;
    }
    const float* h0 = Hs + ty2 * 68;
#pragma unroll 4
    for (int k = 0; k < 64; k++) {
        const ulonglong2* wp = (const ulonglong2*)(W2s + k * 32 + tx2 * 8);
        ulonglong2 wa = wp[0], wb = wp[1];
        ull w[4] = { wa.x, wa.y, wb.x, wb.y };
        ull xa = pack2(h0[k]);
        ull xb = pack2(h0[64 * 68 + k]);
#pragma unroll
        for (int j = 0; j < 4; j++) {
            acc2[0][j] = fma2(xa, w[j], acc2[0][j]);
            acc2[1][j] = fma2(xb, w[j], acc2[1][j]);
        }
    }

    // ---- epilogue: write e_out, scatter g_h[dst], smem-reduce e_comb ----
#pragma unroll
    for (int i = 0; i < 2; i++) {
        const int r = ty2 + 64 * i;
        const size_t e = e0 + r;
        float o[8];
#pragma unroll
        for (int j = 0; j < 4; j++) {
            float2 v = unpack2(acc2[i][j]);
            o[2 * j] = v.x; o[2 * j + 1] = v.y;
        }
        *(float4*)(e_out + e * 32 + tx2 * 8)     = make_float4(o[0], o[1], o[2], o[3]);
        *(float4*)(e_out + e * 32 + tx2 * 8 + 4) = make_float4(o[4], o[5], o[6], o[7]);
        const int di = dst[e];
        float* hp = g_h + (size_t)di * 32 + tx2 * 8;
#pragma unroll
        for (int q = 0; q < 8; q++) atomicAdd(hp + q, o[q]);
        const int gi = e2g[e];
        float* ep = Es + gi * 32 + tx2 * 8;
#pragma unroll
        for (int q = 0; q < 8; q++) atomicAdd(ep + q, o[q]);
    }
    __syncthreads();
    atomicAdd(&g_ecomb[tid], Es[tid]);
}

// ---------------------------------------------------------------------------
// Node kernel: tile = 128 nodes, X[128][96] -> MLP 96->64->32, f32x2
// ---------------------------------------------------------------------------
__global__ void __launch_bounds__(256) node_kernel(
    const float* __restrict__ node_feat, const float* __restrict__ g_repr,
    const int* __restrict__ n2g,
    const float* __restrict__ W1, const float* __restrict__ b1,
    const float* __restrict__ W2, const float* __restrict__ b2,
    float* __restrict__ n_out)
{
    extern __shared__ float sm[];
    float* W1s = sm;              // 6144
    float* W2s = sm + 6144;       // 2048
    float* b1s = sm + 8192;       // 64
    float* b2s = sm + 8256;       // 32
    float* Ns  = sm + 8288;       // 256
    float* Xs  = sm + 8544;       // 128 x 100
    float* Hs  = Xs;              // alias, stride 68

    const int tid = threadIdx.x;
    {
        const float4* wg = (const float4*)W1;  float4* ws = (float4*)W1s;
        for (int i = tid; i < 1536; i += 256) ws[i] = wg[i];
        const float4* w2g = (const float4*)W2; float4* w2s = (float4*)W2s;
        for (int i = tid; i < 512; i += 256) w2s[i] = w2g[i];
        if (tid < HID)  b1s[tid] = b1[tid];
        if (tid < DOUT) b2s[tid] = b2[tid];
        Ns[tid] = 0.f;
    }

    const int n0 = blockIdx.x * 128;

    for (int s = tid; s < 3072; s += 256) {
        const int r = s / 24, q = s % 24;
        const int node = n0 + r;
        float4 v = make_float4(0.f, 0.f, 0.f, 0.f);
        if (node < N_NODES) {
            if (q < 8)       v = ((const float4*)(node_feat + (size_t)node * 32))[q];
            else if (q < 16) v = ((const float4*)(g_h + (size_t)node * 32))[q - 8];
            else {
                const int gi = n2g[node];
                v = ((const float4*)(g_repr + (size_t)gi * 32))[q - 16];
            }
        }
        *(float4*)(Xs + r * 100 + q * 4) = v;
    }
    __syncthreads();

    const int tx = tid & 7, ty = tid >> 3;
    ull acc1[4][4];
    {
        const ulonglong2* bp = (const ulonglong2*)(b1s + tx * 8);
        ulonglong2 ba = bp[0], bb = bp[1];
#pragma unroll
        for (int i = 0; i < 4; i++) {
            acc1[i][0] = ba.x; acc1[i][1] = ba.y;
            acc1[i][2] = bb.x; acc1[i][3] = bb.y;
        }
    }
    const float* x0 = Xs + ty * 100;
#pragma unroll 4
    for (int k = 0; k < 96; k++) {
        const ulonglong2* wp = (const ulonglong2*)(W1s + k * 64 + tx * 8);
        ulonglong2 wa = wp[0], wb = wp[1];
        ull w[4] = { wa.x, wa.y, wb.x, wb.y };
        ull xp[4];
        xp[0] = pack2(x0[k]);
        xp[1] = pack2(x0[3200 + k]);
        xp[2] = pack2(x0[6400 + k]);
        xp[3] = pack2(x0[9600 + k]);
#pragma unroll
        for (int i = 0; i < 4; i++)
#pragma unroll
            for (int j = 0; j < 4; j++)
                acc1[i][j] = fma2(xp[i], w[j], acc1[i][j]);
    }
    __syncthreads();

#pragma unroll
    for (int i = 0; i < 4; i++) {
        float* hr = Hs + (ty + 32 * i) * 68 + tx * 8;
#pragma unroll
        for (int j = 0; j < 4; j++) {
            float2 v = unpack2(acc1[i][j]);
            hr[2 * j]     = fmaxf(v.x, 0.f);
            hr[2 * j + 1] = fmaxf(v.y, 0.f);
        }
    }
    __syncthreads();

    const int tx2 = tid & 3, ty2 = tid >> 2;
    ull acc2[2][4];
    {
        const ulonglong2* bp = (const ulonglong2*)(b2s + tx2 * 8);
        ulonglong2 ba = bp[0], bb = bp[1];
        acc2[0][0] = acc2[1][0] = ba.x; acc2[0][1] = acc2[1][1] = ba.y;
        acc2[0][2] = acc2[1][2] = bb.x; acc2[0][3] = acc2[1][3] = bb.y;
    }
    const float* h0 = Hs + ty2 * 68;
#pragma unroll 4
    for (int k = 0; k < 64; k++) {
        const ulonglong2* wp = (const ulonglong2*)(W2s + k * 32 + tx2 * 8);
        ulonglong2 wa = wp[0], wb = wp[1];
        ull w[4] = { wa.x, wa.y, wb.x, wb.y };
        ull xa = pack2(h0[k]);
        ull xb = pack2(h0[64 * 68 + k]);
#pragma unroll
        for (int j = 0; j < 4; j++) {
            acc2[0][j] = fma2(xa, w[j], acc2[0][j]);
            acc2[1][j] = fma2(xb, w[j], acc2[1][j]);
        }
    }

#pragma unroll
    for (int i = 0; i < 2; i++) {
        const int r = ty2 + 64 * i;
        const int node = n0 + r;
        if (node < N_NODES) {
            float o[8];
#pragma unroll
            for (int j = 0; j < 4; j++) {
                float2 v = unpack2(acc2[i][j]);
                o[2 * j] = v.x; o[2 * j + 1] = v.y;
            }
            *(float4*)(n_out + (size_t)node * 32 + tx2 * 8)     = make_float4(o[0], o[1], o[2], o[3]);
            *(float4*)(n_out + (size_t)node * 32 + tx2 * 8 + 4) = make_float4(o[4], o[5], o[6], o[7]);
            const int gi = n2g[node];
            float* np = Ns + gi * 32 + tx2 * 8;
#pragma unroll
            for (int q = 0; q < 8; q++) atomicAdd(np + q, o[q]);
        }
    }
    __syncthreads();
    atomicAdd(&g_ncomb[tid], Ns[tid]);
}

// ---------------------------------------------------------------------------
// Global kernel
// ---------------------------------------------------------------------------
__global__ void __launch_bounds__(256) global_kernel(
    const float* __restrict__ g_repr,
    const float* __restrict__ Wu1, const float* __restrict__ bu1,
    const float* __restrict__ Wu2, const float* __restrict__ bu2,
    float* __restrict__ g_out)
{
    __shared__ float U[B_GRAPH * 96];
    __shared__ float W1u[96 * HID];
    __shared__ float W2u[HID * DOUT];
    __shared__ float Hg[B_GRAPH * HID];
    const int tid = threadIdx.x;

    for (int i = tid; i < B_GRAPH * 96; i += 256) {
        const int b = i / 96, c = i % 96;
        float v;
        if (c < 32)      v = g_ncomb[b * 32 + c];
        else if (c < 64) v = g_ecomb[b * 32 + (c - 32)];
        else             v = g_repr[b * 32 + (c - 64)];
        U[i] = v;
    }
    {
        const float4* wg = (const float4*)Wu1; float4* ws = (float4*)W1u;
        for (int i = tid; i < 1536; i += 256) ws[i] = wg[i];
        const float4* w2g = (const float4*)Wu2; float4* w2s = (float4*)W2u;
        for (int i = tid; i < 512; i += 256) w2s[i] = w2g[i];
    }
    __syncthreads();

    for (int idx = tid; idx < B_GRAPH * HID; idx += 256) {
        const int b = idx >> 6, j = idx & 63;
        float s = bu1[j];
#pragma unroll 8
        for (int k = 0; k < 96; k++) s += U[b * 96 + k] * W1u[k * 64 + j];
        Hg[idx] = fmaxf(s, 0.f);
    }
    __syncthreads();
    for (int idx = tid; idx < B_GRAPH * DOUT; idx += 256) {
        const int b = idx >> 5, c = idx & 31;
        float s = bu2[c];
#pragma unroll 8
        for (int k = 0; k < 64; k++) s += Hg[b * 64 + k] * W2u[k * 32 + c];
        g_out[idx] = s;
    }
}

extern "C" void kernel_launch(void* const* d_in, const int* in_sizes, int n_in,
                              void* d_out, int out_size)
{
    const float* edge_feat = (const float*)d_in[0];
    const float* node_feat = (const float*)d_in[1];
    const float* g_repr    = (const float*)d_in[2];
    const int*   src       = (const int*)d_in[3];
    const int*   dst       = (const int*)d_in[4];
    const int*   n2g       = (const int*)d_in[5];
    const int*   e2g       = (const int*)d_in[6];
    const float* W_e1 = (const float*)d_in[7];
    const float* b_e1 = (const float*)d_in[8];
    const float* W_e2 = (const float*)d_in[9];
    const float* b_e2 = (const float*)d_in[10];
    const float* W_n1 = (const float*)d_in[11];
    const float* b_n1 = (const float*)d_in[12];
    const float* W_n2 = (const float*)d_in[13];
    const float* b_n2 = (const float*)d_in[14];
    const float* W_u1 = (const float*)d_in[15];
    const float* b_u1 = (const float*)d_in[16];
    const float* W_u2 = (const float*)d_in[17];
    const float* b_u2 = (const float*)d_in[18];

    float* out = (float*)d_out;
    float* e_out = out;                                      // [E, 32]
    float* n_out = out + (size_t)N_EDGES * DOUT;             // [N, 32]
    float* g_out = out + (size_t)(N_EDGES + N_NODES) * DOUT; // [B, 32]

    const int node_smem = 21344 * 4;
    cudaFuncSetAttribute(edge_kernel, cudaFuncAttributeMaxDynamicSharedMemorySize, SM_TOTAL);
    cudaFuncSetAttribute(node_kernel, cudaFuncAttributeMaxDynamicSharedMemorySize, node_smem);

    zero_kernel<<<6251, 256>>>(W_e1);
    edge_kernel<<<N_EDGES / 128, 256, SM_TOTAL>>>(
        edge_feat, node_feat, g_repr, src, dst, e2g,
        b_e1, W_e2, b_e2, e_out);
    node_kernel<<<(N_NODES + 127) / 128, 256, node_smem>>>(
        node_feat, g_repr, n2g, W_n1, b_n1, W_n2, b_n2, n_out);
    global_kernel<<<1, 256>>>(g_repr, W_u1, b_u1, W_u2, b_u2, g_out);
}

// round 6
// speedup vs baseline: 1.6784x; 1.0793x over previous
#include <cuda_runtime.h>
#include <cuda_bf16.h>
#include <cstdint>

#define N_NODES 50000
#define N_EDGES 800000
#define B_GRAPH 8
#define HID 64
#define DOUT 32

typedef unsigned long long ull;

__device__ __forceinline__ ull fma2(ull a, ull b, ull c) {
    ull d;
    asm("fma.rn.f32x2 %0, %1, %2, %3;" : "=l"(d) : "l"(a), "l"(b), "l"(c));
    return d;
}
__device__ __forceinline__ ull pack2(float x) {
    ull d;
    asm("mov.b64 %0, {%1, %1};" : "=l"(d) : "f"(x));
    return d;
}
__device__ __forceinline__ float2 unpack2(ull v) {
    float2 r;
    asm("mov.b64 {%0, %1}, %2;" : "=f"(r.x), "=f"(r.y) : "l"(v));
    return r;
}
__device__ __forceinline__ void mma_bf16(float* d, const uint32_t* a,
                                         uint32_t b0, uint32_t b1) {
    asm volatile(
        "mma.sync.aligned.m16n8k16.row.col.f32.bf16.bf16.f32 "
        "{%0,%1,%2,%3}, {%4,%5,%6,%7}, {%8,%9}, {%0,%1,%2,%3};"
        : "+f"(d[0]), "+f"(d[1]), "+f"(d[2]), "+f"(d[3])
        : "r"(a[0]), "r"(a[1]), "r"(a[2]), "r"(a[3]), "r"(b0), "r"(b1));
}
__device__ __forceinline__ void red2(float* p, float x, float y) {
    asm volatile("red.global.add.v2.f32 [%0], {%1, %2};"
                 :: "l"(p), "f"(x), "f"(y) : "memory");
}

// -------------------- scratch (device globals) --------------------
__device__ float g_h[(size_t)N_NODES * DOUT];
__device__ float g_ecomb[B_GRAPH * DOUT];
__device__ float g_ncomb[B_GRAPH * DOUT];
// W1^T hi/lo: [n=64][stride 136] bf16 (k = 0..127)
__device__ __align__(16) __nv_bfloat16 gWThi[64 * 136];
__device__ __align__(16) __nv_bfloat16 gWTlo[64 * 136];
// W2^T hi/lo: [n=32][stride 72] bf16 (k = 0..63)
__device__ __align__(16) __nv_bfloat16 gWT2hi[32 * 72];
__device__ __align__(16) __nv_bfloat16 gWT2lo[32 * 72];

// -------------------- zero + weight prep --------------------
__global__ void zero_kernel(const float* __restrict__ W1,
                            const float* __restrict__ W2) {
    if (blockIdx.x == 6250) {
        for (int idx = threadIdx.x; idx < 8192; idx += 256) {
            const int k = idx >> 6, n = idx & 63;
            const float v = W1[k * 64 + n];
            const __nv_bfloat16 h = __float2bfloat16(v);
            const __nv_bfloat16 l = __float2bfloat16(v - __bfloat162float(h));
            gWThi[n * 136 + k] = h;
            gWTlo[n * 136 + k] = l;
        }
        for (int idx = threadIdx.x; idx < 2048; idx += 256) {
            const int k = idx >> 5, n = idx & 31;
            const float v = W2[k * 32 + n];
            const __nv_bfloat16 h = __float2bfloat16(v);
            const __nv_bfloat16 l = __float2bfloat16(v - __bfloat162float(h));
            gWT2hi[n * 72 + k] = h;
            gWT2lo[n * 72 + k] = l;
        }
        return;
    }
    size_t i = (size_t)blockIdx.x * blockDim.x + threadIdx.x;
    if (i < (size_t)N_NODES * DOUT) g_h[i] = 0.f;
    if (i < B_GRAPH * DOUT) { g_ecomb[i] = 0.f; g_ncomb[i] = 0.f; }
}

// float8 -> bf16 hi/lo (exact residual split)
__device__ __forceinline__ void cvt8(float4 a, float4 b, uint4& hi, uint4& lo) {
    __nv_bfloat162 h0 = __floats2bfloat162_rn(a.x, a.y);
    __nv_bfloat162 h1 = __floats2bfloat162_rn(a.z, a.w);
    __nv_bfloat162 h2 = __floats2bfloat162_rn(b.x, b.y);
    __nv_bfloat162 h3 = __floats2bfloat162_rn(b.z, b.w);
    float2 f0 = __bfloat1622float2(h0), f1 = __bfloat1622float2(h1);
    float2 f2 = __bfloat1622float2(h2), f3 = __bfloat1622float2(h3);
    __nv_bfloat162 l0 = __floats2bfloat162_rn(a.x - f0.x, a.y - f0.y);
    __nv_bfloat162 l1 = __floats2bfloat162_rn(a.z - f1.x, a.w - f1.y);
    __nv_bfloat162 l2 = __floats2bfloat162_rn(b.x - f2.x, b.y - f2.y);
    __nv_bfloat162 l3 = __floats2bfloat162_rn(b.z - f3.x, b.w - f3.y);
    hi.x = *(uint32_t*)&h0; hi.y = *(uint32_t*)&h1; hi.z = *(uint32_t*)&h2; hi.w = *(uint32_t*)&h3;
    lo.x = *(uint32_t*)&l0; lo.y = *(uint32_t*)&l1; lo.z = *(uint32_t*)&l2; lo.w = *(uint32_t*)&l3;
}

// ---------------- edge kernel smem layout (bytes) ----------------
#define SM_XHI   0        // 128 rows x 272B
#define SM_XLO   34816
#define SM_WTHI  69632    // 64 x 272B
#define SM_WTLO  87040    // 64 x 272B (aliased by WT2 hi/lo after GEMM1)
#define SM_B1    104448   // 256
#define SM_B2    104704   // 128
#define SM_ES    104832   // 1024
#define SM_WT2HI 87040    // 32 x 144B = 4608
#define SM_WT2LO 91648    // 4608
#define SM_TOTAL 105856

__global__ void __launch_bounds__(256) edge_kernel(
    const float* __restrict__ edge_feat, const float* __restrict__ node_feat,
    const float* __restrict__ g_repr, const int* __restrict__ src,
    const int* __restrict__ dst, const int* __restrict__ e2g,
    const float* __restrict__ b1, const float* __restrict__ b2,
    float* __restrict__ e_out)
{
    extern __shared__ unsigned char smem[];
    const int tid = threadIdx.x;
    const int wid = tid >> 5, lid = tid & 31;

    __nv_bfloat16* Xhi = (__nv_bfloat16*)(smem + SM_XHI);
    __nv_bfloat16* Xlo = (__nv_bfloat16*)(smem + SM_XLO);
    const __nv_bfloat16* WTh = (const __nv_bfloat16*)(smem + SM_WTHI);
    const __nv_bfloat16* WTl = (const __nv_bfloat16*)(smem + SM_WTLO);
    const __nv_bfloat16* W2h = (const __nv_bfloat16*)(smem + SM_WT2HI);
    const __nv_bfloat16* W2l = (const __nv_bfloat16*)(smem + SM_WT2LO);
    float* b1s = (float*)(smem + SM_B1);
    float* b2s = (float*)(smem + SM_B2);
    float* Es  = (float*)(smem + SM_ES);

    // ---- stage WT1 (hi+lo), biases, Es ----
    {
        uint4* dsth = (uint4*)(smem + SM_WTHI);
        uint4* dstl = (uint4*)(smem + SM_WTLO);
        const uint4* srch = (const uint4*)gWThi;
        const uint4* srcl = (const uint4*)gWTlo;
        for (int i = tid; i < 1088; i += 256) { dsth[i] = srch[i]; dstl[i] = srcl[i]; }
        if (tid < HID)  b1s[tid] = b1[tid];
        if (tid < DOUT) b2s[tid] = b2[tid];
        Es[tid] = 0.f;
    }

    const size_t e0 = (size_t)blockIdx.x * 128;

    // ---- gather + split-convert into Xhi/Xlo (2 threads per edge row) ----
    {
        const int r = tid >> 1, half = tid & 1;
        const size_t e = e0 + r;
        const int si = src[e], di = dst[e], gi = e2g[e];
        const float4* p0 = (const float4*)(half ? node_feat + (size_t)di * 32
                                                : edge_feat + e * 32);
        const float4* p1 = (const float4*)(half ? g_repr + (size_t)gi * 32
                                                : node_feat + (size_t)si * 32);
        const int kb = half * 64;
        __nv_bfloat16* xh = Xhi + r * 136 + kb;
        __nv_bfloat16* xl = Xlo + r * 136 + kb;
#pragma unroll
        for (int g = 0; g < 4; g++) {
            uint4 hi, lo;
            cvt8(p0[2 * g], p0[2 * g + 1], hi, lo);
            *(uint4*)(xh + g * 8) = hi;
            *(uint4*)(xl + g * 8) = lo;
        }
#pragma unroll
        for (int g = 0; g < 4; g++) {
            uint4 hi, lo;
            cvt8(p1[2 * g], p1[2 * g + 1], hi, lo);
            *(uint4*)(xh + 32 + g * 8) = hi;
            *(uint4*)(xl + 32 + g * 8) = lo;
        }
    }
    __syncthreads();

    // ---- GEMM1: mma m16n8k16 bf16, 3-term hi/lo split ----
    const int g = lid >> 2, t = lid & 3;
    const int r0 = 16 * wid + g;
    float acc[8][4];
#pragma unroll
    for (int n0 = 0; n0 < 8; n0++)
#pragma unroll
        for (int j = 0; j < 4; j++) acc[n0][j] = 0.f;

#pragma unroll
    for (int ks = 0; ks < 8; ks++) {
        const int c0 = ks * 16 + 2 * t;
        const __nv_bfloat16* xh = Xhi + r0 * 136 + c0;
        const __nv_bfloat16* xl = Xlo + r0 * 136 + c0;
        uint32_t ah[4], al[4];
        ah[0] = *(const uint32_t*)(xh);
        ah[1] = *(const uint32_t*)(xh + 8 * 136);
        ah[2] = *(const uint32_t*)(xh + 8);
        ah[3] = *(const uint32_t*)(xh + 8 * 136 + 8);
        al[0] = *(const uint32_t*)(xl);
        al[1] = *(const uint32_t*)(xl + 8 * 136);
        al[2] = *(const uint32_t*)(xl + 8);
        al[3] = *(const uint32_t*)(xl + 8 * 136 + 8);
#pragma unroll
        for (int n0 = 0; n0 < 8; n0++) {
            const __nv_bfloat16* wh = WTh + (n0 * 8 + g) * 136 + c0;
            const __nv_bfloat16* wl = WTl + (n0 * 8 + g) * 136 + c0;
            uint32_t bh0 = *(const uint32_t*)(wh);
            uint32_t bh1 = *(const uint32_t*)(wh + 8);
            uint32_t bl0 = *(const uint32_t*)(wl);
            uint32_t bl1 = *(const uint32_t*)(wl + 8);
            mma_bf16(acc[n0], ah, bh0, bh1);
            mma_bf16(acc[n0], ah, bl0, bl1);
            mma_bf16(acc[n0], al, bh0, bh1);
        }
    }

    // ---- bias + relu + register split: H -> bf16 hi/lo A-fragments ----
    // Ahi[ks2][i]: i0 = (rows g, k=16ks2+2t), i1 = (g+8, same), i2/i3 = k+8
    uint32_t Ahi[4][4], Alo[4][4];
#pragma unroll
    for (int n0 = 0; n0 < 8; n0++) {
        float2 bb = *(const float2*)(b1s + n0 * 8 + 2 * t);
        float v0 = fmaxf(acc[n0][0] + bb.x, 0.f);
        float v1 = fmaxf(acc[n0][1] + bb.y, 0.f);
        float v2 = fmaxf(acc[n0][2] + bb.x, 0.f);
        float v3 = fmaxf(acc[n0][3] + bb.y, 0.f);
        __nv_bfloat162 hA = __floats2bfloat162_rn(v0, v1);
        __nv_bfloat162 hB = __floats2bfloat162_rn(v2, v3);
        float2 fA = __bfloat1622float2(hA), fB = __bfloat1622float2(hB);
        __nv_bfloat162 lA = __floats2bfloat162_rn(v0 - fA.x, v1 - fA.y);
        __nv_bfloat162 lB = __floats2bfloat162_rn(v2 - fB.x, v3 - fB.y);
        const int ks2 = n0 >> 1, ib = (n0 & 1) * 2;
        Ahi[ks2][ib + 0] = *(uint32_t*)&hA;
        Ahi[ks2][ib + 1] = *(uint32_t*)&hB;
        Alo[ks2][ib + 0] = *(uint32_t*)&lA;
        Alo[ks2][ib + 1] = *(uint32_t*)&lB;
    }
    __syncthreads();   // all GEMM1 reads of WTlo complete

    // ---- stage WT2 hi/lo into dead WTlo region ----
    {
        uint4* d2h = (uint4*)(smem + SM_WT2HI);
        uint4* d2l = (uint4*)(smem + SM_WT2LO);
        const uint4* s2h = (const uint4*)gWT2hi;
        const uint4* s2l = (const uint4*)gWT2lo;
        for (int i = tid; i < 288; i += 256) { d2h[i] = s2h[i]; d2l[i] = s2l[i]; }
    }
    __syncthreads();

    // ---- GEMM2: mma m16n8k16, K=64, 3-term, H in registers ----
    float d2[4][4];
#pragma unroll
    for (int nb = 0; nb < 4; nb++)
#pragma unroll
        for (int j = 0; j < 4; j++) d2[nb][j] = 0.f;

#pragma unroll
    for (int ks2 = 0; ks2 < 4; ks2++) {
        const int c0 = ks2 * 16 + 2 * t;
#pragma unroll
        for (int nb = 0; nb < 4; nb++) {
            const __nv_bfloat16* wh = W2h + (nb * 8 + g) * 72 + c0;
            const __nv_bfloat16* wl = W2l + (nb * 8 + g) * 72 + c0;
            uint32_t bh0 = *(const uint32_t*)(wh);
            uint32_t bh1 = *(const uint32_t*)(wh + 8);
            uint32_t bl0 = *(const uint32_t*)(wl);
            uint32_t bl1 = *(const uint32_t*)(wl + 8);
            mma_bf16(d2[nb], Ahi[ks2], bh0, bh1);
            mma_bf16(d2[nb], Ahi[ks2], bl0, bl1);
            mma_bf16(d2[nb], Alo[ks2], bh0, bh1);
        }
    }

    // ---- epilogue from D fragments: rows r0 and r0+8 ----
    {
        const size_t eA = e0 + r0, eB = eA + 8;
        const int dA = dst[eA], dB = dst[eB];
        const int gA = e2g[eA], gB = e2g[eB];
        float* hA = g_h + (size_t)dA * 32;
        float* hB = g_h + (size_t)dB * 32;
        float* oA = e_out + eA * 32;
        float* oB = e_out + eB * 32;
#pragma unroll
        for (int nb = 0; nb < 4; nb++) {
            const int col = nb * 8 + 2 * t;
            float2 bb = *(const float2*)(b2s + col);
            float a0 = d2[nb][0] + bb.x, a1 = d2[nb][1] + bb.y;
            float c0v = d2[nb][2] + bb.x, c1 = d2[nb][3] + bb.y;
            *(float2*)(oA + col) = make_float2(a0, a1);
            *(float2*)(oB + col) = make_float2(c0v, c1);
            red2(hA + col, a0, a1);
            red2(hB + col, c0v, c1);
            atomicAdd(&Es[gA * 32 + col], a0);
            atomicAdd(&Es[gA * 32 + col + 1], a1);
            atomicAdd(&Es[gB * 32 + col], c0v);
            atomicAdd(&Es[gB * 32 + col + 1], c1);
        }
    }
    __syncthreads();
    atomicAdd(&g_ecomb[tid], Es[tid]);
}

// ---------------------------------------------------------------------------
// Node kernel: tile = 128 nodes, X[128][96] -> MLP 96->64->32, f32x2
// ---------------------------------------------------------------------------
__global__ void __launch_bounds__(256) node_kernel(
    const float* __restrict__ node_feat, const float* __restrict__ g_repr,
    const int* __restrict__ n2g,
    const float* __restrict__ W1, const float* __restrict__ b1,
    const float* __restrict__ W2, const float* __restrict__ b2,
    float* __restrict__ n_out)
{
    extern __shared__ float sm[];
    float* W1s = sm;              // 6144
    float* W2s = sm + 6144;       // 2048
    float* b1s = sm + 8192;       // 64
    float* b2s = sm + 8256;       // 32
    float* Ns  = sm + 8288;       // 256
    float* Xs  = sm + 8544;       // 128 x 100
    float* Hs  = Xs;              // alias, stride 68

    const int tid = threadIdx.x;
    {
        const float4* wg = (const float4*)W1;  float4* ws = (float4*)W1s;
        for (int i = tid; i < 1536; i += 256) ws[i] = wg[i];
        const float4* w2g = (const float4*)W2; float4* w2s = (float4*)W2s;
        for (int i = tid; i < 512; i += 256) w2s[i] = w2g[i];
        if (tid < HID)  b1s[tid] = b1[tid];
        if (tid < DOUT) b2s[tid] = b2[tid];
        Ns[tid] = 0.f;
    }

    const int n0 = blockIdx.x * 128;

    for (int s = tid; s < 3072; s += 256) {
        const int r = s / 24, q = s % 24;
        const int node = n0 + r;
        float4 v = make_float4(0.f, 0.f, 0.f, 0.f);
        if (node < N_NODES) {
            if (q < 8)       v = ((const float4*)(node_feat + (size_t)node * 32))[q];
            else if (q < 16) v = ((const float4*)(g_h + (size_t)node * 32))[q - 8];
            else {
                const int gi = n2g[node];
                v = ((const float4*)(g_repr + (size_t)gi * 32))[q - 16];
            }
        }
        *(float4*)(Xs + r * 100 + q * 4) = v;
    }
    __syncthreads();

    const int tx = tid & 7, ty = tid >> 3;
    ull acc1[4][4];
    {
        const ulonglong2* bp = (const ulonglong2*)(b1s + tx * 8);
        ulonglong2 ba = bp[0], bb = bp[1];
#pragma unroll
        for (int i = 0; i < 4; i++) {
            acc1[i][0] = ba.x; acc1[i][1] = ba.y;
            acc1[i][2] = bb.x; acc1[i][3] = bb.y;
        }
    }
    const float* x0 = Xs + ty * 100;
#pragma unroll 4
    for (int k = 0; k < 96; k++) {
        const ulonglong2* wp = (const ulonglong2*)(W1s + k * 64 + tx * 8);
        ulonglong2 wa = wp[0], wb = wp[1];
        ull w[4] = { wa.x, wa.y, wb.x, wb.y };
        ull xp[4];
        xp[0] = pack2(x0[k]);
        xp[1] = pack2(x0[3200 + k]);
        xp[2] = pack2(x0[6400 + k]);
        xp[3] = pack2(x0[9600 + k]);
#pragma unroll
        for (int i = 0; i < 4; i++)
#pragma unroll
            for (int j = 0; j < 4; j++)
                acc1[i][j] = fma2(xp[i], w[j], acc1[i][j]);
    }
    __syncthreads();

#pragma unroll
    for (int i = 0; i < 4; i++) {
        float* hr = Hs + (ty + 32 * i) * 68 + tx * 8;
#pragma unroll
        for (int j = 0; j < 4; j++) {
            float2 v = unpack2(acc1[i][j]);
            hr[2 * j]     = fmaxf(v.x, 0.f);
            hr[2 * j + 1] = fmaxf(v.y, 0.f);
        }
    }
    __syncthreads();

    const int tx2 = tid & 3, ty2 = tid >> 2;
    ull acc2[2][4];
    {
        const ulonglong2* bp = (const ulonglong2*)(b2s + tx2 * 8);
        ulonglong2 ba = bp[0], bb = bp[1];
        acc2[0][0] = acc2[1][0] = ba.x; acc2[0][1] = acc2[1][1] = ba.y;
        acc2[0][2] = acc2[1][2] = bb.x; acc2[0][3] = acc2[1][3] = bb.y;
    }
    const float* h0 = Hs + ty2 * 68;
#pragma unroll 4
    for (int k = 0; k < 64; k++) {
        const ulonglong2* wp = (const ulonglong2*)(W2s + k * 32 + tx2 * 8);
        ulonglong2 wa = wp[0], wb = wp[1];
        ull w[4] = { wa.x, wa.y, wb.x, wb.y };
        ull xa = pack2(h0[k]);
        ull xb = pack2(h0[64 * 68 + k]);
#pragma unroll
        for (int j = 0; j < 4; j++) {
            acc2[0][j] = fma2(xa, w[j], acc2[0][j]);
            acc2[1][j] = fma2(xb, w[j], acc2[1][j]);
        }
    }

#pragma unroll
    for (int i = 0; i < 2; i++) {
        const int r = ty2 + 64 * i;
        const int node = n0 + r;
        if (node < N_NODES) {
            float o[8];
#pragma unroll
            for (int j = 0; j < 4; j++) {
                float2 v = unpack2(acc2[i][j]);
                o[2 * j] = v.x; o[2 * j + 1] = v.y;
            }
            *(float4*)(n_out + (size_t)node * 32 + tx2 * 8)     = make_float4(o[0], o[1], o[2], o[3]);
            *(float4*)(n_out + (size_t)node * 32 + tx2 * 8 + 4) = make_float4(o[4], o[5], o[6], o[7]);
            const int gi = n2g[node];
            float* np = Ns + gi * 32 + tx2 * 8;
#pragma unroll
            for (int q = 0; q < 8; q++) atomicAdd(np + q, o[q]);
        }
    }
    __syncthreads();
    atomicAdd(&g_ncomb[tid], Ns[tid]);
}

// ---------------------------------------------------------------------------
// Global kernel
// ---------------------------------------------------------------------------
__global__ void __launch_bounds__(256) global_kernel(
    const float* __restrict__ g_repr,
    const float* __restrict__ Wu1, const float* __restrict__ bu1,
    const float* __restrict__ Wu2, const float* __restrict__ bu2,
    float* __restrict__ g_out)
{
    __shared__ float U[B_GRAPH * 96];
    __shared__ float W1u[96 * HID];
    __shared__ float W2u[HID * DOUT];
    __shared__ float Hg[B_GRAPH * HID];
    const int tid = threadIdx.x;

    for (int i = tid; i < B_GRAPH * 96; i += 256) {
        const int b = i / 96, c = i % 96;
        float v;
        if (c < 32)      v = g_ncomb[b * 32 + c];
        else if (c < 64) v = g_ecomb[b * 32 + (c - 32)];
        else             v = g_repr[b * 32 + (c - 64)];
        U[i] = v;
    }
    {
        const float4* wg = (const float4*)Wu1; float4* ws = (float4*)W1u;
        for (int i = tid; i < 1536; i += 256) ws[i] = wg[i];
        const float4* w2g = (const float4*)Wu2; float4* w2s = (float4*)W2u;
        for (int i = tid; i < 512; i += 256) w2s[i] = w2g[i];
    }
    __syncthreads();

    for (int idx = tid; idx < B_GRAPH * HID; idx += 256) {
        const int b = idx >> 6, j = idx & 63;
        float s = bu1[j];
#pragma unroll 8
        for (int k = 0; k < 96; k++) s += U[b * 96 + k] * W1u[k * 64 + j];
        Hg[idx] = fmaxf(s, 0.f);
    }
    __syncthreads();
    for (int idx = tid; idx < B_GRAPH * DOUT; idx += 256) {
        const int b = idx >> 5, c = idx & 31;
        float s = bu2[c];
#pragma unroll 8
        for (int k = 0; k < 64; k++) s += Hg[b * 64 + k] * W2u[k * 32 + c];
        g_out[idx] = s;
    }
}

extern "C" void kernel_launch(void* const* d_in, const int* in_sizes, int n_in,
                              void* d_out, int out_size)
{
    const float* edge_feat = (const float*)d_in[0];
    const float* node_feat = (const float*)d_in[1];
    const float* g_repr    = (const float*)d_in[2];
    const int*   src       = (const int*)d_in[3];
    const int*   dst       = (const int*)d_in[4];
    const int*   n2g       = (const int*)d_in[5];
    const int*   e2g       = (const int*)d_in[6];
    const float* W_e1 = (const float*)d_in[7];
    const float* b_e1 = (const float*)d_in[8];
    const float* W_e2 = (const float*)d_in[9];
    const float* b_e2 = (const float*)d_in[10];
    const float* W_n1 = (const float*)d_in[11];
    const float* b_n1 = (const float*)d_in[12];
    const float* W_n2 = (const float*)d_in[13];
    const float* b_n2 = (const float*)d_in[14];
    const float* W_u1 = (const float*)d_in[15];
    const float* b_u1 = (const float*)d_in[16];
    const float* W_u2 = (const float*)d_in[17];
    const float* b_u2 = (const float*)d_in[18];

    float* out = (float*)d_out;
    float* e_out = out;                                      // [E, 32]
    float* n_out = out + (size_t)N_EDGES * DOUT;             // [N, 32]
    float* g_out = out + (size_t)(N_EDGES + N_NODES) * DOUT; // [B, 32]

    const int node_smem = 21344 * 4;
    cudaFuncSetAttribute(edge_kernel, cudaFuncAttributeMaxDynamicSharedMemorySize, SM_TOTAL);
    cudaFuncSetAttribute(node_kernel, cudaFuncAttributeMaxDynamicSharedMemorySize, node_smem);

    zero_kernel<<<6251, 256>>>(W_e1, W_e2);
    edge_kernel<<<N_EDGES / 128, 256, SM_TOTAL>>>(
        edge_feat, node_feat, g_repr, src, dst, e2g,
        b_e1, b_e2, e_out);
    node_kernel<<<(N_NODES + 127) / 128, 256, node_smem>>>(
        node_feat, g_repr, n2g, W_n1, b_n1, W_n2, b_n2, n_out);
    global_kernel<<<1, 256>>>(g_repr, W_u1, b_u1, W_u2, b_u2, g_out);
}

// round 7
// speedup vs baseline: 3.1313x; 1.8656x over previous
#include <cuda_runtime.h>
#include <cuda_bf16.h>
#include <cstdint>

#define N_NODES 50000
#define N_EDGES 800000
#define B_GRAPH 8
#define HID 64
#define DOUT 32

typedef unsigned long long ull;

__device__ __forceinline__ ull fma2(ull a, ull b, ull c) {
    ull d;
    asm("fma.rn.f32x2 %0, %1, %2, %3;" : "=l"(d) : "l"(a), "l"(b), "l"(c));
    return d;
}
__device__ __forceinline__ ull pack2(float x) {
    ull d;
    asm("mov.b64 %0, {%1, %1};" : "=l"(d) : "f"(x));
    return d;
}
__device__ __forceinline__ float2 unpack2(ull v) {
    float2 r;
    asm("mov.b64 {%0, %1}, %2;" : "=f"(r.x), "=f"(r.y) : "l"(v));
    return r;
}
__device__ __forceinline__ void mma_bf16(float* d, const uint32_t* a,
                                         uint32_t b0, uint32_t b1) {
    asm volatile(
        "mma.sync.aligned.m16n8k16.row.col.f32.bf16.bf16.f32 "
        "{%0,%1,%2,%3}, {%4,%5,%6,%7}, {%8,%9}, {%0,%1,%2,%3};"
        : "+f"(d[0]), "+f"(d[1]), "+f"(d[2]), "+f"(d[3])
        : "r"(a[0]), "r"(a[1]), "r"(a[2]), "r"(a[3]), "r"(b0), "r"(b1));
}
__device__ __forceinline__ void red2(float* p, float x, float y) {
    asm volatile("red.global.add.v2.f32 [%0], {%1, %2};"
                 :: "l"(p), "f"(x), "f"(y) : "memory");
}

// -------------------- scratch (device globals) --------------------
__device__ float g_h[(size_t)N_NODES * DOUT];
__device__ float g_ecomb[B_GRAPH * DOUT];
__device__ float g_ncomb[B_GRAPH * DOUT];
// W1 fragment buffer: [ks=8][n0=8][lane=32] uint4 {bh0,bh1,bl0,bl1}
__device__ __align__(16) uint4 gW1frag[8 * 8 * 32];
// W2 fragment buffer: [ks2=4][nb=4][lane=32] uint4
__device__ __align__(16) uint4 gW2frag[4 * 4 * 32];

__device__ __forceinline__ uint32_t bfpack(float a, float b) {
    __nv_bfloat162 h = __floats2bfloat162_rn(a, b);
    return *(uint32_t*)&h;
}

// -------------------- zero + weight-fragment prep --------------------
__global__ void zero_kernel(const float* __restrict__ W1,
                            const float* __restrict__ W2) {
    if (blockIdx.x == 6250) {
        // W1frag: for (ks,n0,l): n = n0*8 + (l>>2), k0 = ks*16 + 2*(l&3)
        for (int idx = threadIdx.x; idx < 2048; idx += 256) {
            const int l = idx & 31, n0 = (idx >> 5) & 7, ks = idx >> 8;
            const int n = n0 * 8 + (l >> 2);
            const int k0 = ks * 16 + 2 * (l & 3);
            float v[4];
            v[0] = W1[k0 * 64 + n];       v[1] = W1[(k0 + 1) * 64 + n];
            v[2] = W1[(k0 + 8) * 64 + n]; v[3] = W1[(k0 + 9) * 64 + n];
            float h[4], lo[4];
#pragma unroll
            for (int i = 0; i < 4; i++) {
                h[i] = __bfloat162float(__float2bfloat16(v[i]));
                lo[i] = v[i] - h[i];
            }
            uint4 f;
            f.x = bfpack(h[0], h[1]);  f.y = bfpack(h[2], h[3]);
            f.z = bfpack(lo[0], lo[1]); f.w = bfpack(lo[2], lo[3]);
            gW1frag[idx] = f;
        }
        // W2frag
        for (int idx = threadIdx.x; idx < 512; idx += 256) {
            const int l = idx & 31, nb = (idx >> 5) & 3, ks2 = idx >> 7;
            const int n = nb * 8 + (l >> 2);
            const int k0 = ks2 * 16 + 2 * (l & 3);
            float v[4];
            v[0] = W2[k0 * 32 + n];       v[1] = W2[(k0 + 1) * 32 + n];
            v[2] = W2[(k0 + 8) * 32 + n]; v[3] = W2[(k0 + 9) * 32 + n];
            float h[4], lo[4];
#pragma unroll
            for (int i = 0; i < 4; i++) {
                h[i] = __bfloat162float(__float2bfloat16(v[i]));
                lo[i] = v[i] - h[i];
            }
            uint4 f;
            f.x = bfpack(h[0], h[1]);  f.y = bfpack(h[2], h[3]);
            f.z = bfpack(lo[0], lo[1]); f.w = bfpack(lo[2], lo[3]);
            gW2frag[idx] = f;
        }
        return;
    }
    size_t i = (size_t)blockIdx.x * blockDim.x + threadIdx.x;
    if (i < (size_t)N_NODES * DOUT) g_h[i] = 0.f;
    if (i < B_GRAPH * DOUT) { g_ecomb[i] = 0.f; g_ncomb[i] = 0.f; }
}

// float8 -> bf16 hi/lo (exact residual split)
__device__ __forceinline__ void cvt8(float4 a, float4 b, uint4& hi, uint4& lo) {
    __nv_bfloat162 h0 = __floats2bfloat162_rn(a.x, a.y);
    __nv_bfloat162 h1 = __floats2bfloat162_rn(a.z, a.w);
    __nv_bfloat162 h2 = __floats2bfloat162_rn(b.x, b.y);
    __nv_bfloat162 h3 = __floats2bfloat162_rn(b.z, b.w);
    float2 f0 = __bfloat1622float2(h0), f1 = __bfloat1622float2(h1);
    float2 f2 = __bfloat1622float2(h2), f3 = __bfloat1622float2(h3);
    __nv_bfloat162 l0 = __floats2bfloat162_rn(a.x - f0.x, a.y - f0.y);
    __nv_bfloat162 l1 = __floats2bfloat162_rn(a.z - f1.x, a.w - f1.y);
    __nv_bfloat162 l2 = __floats2bfloat162_rn(b.x - f2.x, b.y - f2.y);
    __nv_bfloat162 l3 = __floats2bfloat162_rn(b.z - f3.x, b.w - f3.y);
    hi.x = *(uint32_t*)&h0; hi.y = *(uint32_t*)&h1; hi.z = *(uint32_t*)&h2; hi.w = *(uint32_t*)&h3;
    lo.x = *(uint32_t*)&l0; lo.y = *(uint32_t*)&l1; lo.z = *(uint32_t*)&l2; lo.w = *(uint32_t*)&l3;
}

// ---------------- edge kernel smem layout (bytes) ----------------
// X half-K buffer: 128 rows x 72 bf16 (144B) = 18432 each (hi, lo)
#define SM_XHI   0
#define SM_XLO   18432
#define SM_W1F   36864    // 2048 uint4 = 32768
#define SM_W2F   36864    // alias (512 uint4 = 8192), after GEMM1 done
#define SM_B1    69632    // 64 f
#define SM_B2    69888    // 32 f
#define SM_ES    70016    // 256 f = 1024
#define SM_TOTAL 71040

// GEMM1 one K-pass (4 ks-steps over the 64-col half buffer)
__device__ __forceinline__ void gemm1_pass(
    const __nv_bfloat16* __restrict__ Xhi, const __nv_bfloat16* __restrict__ Xlo,
    const uint4* __restrict__ W1F, int r0, int t, int lid, int pass,
    float acc[8][4])
{
#pragma unroll
    for (int ksl = 0; ksl < 4; ksl++) {
        const int c0 = ksl * 16 + 2 * t;
        const __nv_bfloat16* xh = Xhi + r0 * 72 + c0;
        const __nv_bfloat16* xl = Xlo + r0 * 72 + c0;
        uint32_t ah[4], al[4];
        ah[0] = *(const uint32_t*)(xh);
        ah[1] = *(const uint32_t*)(xh + 8 * 72);
        ah[2] = *(const uint32_t*)(xh + 8);
        ah[3] = *(const uint32_t*)(xh + 8 * 72 + 8);
        al[0] = *(const uint32_t*)(xl);
        al[1] = *(const uint32_t*)(xl + 8 * 72);
        al[2] = *(const uint32_t*)(xl + 8);
        al[3] = *(const uint32_t*)(xl + 8 * 72 + 8);
        const uint4* wf = W1F + ((pass * 4 + ksl) * 8) * 32 + lid;
#pragma unroll
        for (int n0 = 0; n0 < 8; n0++) {
            uint4 w = wf[n0 * 32];
            mma_bf16(acc[n0], ah, w.x, w.y);
            mma_bf16(acc[n0], ah, w.z, w.w);
            mma_bf16(acc[n0], al, w.x, w.y);
        }
    }
}

__global__ void __launch_bounds__(256, 3) edge_kernel(
    const float* __restrict__ edge_feat, const float* __restrict__ node_feat,
    const float* __restrict__ g_repr, const int* __restrict__ src,
    const int* __restrict__ dst, const int* __restrict__ e2g,
    const float* __restrict__ b1, const float* __restrict__ b2,
    float* __restrict__ e_out)
{
    extern __shared__ unsigned char smem[];
    const int tid = threadIdx.x;
    const int wid = tid >> 5, lid = tid & 31;

    __nv_bfloat16* Xhi = (__nv_bfloat16*)(smem + SM_XHI);
    __nv_bfloat16* Xlo = (__nv_bfloat16*)(smem + SM_XLO);
    const uint4* W1F = (const uint4*)(smem + SM_W1F);
    const uint4* W2F = (const uint4*)(smem + SM_W2F);
    float* b1s = (float*)(smem + SM_B1);
    float* b2s = (float*)(smem + SM_B2);
    float* Es  = (float*)(smem + SM_ES);

    // ---- stage W1 fragments, biases, Es ----
    {
        uint4* d1 = (uint4*)(smem + SM_W1F);
        for (int i = tid; i < 2048; i += 256) d1[i] = gW1frag[i];
        if (tid < HID)  b1s[tid] = b1[tid];
        if (tid < DOUT) b2s[tid] = b2[tid];
        Es[tid] = 0.f;
    }

    const size_t e0 = (size_t)blockIdx.x * 128;
    const int r = tid >> 1, half = tid & 1;
    const size_t eg = e0 + r;
    const int si = src[eg], di = dst[eg], gi = e2g[eg];

    // ---- gather pass 1: k 0..63 = edge_feat || node_feat[src] ----
    {
        const float4* p = (const float4*)(half ? node_feat + (size_t)si * 32
                                               : edge_feat + eg * 32);
        __nv_bfloat16* xh = Xhi + r * 72 + half * 32;
        __nv_bfloat16* xl = Xlo + r * 72 + half * 32;
#pragma unroll
        for (int q = 0; q < 4; q++) {
            uint4 hi, lo;
            cvt8(p[2 * q], p[2 * q + 1], hi, lo);
            *(uint4*)(xh + q * 8) = hi;
            *(uint4*)(xl + q * 8) = lo;
        }
    }
    __syncthreads();

    const int g = lid >> 2, t = lid & 3;
    const int r0 = 16 * wid + g;
    float acc[8][4];
#pragma unroll
    for (int n0 = 0; n0 < 8; n0++)
#pragma unroll
        for (int j = 0; j < 4; j++) acc[n0][j] = 0.f;

    gemm1_pass(Xhi, Xlo, W1F, r0, t, lid, 0, acc);
    __syncthreads();

    // ---- gather pass 2: k 64..127 = node_feat[dst] || g_repr ----
    {
        const float4* p = (const float4*)(half ? g_repr + (size_t)gi * 32
                                               : node_feat + (size_t)di * 32);
        __nv_bfloat16* xh = Xhi + r * 72 + half * 32;
        __nv_bfloat16* xl = Xlo + r * 72 + half * 32;
#pragma unroll
        for (int q = 0; q < 4; q++) {
            uint4 hi, lo;
            cvt8(p[2 * q], p[2 * q + 1], hi, lo);
            *(uint4*)(xh + q * 8) = hi;
            *(uint4*)(xl + q * 8) = lo;
        }
    }
    __syncthreads();

    gemm1_pass(Xhi, Xlo, W1F, r0, t, lid, 1, acc);

    // ---- bias + relu + register split -> A fragments for GEMM2 ----
    uint32_t Ahi[4][4], Alo[4][4];
#pragma unroll
    for (int n0 = 0; n0 < 8; n0++) {
        float2 bb = *(const float2*)(b1s + n0 * 8 + 2 * t);
        float v0 = fmaxf(acc[n0][0] + bb.x, 0.f);
        float v1 = fmaxf(acc[n0][1] + bb.y, 0.f);
        float v2 = fmaxf(acc[n0][2] + bb.x, 0.f);
        float v3 = fmaxf(acc[n0][3] + bb.y, 0.f);
        __nv_bfloat162 hA = __floats2bfloat162_rn(v0, v1);
        __nv_bfloat162 hB = __floats2bfloat162_rn(v2, v3);
        float2 fA = __bfloat1622float2(hA), fB = __bfloat1622float2(hB);
        __nv_bfloat162 lA = __floats2bfloat162_rn(v0 - fA.x, v1 - fA.y);
        __nv_bfloat162 lB = __floats2bfloat162_rn(v2 - fB.x, v3 - fB.y);
        const int ks2 = n0 >> 1, ib = (n0 & 1) * 2;
        Ahi[ks2][ib + 0] = *(uint32_t*)&hA;
        Ahi[ks2][ib + 1] = *(uint32_t*)&hB;
        Alo[ks2][ib + 0] = *(uint32_t*)&lA;
        Alo[ks2][ib + 1] = *(uint32_t*)&lB;
    }
    __syncthreads();   // all GEMM1 reads of W1F complete

    // ---- stage W2 fragments into (dead) W1F region ----
    {
        uint4* d2 = (uint4*)(smem + SM_W2F);
        for (int i = tid; i < 512; i += 256) d2[i] = gW2frag[i];
    }
    __syncthreads();

    // ---- GEMM2: K=64, 3-term, H in registers ----
    float d2[4][4];
#pragma unroll
    for (int nb = 0; nb < 4; nb++)
#pragma unroll
        for (int j = 0; j < 4; j++) d2[nb][j] = 0.f;

#pragma unroll
    for (int ks2 = 0; ks2 < 4; ks2++) {
        const uint4* wf = W2F + (ks2 * 4) * 32 + lid;
#pragma unroll
        for (int nb = 0; nb < 4; nb++) {
            uint4 w = wf[nb * 32];
            mma_bf16(d2[nb], Ahi[ks2], w.x, w.y);
            mma_bf16(d2[nb], Ahi[ks2], w.z, w.w);
            mma_bf16(d2[nb], Alo[ks2], w.x, w.y);
        }
    }

    // ---- epilogue: rows r0 and r0+8 ----
    {
        const size_t eA = e0 + r0, eB = eA + 8;
        const int dA = dst[eA], dB = dst[eB];
        const int gA = e2g[eA], gB = e2g[eB];
        const int gFirst = e2g[e0 + 16 * wid];
        const int gLast  = e2g[e0 + 16 * wid + 15];
        float* hA = g_h + (size_t)dA * 32;
        float* hB = g_h + (size_t)dB * 32;
        float* oA = e_out + eA * 32;
        float* oB = e_out + eB * 32;
        float a0[4], a1[4], c0v[4], c1[4];
#pragma unroll
        for (int nb = 0; nb < 4; nb++) {
            const int col = nb * 8 + 2 * t;
            float2 bb = *(const float2*)(b2s + col);
            a0[nb] = d2[nb][0] + bb.x;  a1[nb] = d2[nb][1] + bb.y;
            c0v[nb] = d2[nb][2] + bb.x; c1[nb] = d2[nb][3] + bb.y;
            *(float2*)(oA + col) = make_float2(a0[nb], a1[nb]);
            *(float2*)(oB + col) = make_float2(c0v[nb], c1[nb]);
            red2(hA + col, a0[nb], a1[nb]);
            red2(hB + col, c0v[nb], c1[nb]);
        }
        if (gFirst == gLast) {
            // fast path: whole warp-row-range is one graph -> shuffle reduce over g
#pragma unroll
            for (int nb = 0; nb < 4; nb++) {
                float s0 = a0[nb] + c0v[nb];
                float s1 = a1[nb] + c1[nb];
#pragma unroll
                for (int m = 4; m <= 16; m <<= 1) {
                    s0 += __shfl_xor_sync(0xFFFFFFFFu, s0, m);
                    s1 += __shfl_xor_sync(0xFFFFFFFFu, s1, m);
                }
                if (g == 0) {
                    const int col = nb * 8 + 2 * t;
                    atomicAdd(&Es[gFirst * 32 + col], s0);
                    atomicAdd(&Es[gFirst * 32 + col + 1], s1);
                }
            }
        } else {
#pragma unroll
            for (int nb = 0; nb < 4; nb++) {
                const int col = nb * 8 + 2 * t;
                atomicAdd(&Es[gA * 32 + col], a0[nb]);
                atomicAdd(&Es[gA * 32 + col + 1], a1[nb]);
                atomicAdd(&Es[gB * 32 + col], c0v[nb]);
                atomicAdd(&Es[gB * 32 + col + 1], c1[nb]);
            }
        }
    }
    __syncthreads();
    atomicAdd(&g_ecomb[tid], Es[tid]);
}

// ---------------------------------------------------------------------------
// Node kernel: tile = 128 nodes, X[128][96] -> MLP 96->64->32, f32x2
// ---------------------------------------------------------------------------
__global__ void __launch_bounds__(256) node_kernel(
    const float* __restrict__ node_feat, const float* __restrict__ g_repr,
    const int* __restrict__ n2g,
    const float* __restrict__ W1, const float* __restrict__ b1,
    const float* __restrict__ W2, const float* __restrict__ b2,
    float* __restrict__ n_out)
{
    extern __shared__ float sm[];
    float* W1s = sm;              // 6144
    float* W2s = sm + 6144;       // 2048
    float* b1s = sm + 8192;       // 64
    float* b2s = sm + 8256;       // 32
    float* Ns  = sm + 8288;       // 256
    float* Xs  = sm + 8544;       // 128 x 100
    float* Hs  = Xs;              // alias, stride 68

    const int tid = threadIdx.x;
    {
        const float4* wg = (const float4*)W1;  float4* ws = (float4*)W1s;
        for (int i = tid; i < 1536; i += 256) ws[i] = wg[i];
        const float4* w2g = (const float4*)W2; float4* w2s = (float4*)W2s;
        for (int i = tid; i < 512; i += 256) w2s[i] = w2g[i];
        if (tid < HID)  b1s[tid] = b1[tid];
        if (tid < DOUT) b2s[tid] = b2[tid];
        Ns[tid] = 0.f;
    }

    const int n0 = blockIdx.x * 128;

    for (int s = tid; s < 3072; s += 256) {
        const int r = s / 24, q = s % 24;
        const int node = n0 + r;
        float4 v = make_float4(0.f, 0.f, 0.f, 0.f);
        if (node < N_NODES) {
            if (q < 8)       v = ((const float4*)(node_feat + (size_t)node * 32))[q];
            else if (q < 16) v = ((const float4*)(g_h + (size_t)node * 32))[q - 8];
            else {
                const int gi = n2g[node];
                v = ((const float4*)(g_repr + (size_t)gi * 32))[q - 16];
            }
        }
        *(float4*)(Xs + r * 100 + q * 4) = v;
    }
    __syncthreads();

    const int tx = tid & 7, ty = tid >> 3;
    ull acc1[4][4];
    {
        const ulonglong2* bp = (const ulonglong2*)(b1s + tx * 8);
        ulonglong2 ba = bp[0], bb = bp[1];
#pragma unroll
        for (int i = 0; i < 4; i++) {
            acc1[i][0] = ba.x; acc1[i][1] = ba.y;
            acc1[i][2] = bb.x; acc1[i][3] = bb.y;
        }
    }
    const float* x0 = Xs + ty * 100;
#pragma unroll 4
    for (int k = 0; k < 96; k++) {
        const ulonglong2* wp = (const ulonglong2*)(W1s + k * 64 + tx * 8);
        ulonglong2 wa = wp[0], wb = wp[1];
        ull w[4] = { wa.x, wa.y, wb.x, wb.y };
        ull xp[4];
        xp[0] = pack2(x0[k]);
        xp[1] = pack2(x0[3200 + k]);
        xp[2] = pack2(x0[6400 + k]);
        xp[3] = pack2(x0[9600 + k]);
#pragma unroll
        for (int i = 0; i < 4; i++)
#pragma unroll
            for (int j = 0; j < 4; j++)
                acc1[i][j] = fma2(xp[i], w[j], acc1[i][j]);
    }
    __syncthreads();

#pragma unroll
    for (int i = 0; i < 4; i++) {
        float* hr = Hs + (ty + 32 * i) * 68 + tx * 8;
#pragma unroll
        for (int j = 0; j < 4; j++) {
            float2 v = unpack2(acc1[i][j]);
            hr[2 * j]     = fmaxf(v.x, 0.f);
            hr[2 * j + 1] = fmaxf(v.y, 0.f);
        }
    }
    __syncthreads();

    const int tx2 = tid & 3, ty2 = tid >> 2;
    ull acc2[2][4];
    {
        const ulonglong2* bp = (const ulonglong2*)(b2s + tx2 * 8);
        ulonglong2 ba = bp[0], bb = bp[1];
        acc2[0][0] = acc2[1][0] = ba.x; acc2[0][1] = acc2[1][1] = ba.y;
        acc2[0][2] = acc2[1][2] = bb.x; acc2[0][3] = acc2[1][3] = bb.y;
    }
    const float* h0 = Hs + ty2 * 68;
#pragma unroll 4
    for (int k = 0; k < 64; k++) {
        const ulonglong2* wp = (const ulonglong2*)(W2s + k * 32 + tx2 * 8);
        ulonglong2 wa = wp[0], wb = wp[1];
        ull w[4] = { wa.x, wa.y, wb.x, wb.y };
        ull xa = pack2(h0[k]);
        ull xb = pack2(h0[64 * 68 + k]);
#pragma unroll
        for (int j = 0; j < 4; j++) {
            acc2[0][j] = fma2(xa, w[j], acc2[0][j]);
            acc2[1][j] = fma2(xb, w[j], acc2[1][j]);
        }
    }

#pragma unroll
    for (int i = 0; i < 2; i++) {
        const int r = ty2 + 64 * i;
        const int node = n0 + r;
        if (node < N_NODES) {
            float o[8];
#pragma unroll
            for (int j = 0; j < 4; j++) {
                float2 v = unpack2(acc2[i][j]);
                o[2 * j] = v.x; o[2 * j + 1] = v.y;
            }
            *(float4*)(n_out + (size_t)node * 32 + tx2 * 8)     = make_float4(o[0], o[1], o[2], o[3]);
            *(float4*)(n_out + (size_t)node * 32 + tx2 * 8 + 4) = make_float4(o[4], o[5], o[6], o[7]);
            const int gi = n2g[node];
            float* np = Ns + gi * 32 + tx2 * 8;
#pragma unroll
            for (int q = 0; q < 8; q++) atomicAdd(np + q, o[q]);
        }
    }
    __syncthreads();
    atomicAdd(&g_ncomb[tid], Ns[tid]);
}

// ---------------------------------------------------------------------------
// Global kernel
// ---------------------------------------------------------------------------
__global__ void __launch_bounds__(256) global_kernel(
    const float* __restrict__ g_repr,
    const float* __restrict__ Wu1, const float* __restrict__ bu1,
    const float* __restrict__ Wu2, const float* __restrict__ bu2,
    float* __restrict__ g_out)
{
    __shared__ float U[B_GRAPH * 96];
    __shared__ float W1u[96 * HID];
    __shared__ float W2u[HID * DOUT];
    __shared__ float Hg[B_GRAPH * HID];
    const int tid = threadIdx.x;

    for (int i = tid; i < B_GRAPH * 96; i += 256) {
        const int b = i / 96, c = i % 96;
        float v;
        if (c < 32)      v = g_ncomb[b * 32 + c];
        else if (c < 64) v = g_ecomb[b * 32 + (c - 32)];
        else             v = g_repr[b * 32 + (c - 64)];
        U[i] = v;
    }
    {
        const float4* wg = (const float4*)Wu1; float4* ws = (float4*)W1u;
        for (int i = tid; i < 1536; i += 256) ws[i] = wg[i];
        const float4* w2g = (const float4*)Wu2; float4* w2s = (float4*)W2u;
        for (int i = tid; i < 512; i += 256) w2s[i] = w2g[i];
    }
    __syncthreads();

    for (int idx = tid; idx < B_GRAPH * HID; idx += 256) {
        const int b = idx >> 6, j = idx & 63;
        float s = bu1[j];
#pragma unroll 8
        for (int k = 0; k < 96; k++) s += U[b * 96 + k] * W1u[k * 64 + j];
        Hg[idx] = fmaxf(s, 0.f);
    }
    __syncthreads();
    for (int idx = tid; idx < B_GRAPH * DOUT; idx += 256) {
        const int b = idx >> 5, c = idx & 31;
        float s = bu2[c];
#pragma unroll 8
        for (int k = 0; k < 64; k++) s += Hg[b * 64 + k] * W2u[k * 32 + c];
        g_out[idx] = s;
    }
}

extern "C" void kernel_launch(void* const* d_in, const int* in_sizes, int n_in,
                              void* d_out, int out_size)
{
    const float* edge_feat = (const float*)d_in[0];
    const float* node_feat = (const float*)d_in[1];
    const float* g_repr    = (const float*)d_in[2];
    const int*   src       = (const int*)d_in[3];
    const int*   dst       = (const int*)d_in[4];
    const int*   n2g       = (const int*)d_in[5];
    const int*   e2g       = (const int*)d_in[6];
    const float* W_e1 = (const float*)d_in[7];
    const float* b_e1 = (const float*)d_in[8];
    const float* W_e2 = (const float*)d_in[9];
    const float* b_e2 = (const float*)d_in[10];
    const float* W_n1 = (const float*)d_in[11];
    const float* b_n1 = (const float*)d_in[12];
    const float* W_n2 = (const float*)d_in[13];
    const float* b_n2 = (const float*)d_in[14];
    const float* W_u1 = (const float*)d_in[15];
    const float* b_u1 = (const float*)d_in[16];
    const float* W_u2 = (const float*)d_in[17];
    const float* b_u2 = (const float*)d_in[18];

    float* out = (float*)d_out;
    float* e_out = out;                                      // [E, 32]
    float* n_out = out + (size_t)N_EDGES * DOUT;             // [N, 32]
    float* g_out = out + (size_t)(N_EDGES + N_NODES) * DOUT; // [B, 32]

    const int node_smem = 21344 * 4;
    cudaFuncSetAttribute(edge_kernel, cudaFuncAttributeMaxDynamicSharedMemorySize, SM_TOTAL);
    cudaFuncSetAttribute(node_kernel, cudaFuncAttributeMaxDynamicSharedMemorySize, node_smem);

    zero_kernel<<<6251, 256>>>(W_e1, W_e2);
    edge_kernel<<<N_EDGES / 128, 256, SM_TOTAL>>>(
        edge_feat, node_feat, g_repr, src, dst, e2g,
        b_e1, b_e2, e_out);
    node_kernel<<<(N_NODES + 127) / 128, 256, node_smem>>>(
        node_feat, g_repr, n2g, W_n1, b_n1, W_n2, b_n2, n_out);
    global_kernel<<<1, 256>>>(g_repr, W_u1, b_u1, W_u2, b_u2, g_out);
}

// round 8
// speedup vs baseline: 3.6229x; 1.1570x over previous
#include <cuda_runtime.h>
#include <cuda_bf16.h>
#include <cstdint>

#define N_NODES 50000
#define N_EDGES 800000
#define B_GRAPH 8
#define HID 64
#define DOUT 32

typedef unsigned long long ull;

__device__ __forceinline__ void mma_bf16(float* d, const uint32_t* a,
                                         uint32_t b0, uint32_t b1) {
    asm volatile(
        "mma.sync.aligned.m16n8k16.row.col.f32.bf16.bf16.f32 "
        "{%0,%1,%2,%3}, {%4,%5,%6,%7}, {%8,%9}, {%0,%1,%2,%3};"
        : "+f"(d[0]), "+f"(d[1]), "+f"(d[2]), "+f"(d[3])
        : "r"(a[0]), "r"(a[1]), "r"(a[2]), "r"(a[3]), "r"(b0), "r"(b1));
}
__device__ __forceinline__ void red2(float* p, float x, float y) {
    asm volatile("red.global.add.v2.f32 [%0], {%1, %2};"
                 :: "l"(p), "f"(x), "f"(y) : "memory");
}

// -------------------- scratch (device globals) --------------------
__device__ float g_h[(size_t)N_NODES * DOUT];
__device__ float g_ecomb[B_GRAPH * DOUT];
__device__ float g_ncomb[B_GRAPH * DOUT];
__device__ unsigned int g_ticket;
// edge W1 fragments: [ks=8][n0=8][lane=32] uint4 {bh0,bh1,bl0,bl1}
__device__ __align__(16) uint4 gW1frag[8 * 8 * 32];
// edge W2 fragments: [ks2=4][nb=4][lane=32]
__device__ __align__(16) uint4 gW2frag[4 * 4 * 32];
// node W1 fragments: [ks=6][n0=8][lane=32]
__device__ __align__(16) uint4 gWn1frag[6 * 8 * 32];
// node W2 fragments: [ks2=4][nb=4][lane=32]
__device__ __align__(16) uint4 gWn2frag[4 * 4 * 32];

__device__ __forceinline__ uint32_t bfpack(float a, float b) {
    __nv_bfloat162 h = __floats2bfloat162_rn(a, b);
    return *(uint32_t*)&h;
}

__device__ __forceinline__ uint4 make_frag(float v0, float v1, float v2, float v3) {
    float h0 = __bfloat162float(__float2bfloat16(v0));
    float h1 = __bfloat162float(__float2bfloat16(v1));
    float h2 = __bfloat162float(__float2bfloat16(v2));
    float h3 = __bfloat162float(__float2bfloat16(v3));
    uint4 f;
    f.x = bfpack(h0, h1); f.y = bfpack(h2, h3);
    f.z = bfpack(v0 - h0, v1 - h1); f.w = bfpack(v2 - h2, v3 - h3);
    return f;
}

// -------------------- zero + weight-fragment prep --------------------
__global__ void zero_kernel(const float* __restrict__ W1,
                            const float* __restrict__ W2,
                            const float* __restrict__ Wn1,
                            const float* __restrict__ Wn2) {
    if (blockIdx.x == 6250) {
        if (threadIdx.x == 0) g_ticket = 0;
        // edge W1: [128][64]
        for (int idx = threadIdx.x; idx < 2048; idx += 256) {
            const int l = idx & 31, n0 = (idx >> 5) & 7, ks = idx >> 8;
            const int n = n0 * 8 + (l >> 2);
            const int k0 = ks * 16 + 2 * (l & 3);
            gW1frag[idx] = make_frag(W1[k0 * 64 + n], W1[(k0 + 1) * 64 + n],
                                     W1[(k0 + 8) * 64 + n], W1[(k0 + 9) * 64 + n]);
        }
        // edge W2: [64][32]
        for (int idx = threadIdx.x; idx < 512; idx += 256) {
            const int l = idx & 31, nb = (idx >> 5) & 3, ks2 = idx >> 7;
            const int n = nb * 8 + (l >> 2);
            const int k0 = ks2 * 16 + 2 * (l & 3);
            gW2frag[idx] = make_frag(W2[k0 * 32 + n], W2[(k0 + 1) * 32 + n],
                                     W2[(k0 + 8) * 32 + n], W2[(k0 + 9) * 32 + n]);
        }
        // node W1: [96][64]
        for (int idx = threadIdx.x; idx < 1536; idx += 256) {
            const int l = idx & 31, n0 = (idx >> 5) & 7, ks = idx >> 8;
            const int n = n0 * 8 + (l >> 2);
            const int k0 = ks * 16 + 2 * (l & 3);
            gWn1frag[idx] = make_frag(Wn1[k0 * 64 + n], Wn1[(k0 + 1) * 64 + n],
                                      Wn1[(k0 + 8) * 64 + n], Wn1[(k0 + 9) * 64 + n]);
        }
        // node W2: [64][32]
        for (int idx = threadIdx.x; idx < 512; idx += 256) {
            const int l = idx & 31, nb = (idx >> 5) & 3, ks2 = idx >> 7;
            const int n = nb * 8 + (l >> 2);
            const int k0 = ks2 * 16 + 2 * (l & 3);
            gWn2frag[idx] = make_frag(Wn2[k0 * 32 + n], Wn2[(k0 + 1) * 32 + n],
                                      Wn2[(k0 + 8) * 32 + n], Wn2[(k0 + 9) * 32 + n]);
        }
        return;
    }
    size_t i = (size_t)blockIdx.x * blockDim.x + threadIdx.x;
    if (i < (size_t)N_NODES * DOUT) g_h[i] = 0.f;
    if (i < B_GRAPH * DOUT) { g_ecomb[i] = 0.f; g_ncomb[i] = 0.f; }
}

// float8 -> bf16 hi/lo (exact residual split)
__device__ __forceinline__ void cvt8(float4 a, float4 b, uint4& hi, uint4& lo) {
    __nv_bfloat162 h0 = __floats2bfloat162_rn(a.x, a.y);
    __nv_bfloat162 h1 = __floats2bfloat162_rn(a.z, a.w);
    __nv_bfloat162 h2 = __floats2bfloat162_rn(b.x, b.y);
    __nv_bfloat162 h3 = __floats2bfloat162_rn(b.z, b.w);
    float2 f0 = __bfloat1622float2(h0), f1 = __bfloat1622float2(h1);
    float2 f2 = __bfloat1622float2(h2), f3 = __bfloat1622float2(h3);
    __nv_bfloat162 l0 = __floats2bfloat162_rn(a.x - f0.x, a.y - f0.y);
    __nv_bfloat162 l1 = __floats2bfloat162_rn(a.z - f1.x, a.w - f1.y);
    __nv_bfloat162 l2 = __floats2bfloat162_rn(b.x - f2.x, b.y - f2.y);
    __nv_bfloat162 l3 = __floats2bfloat162_rn(b.z - f3.x, b.w - f3.y);
    hi.x = *(uint32_t*)&h0; hi.y = *(uint32_t*)&h1; hi.z = *(uint32_t*)&h2; hi.w = *(uint32_t*)&h3;
    lo.x = *(uint32_t*)&l0; lo.y = *(uint32_t*)&l1; lo.z = *(uint32_t*)&l2; lo.w = *(uint32_t*)&l3;
}

// split fp32 acc -> bf16 hi/lo A-fragment pair
__device__ __forceinline__ void split_frag(float v0, float v1, float v2, float v3,
                                           uint32_t& hA, uint32_t& hB,
                                           uint32_t& lA, uint32_t& lB) {
    __nv_bfloat162 a = __floats2bfloat162_rn(v0, v1);
    __nv_bfloat162 b = __floats2bfloat162_rn(v2, v3);
    float2 fa = __bfloat1622float2(a), fb = __bfloat1622float2(b);
    __nv_bfloat162 la = __floats2bfloat162_rn(v0 - fa.x, v1 - fa.y);
    __nv_bfloat162 lb = __floats2bfloat162_rn(v2 - fb.x, v3 - fb.y);
    hA = *(uint32_t*)&a; hB = *(uint32_t*)&b;
    lA = *(uint32_t*)&la; lB = *(uint32_t*)&lb;
}

// ================== EDGE KERNEL ==================
#define SM_XHI   0
#define SM_XLO   18432
#define SM_W1F   36864    // 2048 uint4 = 32768
#define SM_B1    69632
#define SM_B2    69888
#define SM_ES    70016
#define SM_TOTAL 71040

__device__ __forceinline__ void gemm1_pass(
    const __nv_bfloat16* __restrict__ Xhi, const __nv_bfloat16* __restrict__ Xlo,
    const uint4* __restrict__ W1F, int r0, int t, int lid, int pass,
    float acc[8][4])
{
#pragma unroll
    for (int ksl = 0; ksl < 4; ksl++) {
        const int c0 = ksl * 16 + 2 * t;
        const __nv_bfloat16* xh = Xhi + r0 * 72 + c0;
        const __nv_bfloat16* xl = Xlo + r0 * 72 + c0;
        uint32_t ah[4], al[4];
        ah[0] = *(const uint32_t*)(xh);
        ah[1] = *(const uint32_t*)(xh + 8 * 72);
        ah[2] = *(const uint32_t*)(xh + 8);
        ah[3] = *(const uint32_t*)(xh + 8 * 72 + 8);
        al[0] = *(const uint32_t*)(xl);
        al[1] = *(const uint32_t*)(xl + 8 * 72);
        al[2] = *(const uint32_t*)(xl + 8);
        al[3] = *(const uint32_t*)(xl + 8 * 72 + 8);
        const uint4* wf = W1F + ((pass * 4 + ksl) * 8) * 32 + lid;
#pragma unroll
        for (int n0 = 0; n0 < 8; n0++) {
            uint4 w = wf[n0 * 32];
            mma_bf16(acc[n0], ah, w.x, w.y);
            mma_bf16(acc[n0], ah, w.z, w.w);
            mma_bf16(acc[n0], al, w.x, w.y);
        }
    }
}

__global__ void __launch_bounds__(256, 3) edge_kernel(
    const float* __restrict__ edge_feat, const float* __restrict__ node_feat,
    const float* __restrict__ g_repr, const int* __restrict__ src,
    const int* __restrict__ dst, const int* __restrict__ e2g,
    const float* __restrict__ b1, const float* __restrict__ b2,
    float* __restrict__ e_out)
{
    extern __shared__ unsigned char smem[];
    const int tid = threadIdx.x;
    const int wid = tid >> 5, lid = tid & 31;

    __nv_bfloat16* Xhi = (__nv_bfloat16*)(smem + SM_XHI);
    __nv_bfloat16* Xlo = (__nv_bfloat16*)(smem + SM_XLO);
    const uint4* W1F = (const uint4*)(smem + SM_W1F);
    float* b1s = (float*)(smem + SM_B1);
    float* b2s = (float*)(smem + SM_B2);
    float* Es  = (float*)(smem + SM_ES);

    {
        uint4* d1 = (uint4*)(smem + SM_W1F);
        for (int i = tid; i < 2048; i += 256) d1[i] = gW1frag[i];
        if (tid < HID)  b1s[tid] = b1[tid];
        if (tid < DOUT) b2s[tid] = b2[tid];
        Es[tid] = 0.f;
    }

    const size_t e0 = (size_t)blockIdx.x * 128;
    const int r = tid >> 1, half = tid & 1;
    const size_t eg = e0 + r;
    const int si = src[eg], di = dst[eg], gi = e2g[eg];

    // gather pass 1: k 0..63 = edge_feat || node_feat[src]
    {
        const float4* p = (const float4*)(half ? node_feat + (size_t)si * 32
                                               : edge_feat + eg * 32);
        __nv_bfloat16* xh = Xhi + r * 72 + half * 32;
        __nv_bfloat16* xl = Xlo + r * 72 + half * 32;
#pragma unroll
        for (int q = 0; q < 4; q++) {
            uint4 hi, lo;
            cvt8(p[2 * q], p[2 * q + 1], hi, lo);
            *(uint4*)(xh + q * 8) = hi;
            *(uint4*)(xl + q * 8) = lo;
        }
    }
    __syncthreads();

    const int g = lid >> 2, t = lid & 3;
    const int r0 = 16 * wid + g;
    float acc[8][4];
#pragma unroll
    for (int n0 = 0; n0 < 8; n0++)
#pragma unroll
        for (int j = 0; j < 4; j++) acc[n0][j] = 0.f;

    gemm1_pass(Xhi, Xlo, W1F, r0, t, lid, 0, acc);
    __syncthreads();

    // gather pass 2: k 64..127 = node_feat[dst] || g_repr
    {
        const float4* p = (const float4*)(half ? g_repr + (size_t)gi * 32
                                               : node_feat + (size_t)di * 32);
        __nv_bfloat16* xh = Xhi + r * 72 + half * 32;
        __nv_bfloat16* xl = Xlo + r * 72 + half * 32;
#pragma unroll
        for (int q = 0; q < 4; q++) {
            uint4 hi, lo;
            cvt8(p[2 * q], p[2 * q + 1], hi, lo);
            *(uint4*)(xh + q * 8) = hi;
            *(uint4*)(xl + q * 8) = lo;
        }
    }
    __syncthreads();

    gemm1_pass(Xhi, Xlo, W1F, r0, t, lid, 1, acc);

    // bias + relu + register split -> A fragments
    uint32_t Ahi[4][4], Alo[4][4];
#pragma unroll
    for (int n0 = 0; n0 < 8; n0++) {
        float2 bb = *(const float2*)(b1s + n0 * 8 + 2 * t);
        const int ks2 = n0 >> 1, ib = (n0 & 1) * 2;
        split_frag(fmaxf(acc[n0][0] + bb.x, 0.f), fmaxf(acc[n0][1] + bb.y, 0.f),
                   fmaxf(acc[n0][2] + bb.x, 0.f), fmaxf(acc[n0][3] + bb.y, 0.f),
                   Ahi[ks2][ib], Ahi[ks2][ib + 1], Alo[ks2][ib], Alo[ks2][ib + 1]);
    }

    // GEMM2: K=64, weight fragments straight from L2 (no staging, no syncs)
    float d2[4][4];
#pragma unroll
    for (int nb = 0; nb < 4; nb++)
#pragma unroll
        for (int j = 0; j < 4; j++) d2[nb][j] = 0.f;

#pragma unroll
    for (int ks2 = 0; ks2 < 4; ks2++) {
        const uint4* wf = gW2frag + (ks2 * 4) * 32 + lid;
#pragma unroll
        for (int nb = 0; nb < 4; nb++) {
            uint4 w = wf[nb * 32];
            mma_bf16(d2[nb], Ahi[ks2], w.x, w.y);
            mma_bf16(d2[nb], Ahi[ks2], w.z, w.w);
            mma_bf16(d2[nb], Alo[ks2], w.x, w.y);
        }
    }

    // epilogue
    {
        const size_t eA = e0 + r0, eB = eA + 8;
        const int dA = dst[eA], dB = dst[eB];
        const int gA = e2g[eA], gB = e2g[eB];
        const int gFirst = e2g[e0 + 16 * wid];
        const int gLast  = e2g[e0 + 16 * wid + 15];
        float* hA = g_h + (size_t)dA * 32;
        float* hB = g_h + (size_t)dB * 32;
        float* oA = e_out + eA * 32;
        float* oB = e_out + eB * 32;
        float a0[4], a1[4], c0v[4], c1[4];
#pragma unroll
        for (int nb = 0; nb < 4; nb++) {
            const int col = nb * 8 + 2 * t;
            float2 bb = *(const float2*)(b2s + col);
            a0[nb] = d2[nb][0] + bb.x;  a1[nb] = d2[nb][1] + bb.y;
            c0v[nb] = d2[nb][2] + bb.x; c1[nb] = d2[nb][3] + bb.y;
            *(float2*)(oA + col) = make_float2(a0[nb], a1[nb]);
            *(float2*)(oB + col) = make_float2(c0v[nb], c1[nb]);
            red2(hA + col, a0[nb], a1[nb]);
            red2(hB + col, c0v[nb], c1[nb]);
        }
        if (gFirst == gLast) {
#pragma unroll
            for (int nb = 0; nb < 4; nb++) {
                float s0 = a0[nb] + c0v[nb];
                float s1 = a1[nb] + c1[nb];
#pragma unroll
                for (int m = 4; m <= 16; m <<= 1) {
                    s0 += __shfl_xor_sync(0xFFFFFFFFu, s0, m);
                    s1 += __shfl_xor_sync(0xFFFFFFFFu, s1, m);
                }
                if (g == 0) {
                    const int col = nb * 8 + 2 * t;
                    atomicAdd(&Es[gFirst * 32 + col], s0);
                    atomicAdd(&Es[gFirst * 32 + col + 1], s1);
                }
            }
        } else {
#pragma unroll
            for (int nb = 0; nb < 4; nb++) {
                const int col = nb * 8 + 2 * t;
                atomicAdd(&Es[gA * 32 + col], a0[nb]);
                atomicAdd(&Es[gA * 32 + col + 1], a1[nb]);
                atomicAdd(&Es[gB * 32 + col], c0v[nb]);
                atomicAdd(&Es[gB * 32 + col + 1], c1[nb]);
            }
        }
    }
    __syncthreads();
    atomicAdd(&g_ecomb[tid], Es[tid]);
}

// ================== NODE KERNEL (tensor) + global tail ==================
// X: 128 rows x stride 104 bf16 (208B) = 26624 each
#define NSM_XHI   0
#define NSM_XLO   26624
#define NSM_W1F   53248   // 1536 uint4 = 24576
#define NSM_B1    77824
#define NSM_B2    78080
#define NSM_NS    78208   // 1024
#define NSM_TOTAL 79232

__global__ void __launch_bounds__(256, 2) node_kernel(
    const float* __restrict__ node_feat, const float* __restrict__ g_repr,
    const int* __restrict__ n2g,
    const float* __restrict__ b1, const float* __restrict__ b2,
    const float* __restrict__ Wu1, const float* __restrict__ bu1,
    const float* __restrict__ Wu2, const float* __restrict__ bu2,
    float* __restrict__ n_out, float* __restrict__ g_out)
{
    extern __shared__ unsigned char smem[];
    const int tid = threadIdx.x;
    const int wid = tid >> 5, lid = tid & 31;

    __nv_bfloat16* Xhi = (__nv_bfloat16*)(smem + NSM_XHI);
    __nv_bfloat16* Xlo = (__nv_bfloat16*)(smem + NSM_XLO);
    const uint4* W1F = (const uint4*)(smem + NSM_W1F);
    float* b1s = (float*)(smem + NSM_B1);
    float* b2s = (float*)(smem + NSM_B2);
    float* Ns  = (float*)(smem + NSM_NS);

    {
        uint4* d1 = (uint4*)(smem + NSM_W1F);
        for (int i = tid; i < 1536; i += 256) d1[i] = gWn1frag[i];
        if (tid < HID)  b1s[tid] = b1[tid];
        if (tid < DOUT) b2s[tid] = b2[tid];
        Ns[tid] = 0.f;
    }

    const int n0base = blockIdx.x * 128;

    // gather: 2 threads per row, 48 cols each; X[r][0:96] = node_feat||g_h||g_repr
    {
        const int r = tid >> 1, half = tid & 1;
        const int node = n0base + r;
        __nv_bfloat16* xh = Xhi + r * 104 + half * 48;
        __nv_bfloat16* xl = Xlo + r * 104 + half * 48;
        if (node < N_NODES) {
            if (half == 0) {
                const float4* pn = (const float4*)(node_feat + (size_t)node * 32);
#pragma unroll
                for (int q = 0; q < 4; q++) {
                    uint4 hi, lo;
                    cvt8(pn[2 * q], pn[2 * q + 1], hi, lo);
                    *(uint4*)(xh + q * 8) = hi;
                    *(uint4*)(xl + q * 8) = lo;
                }
                const float4* ph = (const float4*)(g_h + (size_t)node * 32);
#pragma unroll
                for (int q = 0; q < 2; q++) {
                    uint4 hi, lo;
                    cvt8(ph[2 * q], ph[2 * q + 1], hi, lo);
                    *(uint4*)(xh + 32 + q * 8) = hi;
                    *(uint4*)(xl + 32 + q * 8) = lo;
                }
            } else {
                const float4* ph = (const float4*)(g_h + (size_t)node * 32) + 4;
#pragma unroll
                for (int q = 0; q < 2; q++) {
                    uint4 hi, lo;
                    cvt8(ph[2 * q], ph[2 * q + 1], hi, lo);
                    *(uint4*)(xh + q * 8) = hi;
                    *(uint4*)(xl + q * 8) = lo;
                }
                const int gi = n2g[node];
                const float4* pg = (const float4*)(g_repr + (size_t)gi * 32);
#pragma unroll
                for (int q = 0; q < 4; q++) {
                    uint4 hi, lo;
                    cvt8(pg[2 * q], pg[2 * q + 1], hi, lo);
                    *(uint4*)(xh + 16 + q * 8) = hi;
                    *(uint4*)(xl + 16 + q * 8) = lo;
                }
            }
        } else {
            const uint4 z = make_uint4(0, 0, 0, 0);
#pragma unroll
            for (int q = 0; q < 6; q++) {
                *(uint4*)(xh + q * 8) = z;
                *(uint4*)(xl + q * 8) = z;
            }
        }
    }
    __syncthreads();

    // GEMM1: K=96, 6 ks steps, 3-term
    const int g = lid >> 2, t = lid & 3;
    const int r0 = 16 * wid + g;
    float acc[8][4];
#pragma unroll
    for (int n0 = 0; n0 < 8; n0++)
#pragma unroll
        for (int j = 0; j < 4; j++) acc[n0][j] = 0.f;

#pragma unroll
    for (int ksl = 0; ksl < 6; ksl++) {
        const int c0 = ksl * 16 + 2 * t;
        const __nv_bfloat16* xh = Xhi + r0 * 104 + c0;
        const __nv_bfloat16* xl = Xlo + r0 * 104 + c0;
        uint32_t ah[4], al[4];
        ah[0] = *(const uint32_t*)(xh);
        ah[1] = *(const uint32_t*)(xh + 8 * 104);
        ah[2] = *(const uint32_t*)(xh + 8);
        ah[3] = *(const uint32_t*)(xh + 8 * 104 + 8);
        al[0] = *(const uint32_t*)(xl);
        al[1] = *(const uint32_t*)(xl + 8 * 104);
        al[2] = *(const uint32_t*)(xl + 8);
        al[3] = *(const uint32_t*)(xl + 8 * 104 + 8);
        const uint4* wf = W1F + (ksl * 8) * 32 + lid;
#pragma unroll
        for (int n0 = 0; n0 < 8; n0++) {
            uint4 w = wf[n0 * 32];
            mma_bf16(acc[n0], ah, w.x, w.y);
            mma_bf16(acc[n0], ah, w.z, w.w);
            mma_bf16(acc[n0], al, w.x, w.y);
        }
    }

    // bias + relu + split
    uint32_t Ahi[4][4], Alo[4][4];
#pragma unroll
    for (int n0 = 0; n0 < 8; n0++) {
        float2 bb = *(const float2*)(b1s + n0 * 8 + 2 * t);
        const int ks2 = n0 >> 1, ib = (n0 & 1) * 2;
        split_frag(fmaxf(acc[n0][0] + bb.x, 0.f), fmaxf(acc[n0][1] + bb.y, 0.f),
                   fmaxf(acc[n0][2] + bb.x, 0.f), fmaxf(acc[n0][3] + bb.y, 0.f),
                   Ahi[ks2][ib], Ahi[ks2][ib + 1], Alo[ks2][ib], Alo[ks2][ib + 1]);
    }

    // GEMM2: K=64, fragments from L2
    float d2[4][4];
#pragma unroll
    for (int nb = 0; nb < 4; nb++)
#pragma unroll
        for (int j = 0; j < 4; j++) d2[nb][j] = 0.f;

#pragma unroll
    for (int ks2 = 0; ks2 < 4; ks2++) {
        const uint4* wf = gWn2frag + (ks2 * 4) * 32 + lid;
#pragma unroll
        for (int nb = 0; nb < 4; nb++) {
            uint4 w = wf[nb * 32];
            mma_bf16(d2[nb], Ahi[ks2], w.x, w.y);
            mma_bf16(d2[nb], Ahi[ks2], w.z, w.w);
            mma_bf16(d2[nb], Alo[ks2], w.x, w.y);
        }
    }

    // epilogue: rows r0, r0+8
    {
        const int nA = n0base + r0, nB = nA + 8;
        const bool vA = nA < N_NODES, vB = nB < N_NODES;
        const bool warpFull = (n0base + 16 * wid + 15) < N_NODES;
        int gA = 0, gB = 0, gFirst = 0, gLast = -1;
        if (vA) gA = n2g[nA];
        if (vB) gB = n2g[nB];
        if (warpFull) {
            gFirst = n2g[n0base + 16 * wid];
            gLast  = n2g[n0base + 16 * wid + 15];
        }
        float a0[4], a1[4], c0v[4], c1[4];
#pragma unroll
        for (int nb = 0; nb < 4; nb++) {
            const int col = nb * 8 + 2 * t;
            float2 bb = *(const float2*)(b2s + col);
            a0[nb] = d2[nb][0] + bb.x;  a1[nb] = d2[nb][1] + bb.y;
            c0v[nb] = d2[nb][2] + bb.x; c1[nb] = d2[nb][3] + bb.y;
            if (vA) *(float2*)(n_out + (size_t)nA * 32 + col) = make_float2(a0[nb], a1[nb]);
            if (vB) *(float2*)(n_out + (size_t)nB * 32 + col) = make_float2(c0v[nb], c1[nb]);
        }
        if (warpFull && gFirst == gLast) {
#pragma unroll
            for (int nb = 0; nb < 4; nb++) {
                float s0 = a0[nb] + c0v[nb];
                float s1 = a1[nb] + c1[nb];
#pragma unroll
                for (int m = 4; m <= 16; m <<= 1) {
                    s0 += __shfl_xor_sync(0xFFFFFFFFu, s0, m);
                    s1 += __shfl_xor_sync(0xFFFFFFFFu, s1, m);
                }
                if (g == 0) {
                    const int col = nb * 8 + 2 * t;
                    atomicAdd(&Ns[gFirst * 32 + col], s0);
                    atomicAdd(&Ns[gFirst * 32 + col + 1], s1);
                }
            }
        } else {
#pragma unroll
            for (int nb = 0; nb < 4; nb++) {
                const int col = nb * 8 + 2 * t;
                if (vA) {
                    atomicAdd(&Ns[gA * 32 + col], a0[nb]);
                    atomicAdd(&Ns[gA * 32 + col + 1], a1[nb]);
                }
                if (vB) {
                    atomicAdd(&Ns[gB * 32 + col], c0v[nb]);
                    atomicAdd(&Ns[gB * 32 + col + 1], c1[nb]);
                }
            }
        }
    }
    __syncthreads();
    atomicAdd(&g_ncomb[tid], Ns[tid]);

    // -------- last-block global MLP tail --------
    __shared__ unsigned s_done;
    __threadfence();
    __syncthreads();
    if (tid == 0) {
        unsigned tk = atomicAdd(&g_ticket, 1);
        s_done = (tk == gridDim.x - 1) ? 1u : 0u;
    }
    __syncthreads();
    if (!s_done) return;
    __threadfence();

    float* U   = (float*)(smem + 0);        // 768 f
    float* W1u = (float*)(smem + 4096);     // 6144 f
    float* W2u = (float*)(smem + 28672);    // 2048 f
    float* Hg  = (float*)(smem + 40960);    // 512 f

    for (int i = tid; i < B_GRAPH * 96; i += 256) {
        const int b = i / 96, c = i % 96;
        float v;
        if (c < 32)      v = g_ncomb[b * 32 + c];
        else if (c < 64) v = g_ecomb[b * 32 + (c - 32)];
        else             v = g_repr[b * 32 + (c - 64)];
        U[i] = v;
    }
    {
        const float4* wg = (const float4*)Wu1; float4* ws = (float4*)W1u;
        for (int i = tid; i < 1536; i += 256) ws[i] = wg[i];
        const float4* w2g = (const float4*)Wu2; float4* w2s = (float4*)W2u;
        for (int i = tid; i < 512; i += 256) w2s[i] = w2g[i];
    }
    __syncthreads();

    for (int idx = tid; idx < B_GRAPH * HID; idx += 256) {
        const int b = idx >> 6, j = idx & 63;
        float s = bu1[j];
#pragma unroll 8
        for (int k = 0; k < 96; k++) s += U[b * 96 + k] * W1u[k * 64 + j];
        Hg[idx] = fmaxf(s, 0.f);
    }
    __syncthreads();
    for (int idx = tid; idx < B_GRAPH * DOUT; idx += 256) {
        const int b = idx >> 5, c = idx & 31;
        float s = bu2[c];
#pragma unroll 8
        for (int k = 0; k < 64; k++) s += Hg[b * 64 + k] * W2u[k * 32 + c];
        g_out[idx] = s;
    }
}

extern "C" void kernel_launch(void* const* d_in, const int* in_sizes, int n_in,
                              void* d_out, int out_size)
{
    const float* edge_feat = (const float*)d_in[0];
    const float* node_feat = (const float*)d_in[1];
    const float* g_repr    = (const float*)d_in[2];
    const int*   src       = (const int*)d_in[3];
    const int*   dst       = (const int*)d_in[4];
    const int*   n2g       = (const int*)d_in[5];
    const int*   e2g       = (const int*)d_in[6];
    const float* W_e1 = (const float*)d_in[7];
    const float* b_e1 = (const float*)d_in[8];
    const float* W_e2 = (const float*)d_in[9];
    const float* b_e2 = (const float*)d_in[10];
    const float* W_n1 = (const float*)d_in[11];
    const float* b_n1 = (const float*)d_in[12];
    const float* W_n2 = (const float*)d_in[13];
    const float* b_n2 = (const float*)d_in[14];
    const float* W_u1 = (const float*)d_in[15];
    const float* b_u1 = (const float*)d_in[16];
    const float* W_u2 = (const float*)d_in[17];
    const float* b_u2 = (const float*)d_in[18];

    float* out = (float*)d_out;
    float* e_out = out;                                      // [E, 32]
    float* n_out = out + (size_t)N_EDGES * DOUT;             // [N, 32]
    float* g_out = out + (size_t)(N_EDGES + N_NODES) * DOUT; // [B, 32]

    cudaFuncSetAttribute(edge_kernel, cudaFuncAttributeMaxDynamicSharedMemorySize, SM_TOTAL);
    cudaFuncSetAttribute(node_kernel, cudaFuncAttributeMaxDynamicSharedMemorySize, NSM_TOTAL);

    zero_kernel<<<6251, 256>>>(W_e1, W_e2, W_n1, W_n2);
    edge_kernel<<<N_EDGES / 128, 256, SM_TOTAL>>>(
        edge_feat, node_feat, g_repr, src, dst, e2g,
        b_e1, b_e2, e_out);
    node_kernel<<<(N_NODES + 127) / 128, 256, NSM_TOTAL>>>(
        node_feat, g_repr, n2g, b_n1, b_n2,
        W_u1, b_u1, W_u2, b_u2, n_out, g_out);
}

// round 9
// speedup vs baseline: 4.5021x; 1.2427x over previous
#include <cuda_runtime.h>
#include <cuda_bf16.h>
#include <cstdint>

#define N_NODES 50000
#define N_EDGES 800000
#define B_GRAPH 8
#define HID 64
#define DOUT 32

__device__ __forceinline__ void mma_bf16(float* d, const uint32_t* a,
                                         uint32_t b0, uint32_t b1) {
    asm volatile(
        "mma.sync.aligned.m16n8k16.row.col.f32.bf16.bf16.f32 "
        "{%0,%1,%2,%3}, {%4,%5,%6,%7}, {%8,%9}, {%0,%1,%2,%3};"
        : "+f"(d[0]), "+f"(d[1]), "+f"(d[2]), "+f"(d[3])
        : "r"(a[0]), "r"(a[1]), "r"(a[2]), "r"(a[3]), "r"(b0), "r"(b1));
}
__device__ __forceinline__ void red2(float* p, float x, float y) {
    asm volatile("red.global.add.v2.f32 [%0], {%1, %2};"
                 :: "l"(p), "f"(x), "f"(y) : "memory");
}

// -------------------- scratch (device globals) --------------------
__device__ float g_h[(size_t)N_NODES * DOUT];
__device__ float g_ecomb[B_GRAPH * DOUT];
__device__ float g_ncomb[B_GRAPH * DOUT];
__device__ unsigned int g_ticket;
// edge W1 fragments (k 0..95): [ks=6][n0=8][lane=32] uint4 {bh0,bh1,bl0,bl1}
__device__ __align__(16) uint4 gW1frag[6 * 8 * 32];
// edge W2 fragments: [ks2=4][nb=4][lane=32]
__device__ __align__(16) uint4 gW2frag[4 * 4 * 32];
// node W1 fragments (k 0..63): [ks=4][n0=8][lane=32]
__device__ __align__(16) uint4 gWn1frag[4 * 8 * 32];
// node W2 fragments: [ks2=4][nb=4][lane=32]
__device__ __align__(16) uint4 gWn2frag[4 * 4 * 32];
// per-graph fused biases: b1 + g_repr[g] @ W1[tail]
__device__ __align__(16) float gBias1e[B_GRAPH * HID];
__device__ __align__(16) float gBias1n[B_GRAPH * HID];

__device__ __forceinline__ uint32_t bfpack(float a, float b) {
    __nv_bfloat162 h = __floats2bfloat162_rn(a, b);
    return *(uint32_t*)&h;
}

__device__ __forceinline__ uint4 make_frag(float v0, float v1, float v2, float v3) {
    float h0 = __bfloat162float(__float2bfloat16(v0));
    float h1 = __bfloat162float(__float2bfloat16(v1));
    float h2 = __bfloat162float(__float2bfloat16(v2));
    float h3 = __bfloat162float(__float2bfloat16(v3));
    uint4 f;
    f.x = bfpack(h0, h1); f.y = bfpack(h2, h3);
    f.z = bfpack(v0 - h0, v1 - h1); f.w = bfpack(v2 - h2, v3 - h3);
    return f;
}

// -------------------- zero + prep --------------------
#define ZERO_BLOCKS 1563   // 1563*256 float4 >= 400k float4 (g_h)

__global__ void zero_kernel(const float* __restrict__ W1,
                            const float* __restrict__ W2,
                            const float* __restrict__ Wn1,
                            const float* __restrict__ Wn2,
                            const float* __restrict__ b1e,
                            const float* __restrict__ b1n,
                            const float* __restrict__ g_repr) {
    if (blockIdx.x == ZERO_BLOCKS) {
        const int tid = threadIdx.x;
        if (tid == 0) g_ticket = 0;
        // zero comb buffers
        if (tid < 128) {
            ((float4*)g_ecomb)[tid & 63] = make_float4(0.f, 0.f, 0.f, 0.f);
            if (tid >= 64) ((float4*)g_ncomb)[tid & 63] = make_float4(0.f, 0.f, 0.f, 0.f);
        }
        // edge W1 fragments, k 0..95
        for (int idx = tid; idx < 1536; idx += 256) {
            const int l = idx & 31, n0 = (idx >> 5) & 7, ks = idx >> 8;
            const int n = n0 * 8 + (l >> 2);
            const int k0 = ks * 16 + 2 * (l & 3);
            gW1frag[idx] = make_frag(W1[k0 * 64 + n], W1[(k0 + 1) * 64 + n],
                                     W1[(k0 + 8) * 64 + n], W1[(k0 + 9) * 64 + n]);
        }
        // edge W2 fragments
        for (int idx = tid; idx < 512; idx += 256) {
            const int l = idx & 31, nb = (idx >> 5) & 3, ks2 = idx >> 7;
            const int n = nb * 8 + (l >> 2);
            const int k0 = ks2 * 16 + 2 * (l & 3);
            gW2frag[idx] = make_frag(W2[k0 * 32 + n], W2[(k0 + 1) * 32 + n],
                                     W2[(k0 + 8) * 32 + n], W2[(k0 + 9) * 32 + n]);
        }
        // node W1 fragments, k 0..63
        for (int idx = tid; idx < 1024; idx += 256) {
            const int l = idx & 31, n0 = (idx >> 5) & 7, ks = idx >> 8;
            const int n = n0 * 8 + (l >> 2);
            const int k0 = ks * 16 + 2 * (l & 3);
            gWn1frag[idx] = make_frag(Wn1[k0 * 64 + n], Wn1[(k0 + 1) * 64 + n],
                                      Wn1[(k0 + 8) * 64 + n], Wn1[(k0 + 9) * 64 + n]);
        }
        // node W2 fragments
        for (int idx = tid; idx < 512; idx += 256) {
            const int l = idx & 31, nb = (idx >> 5) & 3, ks2 = idx >> 7;
            const int n = nb * 8 + (l >> 2);
            const int k0 = ks2 * 16 + 2 * (l & 3);
            gWn2frag[idx] = make_frag(Wn2[k0 * 32 + n], Wn2[(k0 + 1) * 32 + n],
                                      Wn2[(k0 + 8) * 32 + n], Wn2[(k0 + 9) * 32 + n]);
        }
        // fused per-graph biases (exact fp32 fold of the g_repr tail)
        for (int idx = tid; idx < B_GRAPH * HID; idx += 256) {
            const int g = idx >> 6, n = idx & 63;
            float se = b1e[n], sn = b1n[n];
            for (int k = 0; k < 32; k++) {
                se += g_repr[g * 32 + k] * W1[(96 + k) * 64 + n];
                sn += g_repr[g * 32 + k] * Wn1[(64 + k) * 64 + n];
            }
            gBias1e[idx] = se;
            gBias1n[idx] = sn;
        }
        return;
    }
    size_t i = (size_t)blockIdx.x * 256 + threadIdx.x;
    if (i < (size_t)N_NODES * DOUT / 4)
        ((float4*)g_h)[i] = make_float4(0.f, 0.f, 0.f, 0.f);
}

// float8 -> bf16 hi/lo (exact residual split)
__device__ __forceinline__ void cvt8(float4 a, float4 b, uint4& hi, uint4& lo) {
    __nv_bfloat162 h0 = __floats2bfloat162_rn(a.x, a.y);
    __nv_bfloat162 h1 = __floats2bfloat162_rn(a.z, a.w);
    __nv_bfloat162 h2 = __floats2bfloat162_rn(b.x, b.y);
    __nv_bfloat162 h3 = __floats2bfloat162_rn(b.z, b.w);
    float2 f0 = __bfloat1622float2(h0), f1 = __bfloat1622float2(h1);
    float2 f2 = __bfloat1622float2(h2), f3 = __bfloat1622float2(h3);
    __nv_bfloat162 l0 = __floats2bfloat162_rn(a.x - f0.x, a.y - f0.y);
    __nv_bfloat162 l1 = __floats2bfloat162_rn(a.z - f1.x, a.w - f1.y);
    __nv_bfloat162 l2 = __floats2bfloat162_rn(b.x - f2.x, b.y - f2.y);
    __nv_bfloat162 l3 = __floats2bfloat162_rn(b.z - f3.x, b.w - f3.y);
    hi.x = *(uint32_t*)&h0; hi.y = *(uint32_t*)&h1; hi.z = *(uint32_t*)&h2; hi.w = *(uint32_t*)&h3;
    lo.x = *(uint32_t*)&l0; lo.y = *(uint32_t*)&l1; lo.z = *(uint32_t*)&l2; lo.w = *(uint32_t*)&l3;
}

__device__ __forceinline__ void split_frag(float v0, float v1, float v2, float v3,
                                           uint32_t& hA, uint32_t& hB,
                                           uint32_t& lA, uint32_t& lB) {
    __nv_bfloat162 a = __floats2bfloat162_rn(v0, v1);
    __nv_bfloat162 b = __floats2bfloat162_rn(v2, v3);
    float2 fa = __bfloat1622float2(a), fb = __bfloat1622float2(b);
    __nv_bfloat162 la = __floats2bfloat162_rn(v0 - fa.x, v1 - fa.y);
    __nv_bfloat162 lb = __floats2bfloat162_rn(v2 - fb.x, v3 - fb.y);
    hA = *(uint32_t*)&a; hB = *(uint32_t*)&b;
    lA = *(uint32_t*)&la; lB = *(uint32_t*)&lb;
}

// X tile GEMM pass over stride-72 hi/lo buffers; NKS ks-steps, W offset KS0.
template<int KS0, int NKS>
__device__ __forceinline__ void gemm_pass(
    const __nv_bfloat16* __restrict__ Xhi, const __nv_bfloat16* __restrict__ Xlo,
    const uint4* __restrict__ WF, int r0, int t, int lid, float acc[8][4])
{
#pragma unroll
    for (int ksl = 0; ksl < NKS; ksl++) {
        const int c0 = ksl * 16 + 2 * t;
        const __nv_bfloat16* xh = Xhi + r0 * 72 + c0;
        const __nv_bfloat16* xl = Xlo + r0 * 72 + c0;
        uint32_t ah[4], al[4];
        ah[0] = *(const uint32_t*)(xh);
        ah[1] = *(const uint32_t*)(xh + 8 * 72);
        ah[2] = *(const uint32_t*)(xh + 8);
        ah[3] = *(const uint32_t*)(xh + 8 * 72 + 8);
        al[0] = *(const uint32_t*)(xl);
        al[1] = *(const uint32_t*)(xl + 8 * 72);
        al[2] = *(const uint32_t*)(xl + 8);
        al[3] = *(const uint32_t*)(xl + 8 * 72 + 8);
        const uint4* wf = WF + ((KS0 + ksl) * 8) * 32 + lid;
#pragma unroll
        for (int n0 = 0; n0 < 8; n0++) {
            uint4 w = wf[n0 * 32];
            mma_bf16(acc[n0], ah, w.x, w.y);
            mma_bf16(acc[n0], ah, w.z, w.w);
            mma_bf16(acc[n0], al, w.x, w.y);
        }
    }
}

// ================== EDGE KERNEL ==================
#define SM_XHI   0        // 128 x 72 bf16 = 18432
#define SM_XLO   18432
#define SM_W1F   36864    // 1536 uint4 = 24576
#define SM_BIAS  61440    // 512 f = 2048
#define SM_B2    63488    // 128
#define SM_ES    63616    // 1024
#define SM_TOTAL 64640

__global__ void __launch_bounds__(256, 3) edge_kernel(
    const float* __restrict__ edge_feat, const float* __restrict__ node_feat,
    const int* __restrict__ src, const int* __restrict__ dst,
    const int* __restrict__ e2g, const float* __restrict__ b2,
    float* __restrict__ e_out)
{
    extern __shared__ unsigned char smem[];
    const int tid = threadIdx.x;
    const int wid = tid >> 5, lid = tid & 31;

    __nv_bfloat16* Xhi = (__nv_bfloat16*)(smem + SM_XHI);
    __nv_bfloat16* Xlo = (__nv_bfloat16*)(smem + SM_XLO);
    const uint4* W1F = (const uint4*)(smem + SM_W1F);
    float* Bs  = (float*)(smem + SM_BIAS);
    float* b2s = (float*)(smem + SM_B2);
    float* Es  = (float*)(smem + SM_ES);

    {
        uint4* d1 = (uint4*)(smem + SM_W1F);
        for (int i = tid; i < 1536; i += 256) d1[i] = gW1frag[i];
        for (int i = tid; i < 512; i += 256) Bs[i] = gBias1e[i];
        if (tid < DOUT) b2s[tid] = b2[tid];
        Es[tid] = 0.f;
    }

    const size_t e0 = (size_t)blockIdx.x * 128;
    const int r = tid >> 1, half = tid & 1;
    const size_t eg = e0 + r;
    const int si = src[eg], di = dst[eg];

    // prefetch pass-2 gather (node_feat[dst], 16 cols per thread)
    float4 pf[4];
    {
        const float4* pd = (const float4*)(node_feat + (size_t)di * 32) + 4 * half;
        pf[0] = pd[0]; pf[1] = pd[1]; pf[2] = pd[2]; pf[3] = pd[3];
    }

    // gather pass 1: k 0..63 = edge_feat || node_feat[src]
    {
        const float4* p = (const float4*)(half ? node_feat + (size_t)si * 32
                                               : edge_feat + eg * 32);
        __nv_bfloat16* xh = Xhi + r * 72 + half * 32;
        __nv_bfloat16* xl = Xlo + r * 72 + half * 32;
#pragma unroll
        for (int q = 0; q < 4; q++) {
            uint4 hi, lo;
            cvt8(p[2 * q], p[2 * q + 1], hi, lo);
            *(uint4*)(xh + q * 8) = hi;
            *(uint4*)(xl + q * 8) = lo;
        }
    }
    __syncthreads();

    const int g = lid >> 2, t = lid & 3;
    const int r0 = 16 * wid + g;
    float acc[8][4];
#pragma unroll
    for (int n0 = 0; n0 < 8; n0++)
#pragma unroll
        for (int j = 0; j < 4; j++) acc[n0][j] = 0.f;

    gemm_pass<0, 4>(Xhi, Xlo, W1F, r0, t, lid, acc);
    __syncthreads();

    // store pass-2 gather (cols 0..31 now hold k 64..95 = node_feat[dst])
    {
        __nv_bfloat16* xh = Xhi + r * 72 + half * 16;
        __nv_bfloat16* xl = Xlo + r * 72 + half * 16;
        uint4 hi, lo;
        cvt8(pf[0], pf[1], hi, lo);
        *(uint4*)(xh) = hi; *(uint4*)(xl) = lo;
        cvt8(pf[2], pf[3], hi, lo);
        *(uint4*)(xh + 8) = hi; *(uint4*)(xl + 8) = lo;
    }
    __syncthreads();

    // row graph ids (needed for fused bias + epilogue)
    const size_t eA = e0 + r0, eB = eA + 8;
    const int gA = e2g[eA], gB = e2g[eB];

    gemm_pass<4, 2>(Xhi, Xlo, W1F, r0, t, lid, acc);

    // fused bias + relu + register split
    uint32_t Ahi[4][4], Alo[4][4];
#pragma unroll
    for (int n0 = 0; n0 < 8; n0++) {
        const int col = n0 * 8 + 2 * t;
        float2 bbA = *(const float2*)(Bs + gA * 64 + col);
        float2 bbB = *(const float2*)(Bs + gB * 64 + col);
        const int ks2 = n0 >> 1, ib = (n0 & 1) * 2;
        split_frag(fmaxf(acc[n0][0] + bbA.x, 0.f), fmaxf(acc[n0][1] + bbA.y, 0.f),
                   fmaxf(acc[n0][2] + bbB.x, 0.f), fmaxf(acc[n0][3] + bbB.y, 0.f),
                   Ahi[ks2][ib], Ahi[ks2][ib + 1], Alo[ks2][ib], Alo[ks2][ib + 1]);
    }

    // GEMM2: K=64, weight fragments from L1/L2
    float d2[4][4];
#pragma unroll
    for (int nb = 0; nb < 4; nb++)
#pragma unroll
        for (int j = 0; j < 4; j++) d2[nb][j] = 0.f;

#pragma unroll
    for (int ks2 = 0; ks2 < 4; ks2++) {
        const uint4* wf = gW2frag + (ks2 * 4) * 32 + lid;
#pragma unroll
        for (int nb = 0; nb < 4; nb++) {
            uint4 w = wf[nb * 32];
            mma_bf16(d2[nb], Ahi[ks2], w.x, w.y);
            mma_bf16(d2[nb], Ahi[ks2], w.z, w.w);
            mma_bf16(d2[nb], Alo[ks2], w.x, w.y);
        }
    }

    // epilogue
    {
        const int dA = dst[eA], dB = dst[eB];
        const int gFirst = e2g[e0 + 16 * wid];
        const int gLast  = e2g[e0 + 16 * wid + 15];
        float* hA = g_h + (size_t)dA * 32;
        float* hB = g_h + (size_t)dB * 32;
        float* oA = e_out + eA * 32;
        float* oB = e_out + eB * 32;
        float a0[4], a1[4], c0v[4], c1[4];
#pragma unroll
        for (int nb = 0; nb < 4; nb++) {
            const int col = nb * 8 + 2 * t;
            float2 bb = *(const float2*)(b2s + col);
            a0[nb] = d2[nb][0] + bb.x;  a1[nb] = d2[nb][1] + bb.y;
            c0v[nb] = d2[nb][2] + bb.x; c1[nb] = d2[nb][3] + bb.y;
            *(float2*)(oA + col) = make_float2(a0[nb], a1[nb]);
            *(float2*)(oB + col) = make_float2(c0v[nb], c1[nb]);
            red2(hA + col, a0[nb], a1[nb]);
            red2(hB + col, c0v[nb], c1[nb]);
        }
        if (gFirst == gLast) {
#pragma unroll
            for (int nb = 0; nb < 4; nb++) {
                float s0 = a0[nb] + c0v[nb];
                float s1 = a1[nb] + c1[nb];
#pragma unroll
                for (int m = 4; m <= 16; m <<= 1) {
                    s0 += __shfl_xor_sync(0xFFFFFFFFu, s0, m);
                    s1 += __shfl_xor_sync(0xFFFFFFFFu, s1, m);
                }
                if (g == 0) {
                    const int col = nb * 8 + 2 * t;
                    atomicAdd(&Es[gFirst * 32 + col], s0);
                    atomicAdd(&Es[gFirst * 32 + col + 1], s1);
                }
            }
        } else {
#pragma unroll
            for (int nb = 0; nb < 4; nb++) {
                const int col = nb * 8 + 2 * t;
                atomicAdd(&Es[gA * 32 + col], a0[nb]);
                atomicAdd(&Es[gA * 32 + col + 1], a1[nb]);
                atomicAdd(&Es[gB * 32 + col], c0v[nb]);
                atomicAdd(&Es[gB * 32 + col + 1], c1[nb]);
            }
        }
    }
    __syncthreads();
    atomicAdd(&g_ecomb[tid], Es[tid]);
}

// ================== NODE KERNEL + global tail ==================
#define NSM_XHI   0        // 128 x 72 bf16 = 18432
#define NSM_XLO   18432
#define NSM_W1F   36864    // 1024 uint4 = 16384
#define NSM_BIAS  53248    // 2048
#define NSM_B2    55296    // 128
#define NSM_NS    55424    // 1024
#define NSM_TOTAL 56448

__global__ void __launch_bounds__(256, 3) node_kernel(
    const float* __restrict__ node_feat, const float* __restrict__ g_repr,
    const int* __restrict__ n2g, const float* __restrict__ b2,
    const float* __restrict__ Wu1, const float* __restrict__ bu1,
    const float* __restrict__ Wu2, const float* __restrict__ bu2,
    float* __restrict__ n_out, float* __restrict__ g_out)
{
    extern __shared__ unsigned char smem[];
    const int tid = threadIdx.x;
    const int wid = tid >> 5, lid = tid & 31;

    __nv_bfloat16* Xhi = (__nv_bfloat16*)(smem + NSM_XHI);
    __nv_bfloat16* Xlo = (__nv_bfloat16*)(smem + NSM_XLO);
    const uint4* W1F = (const uint4*)(smem + NSM_W1F);
    float* Bs  = (float*)(smem + NSM_BIAS);
    float* b2s = (float*)(smem + NSM_B2);
    float* Ns  = (float*)(smem + NSM_NS);

    {
        uint4* d1 = (uint4*)(smem + NSM_W1F);
        for (int i = tid; i < 1024; i += 256) d1[i] = gWn1frag[i];
        for (int i = tid; i < 512; i += 256) Bs[i] = gBias1n[i];
        if (tid < DOUT) b2s[tid] = b2[tid];
        Ns[tid] = 0.f;
    }

    const int n0base = blockIdx.x * 128;

    // gather: k 0..63 = node_feat || g_h; 2 threads per row, 32 cols each
    {
        const int r = tid >> 1, half = tid & 1;
        const int node = n0base + r;
        __nv_bfloat16* xh = Xhi + r * 72 + half * 32;
        __nv_bfloat16* xl = Xlo + r * 72 + half * 32;
        if (node < N_NODES) {
            const float4* p = (const float4*)((half ? g_h : node_feat) + (size_t)node * 32);
#pragma unroll
            for (int q = 0; q < 4; q++) {
                uint4 hi, lo;
                cvt8(p[2 * q], p[2 * q + 1], hi, lo);
                *(uint4*)(xh + q * 8) = hi;
                *(uint4*)(xl + q * 8) = lo;
            }
        } else {
            const uint4 z = make_uint4(0, 0, 0, 0);
#pragma unroll
            for (int q = 0; q < 4; q++) {
                *(uint4*)(xh + q * 8) = z;
                *(uint4*)(xl + q * 8) = z;
            }
        }
    }
    __syncthreads();

    const int g = lid >> 2, t = lid & 3;
    const int r0 = 16 * wid + g;
    float acc[8][4];
#pragma unroll
    for (int n0 = 0; n0 < 8; n0++)
#pragma unroll
        for (int j = 0; j < 4; j++) acc[n0][j] = 0.f;

    gemm_pass<0, 4>(Xhi, Xlo, W1F, r0, t, lid, acc);

    // fused bias + relu + split
    const int nA = n0base + r0, nB = nA + 8;
    const bool vA = nA < N_NODES, vB = nB < N_NODES;
    const int gA = vA ? n2g[nA] : 0, gB = vB ? n2g[nB] : 0;

    uint32_t Ahi[4][4], Alo[4][4];
#pragma unroll
    for (int n0 = 0; n0 < 8; n0++) {
        const int col = n0 * 8 + 2 * t;
        float2 bbA = *(const float2*)(Bs + gA * 64 + col);
        float2 bbB = *(const float2*)(Bs + gB * 64 + col);
        const int ks2 = n0 >> 1, ib = (n0 & 1) * 2;
        split_frag(fmaxf(acc[n0][0] + bbA.x, 0.f), fmaxf(acc[n0][1] + bbA.y, 0.f),
                   fmaxf(acc[n0][2] + bbB.x, 0.f), fmaxf(acc[n0][3] + bbB.y, 0.f),
                   Ahi[ks2][ib], Ahi[ks2][ib + 1], Alo[ks2][ib], Alo[ks2][ib + 1]);
    }

    float d2[4][4];
#pragma unroll
    for (int nb = 0; nb < 4; nb++)
#pragma unroll
        for (int j = 0; j < 4; j++) d2[nb][j] = 0.f;

#pragma unroll
    for (int ks2 = 0; ks2 < 4; ks2++) {
        const uint4* wf = gWn2frag + (ks2 * 4) * 32 + lid;
#pragma unroll
        for (int nb = 0; nb < 4; nb++) {
            uint4 w = wf[nb * 32];
            mma_bf16(d2[nb], Ahi[ks2], w.x, w.y);
            mma_bf16(d2[nb], Ahi[ks2], w.z, w.w);
            mma_bf16(d2[nb], Alo[ks2], w.x, w.y);
        }
    }

    // epilogue
    {
        const bool warpFull = (n0base + 16 * wid + 15) < N_NODES;
        int gFirst = 0, gLast = -1;
        if (warpFull) {
            gFirst = n2g[n0base + 16 * wid];
            gLast  = n2g[n0base + 16 * wid + 15];
        }
        float a0[4], a1[4], c0v[4], c1[4];
#pragma unroll
        for (int nb = 0; nb < 4; nb++) {
            const int col = nb * 8 + 2 * t;
            float2 bb = *(const float2*)(b2s + col);
            a0[nb] = d2[nb][0] + bb.x;  a1[nb] = d2[nb][1] + bb.y;
            c0v[nb] = d2[nb][2] + bb.x; c1[nb] = d2[nb][3] + bb.y;
            if (vA) *(float2*)(n_out + (size_t)nA * 32 + col) = make_float2(a0[nb], a1[nb]);
            if (vB) *(float2*)(n_out + (size_t)nB * 32 + col) = make_float2(c0v[nb], c1[nb]);
        }
        if (warpFull && gFirst == gLast) {
#pragma unroll
            for (int nb = 0; nb < 4; nb++) {
                float s0 = a0[nb] + c0v[nb];
                float s1 = a1[nb] + c1[nb];
#pragma unroll
                for (int m = 4; m <= 16; m <<= 1) {
                    s0 += __shfl_xor_sync(0xFFFFFFFFu, s0, m);
                    s1 += __shfl_xor_sync(0xFFFFFFFFu, s1, m);
                }
                if (g == 0) {
                    const int col = nb * 8 + 2 * t;
                    atomicAdd(&Ns[gFirst * 32 + col], s0);
                    atomicAdd(&Ns[gFirst * 32 + col + 1], s1);
                }
            }
        } else {
#pragma unroll
            for (int nb = 0; nb < 4; nb++) {
                const int col = nb * 8 + 2 * t;
                if (vA) {
                    atomicAdd(&Ns[gA * 32 + col], a0[nb]);
                    atomicAdd(&Ns[gA * 32 + col + 1], a1[nb]);
                }
                if (vB) {
                    atomicAdd(&Ns[gB * 32 + col], c0v[nb]);
                    atomicAdd(&Ns[gB * 32 + col + 1], c1[nb]);
                }
            }
        }
    }
    __syncthreads();
    atomicAdd(&g_ncomb[tid], Ns[tid]);

    // -------- last-block global MLP tail --------
    __shared__ unsigned s_done;
    __threadfence();
    __syncthreads();
    if (tid == 0) {
        unsigned tk = atomicAdd(&g_ticket, 1);
        s_done = (tk == gridDim.x - 1) ? 1u : 0u;
    }
    __syncthreads();
    if (!s_done) return;
    __threadfence();

    float* U   = (float*)(smem + 0);        // 768 f
    float* W1u = (float*)(smem + 4096);     // 6144 f
    float* W2u = (float*)(smem + 28672);    // 2048 f
    float* Hg  = (float*)(smem + 40960);    // 512 f

    for (int i = tid; i < B_GRAPH * 96; i += 256) {
        const int b = i / 96, c = i % 96;
        float v;
        if (c < 32)      v = g_ncomb[b * 32 + c];
        else if (c < 64) v = g_ecomb[b * 32 + (c - 32)];
        else             v = g_repr[b * 32 + (c - 64)];
        U[i] = v;
    }
    {
        const float4* wg = (const float4*)Wu1; float4* ws = (float4*)W1u;
        for (int i = tid; i < 1536; i += 256) ws[i] = wg[i];
        const float4* w2g = (const float4*)Wu2; float4* w2s = (float4*)W2u;
        for (int i = tid; i < 512; i += 256) w2s[i] = w2g[i];
    }
    __syncthreads();

    for (int idx = tid; idx < B_GRAPH * HID; idx += 256) {
        const int b = idx >> 6, j = idx & 63;
        float s = bu1[j];
#pragma unroll 8
        for (int k = 0; k < 96; k++) s += U[b * 96 + k] * W1u[k * 64 + j];
        Hg[idx] = fmaxf(s, 0.f);
    }
    __syncthreads();
    for (int idx = tid; idx < B_GRAPH * DOUT; idx += 256) {
        const int b = idx >> 5, c = idx & 31;
        float s = bu2[c];
#pragma unroll 8
        for (int k = 0; k < 64; k++) s += Hg[b * 64 + k] * W2u[k * 32 + c];
        g_out[idx] = s;
    }
}

extern "C" void kernel_launch(void* const* d_in, const int* in_sizes, int n_in,
                              void* d_out, int out_size)
{
    const float* edge_feat = (const float*)d_in[0];
    const float* node_feat = (const float*)d_in[1];
    const float* g_repr    = (const float*)d_in[2];
    const int*   src       = (const int*)d_in[3];
    const int*   dst       = (const int*)d_in[4];
    const int*   n2g       = (const int*)d_in[5];
    const int*   e2g       = (const int*)d_in[6];
    const float* W_e1 = (const float*)d_in[7];
    const float* b_e1 = (const float*)d_in[8];
    const float* W_e2 = (const float*)d_in[9];
    const float* b_e2 = (const float*)d_in[10];
    const float* W_n1 = (const float*)d_in[11];
    const float* b_n1 = (const float*)d_in[12];
    const float* W_n2 = (const float*)d_in[13];
    const float* b_n2 = (const float*)d_in[14];
    const float* W_u1 = (const float*)d_in[15];
    const float* b_u1 = (const float*)d_in[16];
    const float* W_u2 = (const float*)d_in[17];
    const float* b_u2 = (const float*)d_in[18];

    float* out = (float*)d_out;
    float* e_out = out;                                      // [E, 32]
    float* n_out = out + (size_t)N_EDGES * DOUT;             // [N, 32]
    float* g_out = out + (size_t)(N_EDGES + N_NODES) * DOUT; // [B, 32]

    cudaFuncSetAttribute(edge_kernel, cudaFuncAttributeMaxDynamicSharedMemorySize, SM_TOTAL);
    cudaFuncSetAttribute(node_kernel, cudaFuncAttributeMaxDynamicSharedMemorySize, NSM_TOTAL);

    zero_kernel<<<ZERO_BLOCKS + 1, 256>>>(W_e1, W_e2, W_n1, W_n2,
                                          b_e1, b_n1, g_repr);
    edge_kernel<<<N_EDGES / 128, 256, SM_TOTAL>>>(
        edge_feat, node_feat, src, dst, e2g, b_e2, e_out);
    node_kernel<<<(N_NODES + 127) / 128, 256, NSM_TOTAL>>>(
        node_feat, g_repr, n2g, b_n2,
        W_u1, b_u1, W_u2, b_u2, n_out, g_out);
}

// round 10
// speedup vs baseline: 5.4406x; 1.2085x over previous
#include <cuda_runtime.h>
#include <cuda_fp16.h>
#include <cstdint>

#define N_NODES 50000
#define N_EDGES 800000
#define B_GRAPH 8
#define HID 64
#define DOUT 32

__device__ __forceinline__ void mma_h(float* d, const uint32_t* a,
                                      uint32_t b0, uint32_t b1) {
    asm volatile(
        "mma.sync.aligned.m16n8k16.row.col.f32.f16.f16.f32 "
        "{%0,%1,%2,%3}, {%4,%5,%6,%7}, {%8,%9}, {%0,%1,%2,%3};"
        : "+f"(d[0]), "+f"(d[1]), "+f"(d[2]), "+f"(d[3])
        : "r"(a[0]), "r"(a[1]), "r"(a[2]), "r"(a[3]), "r"(b0), "r"(b1));
}
__device__ __forceinline__ void red2(float* p, float x, float y) {
    asm volatile("red.global.add.v2.f32 [%0], {%1, %2};"
                 :: "l"(p), "f"(x), "f"(y) : "memory");
}

// -------------------- scratch (device globals) --------------------
__device__ float g_h[(size_t)N_NODES * DOUT];
__device__ float g_ecomb[B_GRAPH * DOUT];
__device__ float g_ncomb[B_GRAPH * DOUT];
__device__ unsigned int g_ticket;
// fp16 hi-only weight fragments; each uint4 = two n-blocks {b0,b1} pairs
// edge W1 (k 0..95): [ks=6][p=4][lane=32]
__device__ __align__(16) uint4 gW1frag[6 * 4 * 32];
// edge W2: [ks2=4][p=2][lane=32]
__device__ __align__(16) uint4 gW2frag[4 * 2 * 32];
// node W1 (k 0..63): [ks=4][p=4][lane=32]
__device__ __align__(16) uint4 gWn1frag[4 * 4 * 32];
// node W2: [ks2=4][p=2][lane=32]
__device__ __align__(16) uint4 gWn2frag[4 * 2 * 32];
// per-graph fused biases: b1 + g_repr[g] @ W1[tail]  (exact fp32 fold)
__device__ __align__(16) float gBias1e[B_GRAPH * HID];
__device__ __align__(16) float gBias1n[B_GRAPH * HID];

__device__ __forceinline__ uint32_t hpack(float a, float b) {
    __half2 h = __floats2half2_rn(a, b);
    return *(uint32_t*)&h;
}

// -------------------- zero + prep (prep spread over 8 blocks) --------------------
#define ZERO_BLOCKS 1563   // 1563*256 float4 >= 400k float4 (g_h)
#define PSTRIDE 2048       // 8 prep blocks * 256 threads

__global__ void zero_kernel(const float* __restrict__ W1,
                            const float* __restrict__ W2,
                            const float* __restrict__ Wn1,
                            const float* __restrict__ Wn2,
                            const float* __restrict__ b1e,
                            const float* __restrict__ b1n,
                            const float* __restrict__ g_repr) {
    if (blockIdx.x >= ZERO_BLOCKS) {
        const int pidx = (blockIdx.x - ZERO_BLOCKS) * 256 + threadIdx.x;
        if (pidx == 0) g_ticket = 0;
        if (pidx < 64) ((float4*)g_ecomb)[pidx] = make_float4(0.f, 0.f, 0.f, 0.f);
        else if (pidx < 128) ((float4*)g_ncomb)[pidx - 64] = make_float4(0.f, 0.f, 0.f, 0.f);
        // edge W1 fragments (hi-only fp16), k 0..95
        for (int idx = pidx; idx < 768; idx += PSTRIDE) {
            const int l = idx & 31, p = (idx >> 5) & 3, ks = idx >> 7;
            const int ne = p * 16 + (l >> 2), no = ne + 8;
            const int k0 = ks * 16 + 2 * (l & 3);
            uint4 f;
            f.x = hpack(W1[k0 * 64 + ne], W1[(k0 + 1) * 64 + ne]);
            f.y = hpack(W1[(k0 + 8) * 64 + ne], W1[(k0 + 9) * 64 + ne]);
            f.z = hpack(W1[k0 * 64 + no], W1[(k0 + 1) * 64 + no]);
            f.w = hpack(W1[(k0 + 8) * 64 + no], W1[(k0 + 9) * 64 + no]);
            gW1frag[idx] = f;
        }
        // edge W2 fragments
        for (int idx = pidx; idx < 256; idx += PSTRIDE) {
            const int l = idx & 31, p = (idx >> 5) & 1, ks2 = idx >> 6;
            const int ne = p * 16 + (l >> 2), no = ne + 8;
            const int k0 = ks2 * 16 + 2 * (l & 3);
            uint4 f;
            f.x = hpack(W2[k0 * 32 + ne], W2[(k0 + 1) * 32 + ne]);
            f.y = hpack(W2[(k0 + 8) * 32 + ne], W2[(k0 + 9) * 32 + ne]);
            f.z = hpack(W2[k0 * 32 + no], W2[(k0 + 1) * 32 + no]);
            f.w = hpack(W2[(k0 + 8) * 32 + no], W2[(k0 + 9) * 32 + no]);
            gW2frag[idx] = f;
        }
        // node W1 fragments, k 0..63
        for (int idx = pidx; idx < 512; idx += PSTRIDE) {
            const int l = idx & 31, p = (idx >> 5) & 3, ks = idx >> 7;
            const int ne = p * 16 + (l >> 2), no = ne + 8;
            const int k0 = ks * 16 + 2 * (l & 3);
            uint4 f;
            f.x = hpack(Wn1[k0 * 64 + ne], Wn1[(k0 + 1) * 64 + ne]);
            f.y = hpack(Wn1[(k0 + 8) * 64 + ne], Wn1[(k0 + 9) * 64 + ne]);
            f.z = hpack(Wn1[k0 * 64 + no], Wn1[(k0 + 1) * 64 + no]);
            f.w = hpack(Wn1[(k0 + 8) * 64 + no], Wn1[(k0 + 9) * 64 + no]);
            gWn1frag[idx] = f;
        }
        // node W2 fragments
        for (int idx = pidx; idx < 256; idx += PSTRIDE) {
            const int l = idx & 31, p = (idx >> 5) & 1, ks2 = idx >> 6;
            const int ne = p * 16 + (l >> 2), no = ne + 8;
            const int k0 = ks2 * 16 + 2 * (l & 3);
            uint4 f;
            f.x = hpack(Wn2[k0 * 32 + ne], Wn2[(k0 + 1) * 32 + ne]);
            f.y = hpack(Wn2[(k0 + 8) * 32 + ne], Wn2[(k0 + 9) * 32 + ne]);
            f.z = hpack(Wn2[k0 * 32 + no], Wn2[(k0 + 1) * 32 + no]);
            f.w = hpack(Wn2[(k0 + 8) * 32 + no], Wn2[(k0 + 9) * 32 + no]);
            gWn2frag[idx] = f;
        }
        // fused per-graph biases (exact fp32)
        for (int idx = pidx; idx < B_GRAPH * HID; idx += PSTRIDE) {
            const int g = idx >> 6, n = idx & 63;
            float se = b1e[n], sn = b1n[n];
            for (int k = 0; k < 32; k++) {
                se += g_repr[g * 32 + k] * W1[(96 + k) * 64 + n];
                sn += g_repr[g * 32 + k] * Wn1[(64 + k) * 64 + n];
            }
            gBias1e[idx] = se;
            gBias1n[idx] = sn;
        }
        return;
    }
    size_t i = (size_t)blockIdx.x * 256 + threadIdx.x;
    if (i < (size_t)N_NODES * DOUT / 4)
        ((float4*)g_h)[i] = make_float4(0.f, 0.f, 0.f, 0.f);
}

// float8 -> fp16 hi/lo (X captured to ~2^-22)
__device__ __forceinline__ void cvt8h(float4 a, float4 b, uint4& hi, uint4& lo) {
    __half2 h0 = __floats2half2_rn(a.x, a.y);
    __half2 h1 = __floats2half2_rn(a.z, a.w);
    __half2 h2 = __floats2half2_rn(b.x, b.y);
    __half2 h3 = __floats2half2_rn(b.z, b.w);
    float2 f0 = __half22float2(h0), f1 = __half22float2(h1);
    float2 f2 = __half22float2(h2), f3 = __half22float2(h3);
    __half2 l0 = __floats2half2_rn(a.x - f0.x, a.y - f0.y);
    __half2 l1 = __floats2half2_rn(a.z - f1.x, a.w - f1.y);
    __half2 l2 = __floats2half2_rn(b.x - f2.x, b.y - f2.y);
    __half2 l3 = __floats2half2_rn(b.z - f3.x, b.w - f3.y);
    hi.x = *(uint32_t*)&h0; hi.y = *(uint32_t*)&h1; hi.z = *(uint32_t*)&h2; hi.w = *(uint32_t*)&h3;
    lo.x = *(uint32_t*)&l0; lo.y = *(uint32_t*)&l1; lo.z = *(uint32_t*)&l2; lo.w = *(uint32_t*)&l3;
}

__device__ __forceinline__ void split_frag(float v0, float v1, float v2, float v3,
                                           uint32_t& hA, uint32_t& hB,
                                           uint32_t& lA, uint32_t& lB) {
    __half2 a = __floats2half2_rn(v0, v1);
    __half2 b = __floats2half2_rn(v2, v3);
    float2 fa = __half22float2(a), fb = __half22float2(b);
    __half2 la = __floats2half2_rn(v0 - fa.x, v1 - fa.y);
    __half2 lb = __floats2half2_rn(v2 - fb.x, v3 - fb.y);
    hA = *(uint32_t*)&a; hB = *(uint32_t*)&b;
    lA = *(uint32_t*)&la; lB = *(uint32_t*)&lb;
}

// X tile GEMM pass over stride-72 fp16 hi/lo buffers; 2-term (Xhi+Xlo)*Whi.
template<int KS0, int NKS>
__device__ __forceinline__ void gemm_pass(
    const __half* __restrict__ Xhi, const __half* __restrict__ Xlo,
    const uint4* __restrict__ WF, int r0, int t, int lid, float acc[8][4])
{
#pragma unroll
    for (int ksl = 0; ksl < NKS; ksl++) {
        const int c0 = ksl * 16 + 2 * t;
        const __half* xh = Xhi + r0 * 72 + c0;
        const __half* xl = Xlo + r0 * 72 + c0;
        uint32_t ah[4], al[4];
        ah[0] = *(const uint32_t*)(xh);
        ah[1] = *(const uint32_t*)(xh + 8 * 72);
        ah[2] = *(const uint32_t*)(xh + 8);
        ah[3] = *(const uint32_t*)(xh + 8 * 72 + 8);
        al[0] = *(const uint32_t*)(xl);
        al[1] = *(const uint32_t*)(xl + 8 * 72);
        al[2] = *(const uint32_t*)(xl + 8);
        al[3] = *(const uint32_t*)(xl + 8 * 72 + 8);
        const uint4* wf = WF + ((KS0 + ksl) * 4) * 32 + lid;
#pragma unroll
        for (int p = 0; p < 4; p++) {
            uint4 w = wf[p * 32];
            mma_h(acc[2 * p], ah, w.x, w.y);
            mma_h(acc[2 * p], al, w.x, w.y);
            mma_h(acc[2 * p + 1], ah, w.z, w.w);
            mma_h(acc[2 * p + 1], al, w.z, w.w);
        }
    }
}

// ================== EDGE KERNEL ==================
#define SM_XHI   0        // 128 x 72 fp16 = 18432
#define SM_XLO   18432
#define SM_W1F   36864    // 768 uint4 = 12288
#define SM_BIAS  49152    // 512 f = 2048
#define SM_B2    51200    // 128
#define SM_ES    51328    // 1024
#define SM_TOTAL 52352

__global__ void __launch_bounds__(256, 3) edge_kernel(
    const float* __restrict__ edge_feat, const float* __restrict__ node_feat,
    const int* __restrict__ src, const int* __restrict__ dst,
    const int* __restrict__ e2g, const float* __restrict__ b2,
    float* __restrict__ e_out)
{
    extern __shared__ unsigned char smem[];
    const int tid = threadIdx.x;
    const int wid = tid >> 5, lid = tid & 31;

    __half* Xhi = (__half*)(smem + SM_XHI);
    __half* Xlo = (__half*)(smem + SM_XLO);
    const uint4* W1F = (const uint4*)(smem + SM_W1F);
    float* Bs  = (float*)(smem + SM_BIAS);
    float* b2s = (float*)(smem + SM_B2);
    float* Es  = (float*)(smem + SM_ES);

    {
        uint4* d1 = (uint4*)(smem + SM_W1F);
        for (int i = tid; i < 768; i += 256) d1[i] = gW1frag[i];
        for (int i = tid; i < 512; i += 256) Bs[i] = gBias1e[i];
        if (tid < DOUT) b2s[tid] = b2[tid];
        Es[tid] = 0.f;
    }

    const size_t e0 = (size_t)blockIdx.x * 128;
    const int r = tid >> 1, half = tid & 1;
    const size_t eg = e0 + r;
    const int si = src[eg], di = dst[eg];

    // prefetch pass-2 gather (node_feat[dst], 16 cols per thread)
    float4 pf[4];
    {
        const float4* pd = (const float4*)(node_feat + (size_t)di * 32) + 4 * half;
        pf[0] = pd[0]; pf[1] = pd[1]; pf[2] = pd[2]; pf[3] = pd[3];
    }

    // gather pass 1: k 0..63 = edge_feat || node_feat[src]
    {
        const float4* p = (const float4*)(half ? node_feat + (size_t)si * 32
                                               : edge_feat + eg * 32);
        __half* xh = Xhi + r * 72 + half * 32;
        __half* xl = Xlo + r * 72 + half * 32;
#pragma unroll
        for (int q = 0; q < 4; q++) {
            uint4 hi, lo;
            cvt8h(p[2 * q], p[2 * q + 1], hi, lo);
            *(uint4*)(xh + q * 8) = hi;
            *(uint4*)(xl + q * 8) = lo;
        }
    }
    __syncthreads();

    const int g = lid >> 2, t = lid & 3;
    const int r0 = 16 * wid + g;
    float acc[8][4];
#pragma unroll
    for (int n0 = 0; n0 < 8; n0++)
#pragma unroll
        for (int j = 0; j < 4; j++) acc[n0][j] = 0.f;

    gemm_pass<0, 4>(Xhi, Xlo, W1F, r0, t, lid, acc);
    __syncthreads();

    // store pass-2 gather (cols 0..31 now hold k 64..95 = node_feat[dst])
    {
        __half* xh = Xhi + r * 72 + half * 16;
        __half* xl = Xlo + r * 72 + half * 16;
        uint4 hi, lo;
        cvt8h(pf[0], pf[1], hi, lo);
        *(uint4*)(xh) = hi; *(uint4*)(xl) = lo;
        cvt8h(pf[2], pf[3], hi, lo);
        *(uint4*)(xh + 8) = hi; *(uint4*)(xl + 8) = lo;
    }
    __syncthreads();

    const size_t eA = e0 + r0, eB = eA + 8;
    const int gA = e2g[eA], gB = e2g[eB];

    gemm_pass<4, 2>(Xhi, Xlo, W1F, r0, t, lid, acc);

    // fused bias + relu + register split (fp16 hi/lo A fragments)
    uint32_t Ahi[4][4], Alo[4][4];
#pragma unroll
    for (int n0 = 0; n0 < 8; n0++) {
        const int col = n0 * 8 + 2 * t;
        float2 bbA = *(const float2*)(Bs + gA * 64 + col);
        float2 bbB = *(const float2*)(Bs + gB * 64 + col);
        const int ks2 = n0 >> 1, ib = (n0 & 1) * 2;
        split_frag(fmaxf(acc[n0][0] + bbA.x, 0.f), fmaxf(acc[n0][1] + bbA.y, 0.f),
                   fmaxf(acc[n0][2] + bbB.x, 0.f), fmaxf(acc[n0][3] + bbB.y, 0.f),
                   Ahi[ks2][ib], Ahi[ks2][ib + 1], Alo[ks2][ib], Alo[ks2][ib + 1]);
    }

    // GEMM2: K=64, 2-term, weight fragments from L1/L2
    float d2[4][4];
#pragma unroll
    for (int nb = 0; nb < 4; nb++)
#pragma unroll
        for (int j = 0; j < 4; j++) d2[nb][j] = 0.f;

#pragma unroll
    for (int ks2 = 0; ks2 < 4; ks2++) {
        const uint4* wf = gW2frag + (ks2 * 2) * 32 + lid;
#pragma unroll
        for (int p = 0; p < 2; p++) {
            uint4 w = wf[p * 32];
            mma_h(d2[2 * p], Ahi[ks2], w.x, w.y);
            mma_h(d2[2 * p], Alo[ks2], w.x, w.y);
            mma_h(d2[2 * p + 1], Ahi[ks2], w.z, w.w);
            mma_h(d2[2 * p + 1], Alo[ks2], w.z, w.w);
        }
    }

    // epilogue
    {
        const int dA = dst[eA], dB = dst[eB];
        const int gFirst = e2g[e0 + 16 * wid];
        const int gLast  = e2g[e0 + 16 * wid + 15];
        float* hA = g_h + (size_t)dA * 32;
        float* hB = g_h + (size_t)dB * 32;
        float* oA = e_out + eA * 32;
        float* oB = e_out + eB * 32;
        float a0[4], a1[4], c0v[4], c1[4];
#pragma unroll
        for (int nb = 0; nb < 4; nb++) {
            const int col = nb * 8 + 2 * t;
            float2 bb = *(const float2*)(b2s + col);
            a0[nb] = d2[nb][0] + bb.x;  a1[nb] = d2[nb][1] + bb.y;
            c0v[nb] = d2[nb][2] + bb.x; c1[nb] = d2[nb][3] + bb.y;
            *(float2*)(oA + col) = make_float2(a0[nb], a1[nb]);
            *(float2*)(oB + col) = make_float2(c0v[nb], c1[nb]);
            red2(hA + col, a0[nb], a1[nb]);
            red2(hB + col, c0v[nb], c1[nb]);
        }
        if (gFirst == gLast) {
#pragma unroll
            for (int nb = 0; nb < 4; nb++) {
                float s0 = a0[nb] + c0v[nb];
                float s1 = a1[nb] + c1[nb];
#pragma unroll
                for (int m = 4; m <= 16; m <<= 1) {
                    s0 += __shfl_xor_sync(0xFFFFFFFFu, s0, m);
                    s1 += __shfl_xor_sync(0xFFFFFFFFu, s1, m);
                }
                if (g == 0) {
                    const int col = nb * 8 + 2 * t;
                    atomicAdd(&Es[gFirst * 32 + col], s0);
                    atomicAdd(&Es[gFirst * 32 + col + 1], s1);
                }
            }
        } else {
#pragma unroll
            for (int nb = 0; nb < 4; nb++) {
                const int col = nb * 8 + 2 * t;
                atomicAdd(&Es[gA * 32 + col], a0[nb]);
                atomicAdd(&Es[gA * 32 + col + 1], a1[nb]);
                atomicAdd(&Es[gB * 32 + col], c0v[nb]);
                atomicAdd(&Es[gB * 32 + col + 1], c1[nb]);
            }
        }
    }
    __syncthreads();
    atomicAdd(&g_ecomb[tid], Es[tid]);
}

// ================== NODE KERNEL + global tail ==================
#define NSM_XHI   0        // 128 x 72 fp16 = 18432
#define NSM_XLO   18432
#define NSM_W1F   36864    // 512 uint4 = 8192
#define NSM_BIAS  45056    // 2048
#define NSM_B2    47104    // 128
#define NSM_NS    47232    // 1024
#define NSM_TOTAL 48256

__global__ void __launch_bounds__(256, 3) node_kernel(
    const float* __restrict__ node_feat, const float* __restrict__ g_repr,
    const int* __restrict__ n2g, const float* __restrict__ b2,
    const float* __restrict__ Wu1, const float* __restrict__ bu1,
    const float* __restrict__ Wu2, const float* __restrict__ bu2,
    float* __restrict__ n_out, float* __restrict__ g_out)
{
    extern __shared__ unsigned char smem[];
    const int tid = threadIdx.x;
    const int wid = tid >> 5, lid = tid & 31;

    __half* Xhi = (__half*)(smem + NSM_XHI);
    __half* Xlo = (__half*)(smem + NSM_XLO);
    const uint4* W1F = (const uint4*)(smem + NSM_W1F);
    float* Bs  = (float*)(smem + NSM_BIAS);
    float* b2s = (float*)(smem + NSM_B2);
    float* Ns  = (float*)(smem + NSM_NS);

    {
        uint4* d1 = (uint4*)(smem + NSM_W1F);
        for (int i = tid; i < 512; i += 256) d1[i] = gWn1frag[i];
        for (int i = tid; i < 512; i += 256) Bs[i] = gBias1n[i];
        if (tid < DOUT) b2s[tid] = b2[tid];
        Ns[tid] = 0.f;
    }

    const int n0base = blockIdx.x * 128;

    // gather: k 0..63 = node_feat || g_h; 2 threads per row, 32 cols each
    {
        const int r = tid >> 1, half = tid & 1;
        const int node = n0base + r;
        __half* xh = Xhi + r * 72 + half * 32;
        __half* xl = Xlo + r * 72 + half * 32;
        if (node < N_NODES) {
            const float4* p = (const float4*)((half ? g_h : node_feat) + (size_t)node * 32);
#pragma unroll
            for (int q = 0; q < 4; q++) {
                uint4 hi, lo;
                cvt8h(p[2 * q], p[2 * q + 1], hi, lo);
                *(uint4*)(xh + q * 8) = hi;
                *(uint4*)(xl + q * 8) = lo;
            }
        } else {
            const uint4 z = make_uint4(0, 0, 0, 0);
#pragma unroll
            for (int q = 0; q < 4; q++) {
                *(uint4*)(xh + q * 8) = z;
                *(uint4*)(xl + q * 8) = z;
            }
        }
    }
    __syncthreads();

    const int g = lid >> 2, t = lid & 3;
    const int r0 = 16 * wid + g;
    float acc[8][4];
#pragma unroll
    for (int n0 = 0; n0 < 8; n0++)
#pragma unroll
        for (int j = 0; j < 4; j++) acc[n0][j] = 0.f;

    gemm_pass<0, 4>(Xhi, Xlo, W1F, r0, t, lid, acc);

    const int nA = n0base + r0, nB = nA + 8;
    const bool vA = nA < N_NODES, vB = nB < N_NODES;
    const int gA = vA ? n2g[nA] : 0, gB = vB ? n2g[nB] : 0;

    uint32_t Ahi[4][4], Alo[4][4];
#pragma unroll
    for (int n0 = 0; n0 < 8; n0++) {
        const int col = n0 * 8 + 2 * t;
        float2 bbA = *(const float2*)(Bs + gA * 64 + col);
        float2 bbB = *(const float2*)(Bs + gB * 64 + col);
        const int ks2 = n0 >> 1, ib = (n0 & 1) * 2;
        split_frag(fmaxf(acc[n0][0] + bbA.x, 0.f), fmaxf(acc[n0][1] + bbA.y, 0.f),
                   fmaxf(acc[n0][2] + bbB.x, 0.f), fmaxf(acc[n0][3] + bbB.y, 0.f),
                   Ahi[ks2][ib], Ahi[ks2][ib + 1], Alo[ks2][ib], Alo[ks2][ib + 1]);
    }

    float d2[4][4];
#pragma unroll
    for (int nb = 0; nb < 4; nb++)
#pragma unroll
        for (int j = 0; j < 4; j++) d2[nb][j] = 0.f;

#pragma unroll
    for (int ks2 = 0; ks2 < 4; ks2++) {
        const uint4* wf = gWn2frag + (ks2 * 2) * 32 + lid;
#pragma unroll
        for (int p = 0; p < 2; p++) {
            uint4 w = wf[p * 32];
            mma_h(d2[2 * p], Ahi[ks2], w.x, w.y);
            mma_h(d2[2 * p], Alo[ks2], w.x, w.y);
            mma_h(d2[2 * p + 1], Ahi[ks2], w.z, w.w);
            mma_h(d2[2 * p + 1], Alo[ks2], w.z, w.w);
        }
    }

    // epilogue
    {
        const bool warpFull = (n0base + 16 * wid + 15) < N_NODES;
        int gFirst = 0, gLast = -1;
        if (warpFull) {
            gFirst = n2g[n0base + 16 * wid];
            gLast  = n2g[n0base + 16 * wid + 15];
        }
        float a0[4], a1[4], c0v[4], c1[4];
#pragma unroll
        for (int nb = 0; nb < 4; nb++) {
            const int col = nb * 8 + 2 * t;
            float2 bb = *(const float2*)(b2s + col);
            a0[nb] = d2[nb][0] + bb.x;  a1[nb] = d2[nb][1] + bb.y;
            c0v[nb] = d2[nb][2] + bb.x; c1[nb] = d2[nb][3] + bb.y;
            if (vA) *(float2*)(n_out + (size_t)nA * 32 + col) = make_float2(a0[nb], a1[nb]);
            if (vB) *(float2*)(n_out + (size_t)nB * 32 + col) = make_float2(c0v[nb], c1[nb]);
        }
        if (warpFull && gFirst == gLast) {
#pragma unroll
            for (int nb = 0; nb < 4; nb++) {
                float s0 = a0[nb] + c0v[nb];
                float s1 = a1[nb] + c1[nb];
#pragma unroll
                for (int m = 4; m <= 16; m <<= 1) {
                    s0 += __shfl_xor_sync(0xFFFFFFFFu, s0, m);
                    s1 += __shfl_xor_sync(0xFFFFFFFFu, s1, m);
                }
                if (g == 0) {
                    const int col = nb * 8 + 2 * t;
                    atomicAdd(&Ns[gFirst * 32 + col], s0);
                    atomicAdd(&Ns[gFirst * 32 + col + 1], s1);
                }
            }
        } else {
#pragma unroll
            for (int nb = 0; nb < 4; nb++) {
                const int col = nb * 8 + 2 * t;
                if (vA) {
                    atomicAdd(&Ns[gA * 32 + col], a0[nb]);
                    atomicAdd(&Ns[gA * 32 + col + 1], a1[nb]);
                }
                if (vB) {
                    atomicAdd(&Ns[gB * 32 + col], c0v[nb]);
                    atomicAdd(&Ns[gB * 32 + col + 1], c1[nb]);
                }
            }
        }
    }
    __syncthreads();
    atomicAdd(&g_ncomb[tid], Ns[tid]);

    // -------- last-block global MLP tail --------
    __shared__ unsigned s_done;
    __threadfence();
    __syncthreads();
    if (tid == 0) {
        unsigned tk = atomicAdd(&g_ticket, 1);
        s_done = (tk == gridDim.x - 1) ? 1u : 0u;
    }
    __syncthreads();
    if (!s_done) return;
    __threadfence();

    float* U   = (float*)(smem + 0);        // 768 f
    float* W1u = (float*)(smem + 4096);     // 6144 f
    float* W2u = (float*)(smem + 28672);    // 2048 f
    float* Hg  = (float*)(smem + 40960);    // 512 f

    for (int i = tid; i < B_GRAPH * 96; i += 256) {
        const int b = i / 96, c = i % 96;
        float v;
        if (c < 32)      v = g_ncomb[b * 32 + c];
        else if (c < 64) v = g_ecomb[b * 32 + (c - 32)];
        else             v = g_repr[b * 32 + (c - 64)];
        U[i] = v;
    }
    {
        const float4* wg = (const float4*)Wu1; float4* ws = (float4*)W1u;
        for (int i = tid; i < 1536; i += 256) ws[i] = wg[i];
        const float4* w2g = (const float4*)Wu2; float4* w2s = (float4*)W2u;
        for (int i = tid; i < 512; i += 256) w2s[i] = w2g[i];
    }
    __syncthreads();

    for (int idx = tid; idx < B_GRAPH * HID; idx += 256) {
        const int b = idx >> 6, j = idx & 63;
        float s = bu1[j];
#pragma unroll 8
        for (int k = 0; k < 96; k++) s += U[b * 96 + k] * W1u[k * 64 + j];
        Hg[idx] = fmaxf(s, 0.f);
    }
    __syncthreads();
    for (int idx = tid; idx < B_GRAPH * DOUT; idx += 256) {
        const int b = idx >> 5, c = idx & 31;
        float s = bu2[c];
#pragma unroll 8
        for (int k = 0; k < 64; k++) s += Hg[b * 64 + k] * W2u[k * 32 + c];
        g_out[idx] = s;
    }
}

extern "C" void kernel_launch(void* const* d_in, const int* in_sizes, int n_in,
                              void* d_out, int out_size)
{
    const float* edge_feat = (const float*)d_in[0];
    const float* node_feat = (const float*)d_in[1];
    const float* g_repr    = (const float*)d_in[2];
    const int*   src       = (const int*)d_in[3];
    const int*   dst       = (const int*)d_in[4];
    const int*   n2g       = (const int*)d_in[5];
    const int*   e2g       = (const int*)d_in[6];
    const float* W_e1 = (const float*)d_in[7];
    const float* b_e1 = (const float*)d_in[8];
    const float* W_e2 = (const float*)d_in[9];
    const float* b_e2 = (const float*)d_in[10];
    const float* W_n1 = (const float*)d_in[11];
    const float* b_n1 = (const float*)d_in[12];
    const float* W_n2 = (const float*)d_in[13];
    const float* b_n2 = (const float*)d_in[14];
    const float* W_u1 = (const float*)d_in[15];
    const float* b_u1 = (const float*)d_in[16];
    const float* W_u2 = (const float*)d_in[17];
    const float* b_u2 = (const float*)d_in[18];

    float* out = (float*)d_out;
    float* e_out = out;                                      // [E, 32]
    float* n_out = out + (size_t)N_EDGES * DOUT;             // [N, 32]
    float* g_out = out + (size_t)(N_EDGES + N_NODES) * DOUT; // [B, 32]

    cudaFuncSetAttribute(edge_kernel, cudaFuncAttributeMaxDynamicSharedMemorySize, SM_TOTAL);
    cudaFuncSetAttribute(node_kernel, cudaFuncAttributeMaxDynamicSharedMemorySize, NSM_TOTAL);

    zero_kernel<<<ZERO_BLOCKS + 8, 256>>>(W_e1, W_e2, W_n1, W_n2,
                                          b_e1, b_n1, g_repr);
    edge_kernel<<<N_EDGES / 128, 256, SM_TOTAL>>>(
        edge_feat, node_feat, src, dst, e2g, b_e2, e_out);
    node_kernel<<<(N_NODES + 127) / 128, 256, NSM_TOTAL>>>(
        node_feat, g_repr, n2g, b_n2,
        W_u1, b_u1, W_u2, b_u2, n_out, g_out);
}